// round 1
// baseline (speedup 1.0000x reference)
#include <cuda_runtime.h>
#include <math.h>

#define NXc 512
#define NQc 512
#define NUc 128
#define Bc  32768
#define NHc 1024
#define EPSc 1e-3f

// ---------------- scratch (device globals; no allocation allowed) ----------
__device__ float g_H[NHc * NHc];        // 4 MB
__device__ float g_P[NXc * NXc];        // 1 MB  (holds L panels after factorization)
__device__ float g_Linv[8 * 64 * 64];   // inverses of diagonal Cholesky blocks
__device__ float g_rlam[NQc];           // 1/lam
__device__ float g_D11[NQc * NQc];
__device__ float g_C1[NQc * NXc];
__device__ float g_RHS[NXc * 1024];     // [Y | R]
__device__ float g_Z[NXc * 1024];       // forward-solve result
__device__ float g_S[NXc * 1024];       // [A | B1]
__device__ float g_base[(size_t)Bc * NQc]; // 64 MB
__device__ float g_w[(size_t)Bc * NQc];    // 64 MB

// ---------------- fast accurate tanh (~1e-6 rel err) -----------------------
__device__ __forceinline__ float ftanh(float x) {
    float a = fabsf(x);
    float t = __expf(-2.0f * a);              // in (0,1]
    float r = __fdividef(1.0f - t, 1.0f + t); // in [0,1)
    return copysignf(r, x);
}

// ---------------- generic small GEMM: C = beta*C + alpha*opA(A)*opB(B) -----
// 64x64 tiles, BK=16, 256 threads, 4x4 per thread. M,N multiples of 64,
// K multiple of 16 (guaranteed by construction). diagAdd added where
// global row == global col.
template <int TA, int TB>
__global__ __launch_bounds__(256) void sgemm64(
    const float* __restrict__ A, int lda,
    const float* __restrict__ B, int ldb,
    float* __restrict__ C, int ldc,
    int K, float alpha, float beta, float diagAdd)
{
    __shared__ float As[16][68];
    __shared__ float Bs[16][68];
    int tid = threadIdx.x;
    int m0 = blockIdx.y * 64, n0 = blockIdx.x * 64;
    int tx = tid & 15, ty = tid >> 4;
    float acc[4][4] = {};

    for (int kt = 0; kt < K; kt += 16) {
        __syncthreads();
        if (TA == 0) {
            int r = tid >> 2, kq = (tid & 3) * 4;
            float4 v = *(const float4*)(A + (size_t)(m0 + r) * lda + kt + kq);
            As[kq + 0][r] = v.x; As[kq + 1][r] = v.y;
            As[kq + 2][r] = v.z; As[kq + 3][r] = v.w;
        } else {
            int m4 = (tid & 15) * 4, k = tid >> 4;
            float4 v = *(const float4*)(A + (size_t)(kt + k) * lda + m0 + m4);
            As[k][m4 + 0] = v.x; As[k][m4 + 1] = v.y;
            As[k][m4 + 2] = v.z; As[k][m4 + 3] = v.w;
        }
        if (TB == 0) {
            int n4 = (tid & 15) * 4, k = tid >> 4;
            float4 v = *(const float4*)(B + (size_t)(kt + k) * ldb + n0 + n4);
            Bs[k][n4 + 0] = v.x; Bs[k][n4 + 1] = v.y;
            Bs[k][n4 + 2] = v.z; Bs[k][n4 + 3] = v.w;
        } else {
            int r = tid >> 2, kq = (tid & 3) * 4;
            float4 v = *(const float4*)(B + (size_t)(n0 + r) * ldb + kt + kq);
            Bs[kq + 0][r] = v.x; Bs[kq + 1][r] = v.y;
            Bs[kq + 2][r] = v.z; Bs[kq + 3][r] = v.w;
        }
        __syncthreads();
        #pragma unroll
        for (int kk = 0; kk < 16; ++kk) {
            float4 a = *(const float4*)&As[kk][ty * 4];
            float4 b = *(const float4*)&Bs[kk][tx * 4];
            float am[4] = {a.x, a.y, a.z, a.w};
            float bm[4] = {b.x, b.y, b.z, b.w};
            #pragma unroll
            for (int i = 0; i < 4; ++i)
                #pragma unroll
                for (int j = 0; j < 4; ++j)
                    acc[i][j] += am[i] * bm[j];
        }
    }

    #pragma unroll
    for (int i = 0; i < 4; ++i) {
        int gr = m0 + ty * 4 + i;
        #pragma unroll
        for (int j = 0; j < 4; ++j) {
            int gc = n0 + tx * 4 + j;
            float v = alpha * acc[i][j];
            if (beta != 0.0f) v += beta * C[(size_t)gr * ldc + gc];
            if (gr == gc) v += diagAdd;
            C[(size_t)gr * ldc + gc] = v;
        }
    }
}

// ---------------- prep kernels ----------------------------------------------
__global__ void prep_lam() {
    int i = threadIdx.x;
    if (i < NQc) g_rlam[i] = 2.0f / g_H[(size_t)(NXc + i) * NHc + NXc + i];
}

__global__ void prep_mats(const float* __restrict__ Y1, const float* __restrict__ Chi) {
    int idx = blockIdx.x * 256 + threadIdx.x;   // 512*512 total
    int i = idx >> 9, j = idx & 511;
    // RHS[:, :512] = Y = -0.5*(H1 + Y1 - Y1^T)   (alpha = 0)
    g_RHS[(size_t)i * 1024 + j] =
        -0.5f * (g_H[(size_t)i * NHc + j] + Y1[(size_t)i * 512 + j] - Y1[(size_t)j * 512 + i]);
    // RHS[:, 512:] = R = -H2 - Chi
    g_RHS[(size_t)i * 1024 + 512 + j] =
        -g_H[(size_t)i * NHc + 512 + j] - Chi[(size_t)i * 512 + j];
    float rl = g_rlam[i];
    // D11 = -tril(H4,-1)/lam
    g_D11[(size_t)i * 512 + j] =
        (j < i) ? -g_H[(size_t)(512 + i) * NHc + 512 + j] * rl : 0.0f;
    // C1 = Chi^T / lam
    g_C1[(size_t)i * 512 + j] = Chi[(size_t)j * 512 + i] * rl;
}

// ---------------- 64x64 Cholesky block factor + triangular inverse ---------
__global__ __launch_bounds__(256) void potf2_inv(int k)
{
    __shared__ float S[64][65];
    __shared__ float Dinv[64];
    __shared__ float sd;
    int tid = threadIdx.x;

    for (int idx = tid; idx < 4096; idx += 256) {
        int i = idx >> 6, j = idx & 63;
        S[i][j] = g_P[(size_t)(k * 64 + i) * NXc + k * 64 + j];
    }
    __syncthreads();

    for (int j = 0; j < 64; ++j) {
        if (tid == 0) sd = rsqrtf(S[j][j]);
        __syncthreads();
        if (tid >= j && tid < 64) S[tid][j] *= sd;
        __syncthreads();
        for (int idx = tid; idx < 4096; idx += 256) {
            int i = idx >> 6, c = idx & 63;
            if (i > j && c > j) S[i][c] -= S[i][j] * S[c][j];
        }
        __syncthreads();
    }

    if (tid < 64) Dinv[tid] = 1.0f / S[tid][tid];
    __syncthreads();

    // W = inv(L) : warp-per-8-columns, row-parallel column sweep
    int wd = tid >> 5, lane = tid & 31;
    for (int cc = 0; cc < 8; ++cc) {
        int c = wd * 8 + cc;
        float x0 = (lane == c) ? 1.0f : 0.0f;       // row `lane`
        float x1 = (lane + 32 == c) ? 1.0f : 0.0f;  // row `lane+32`
        for (int i = c; i < 64; ++i) {
            float src = (i < 32) ? x0 : x1;
            float part = __shfl_sync(0xffffffffu, src, i & 31);
            float xv = part * Dinv[i];
            if (i < 32) { if (lane == i) x0 = xv; }
            else        { if (lane == i - 32) x1 = xv; }
            if (lane > i)      x0 -= S[lane][i] * xv;
            if (lane + 32 > i) x1 -= S[lane + 32][i] * xv;
        }
        g_Linv[k * 4096 + lane * 64 + c] = x0;
        g_Linv[k * 4096 + (lane + 32) * 64 + c] = x1;
    }
}

// ---------------- batch GEMM: C = (addTo?C:0) + sum_s A_s * W_s^T ----------
// 128x64 tiles, BK=16, 256 threads, 8x4 per thread. M mult of 128, N of 64,
// each K mult of 16. W stored row-major (N x K).
__device__ __forceinline__ void bg_seg(
    const float* __restrict__ A, int lda,
    const float* __restrict__ W, int ldw, int K,
    int m0, int n0, int tid, float acc[8][4],
    float (*As)[132], float (*Ws)[68])
{
    int la_m = tid >> 2;
    int la_k = (tid & 3) * 4;
    int tx = tid & 15, ty = tid >> 4;
    for (int kt = 0; kt < K; kt += 16) {
        __syncthreads();
        float4 a0 = *(const float4*)(A + (size_t)(m0 + la_m) * lda + kt + la_k);
        float4 a1 = *(const float4*)(A + (size_t)(m0 + la_m + 64) * lda + kt + la_k);
        float4 wv = *(const float4*)(W + (size_t)(n0 + la_m) * ldw + kt + la_k);
        As[la_k + 0][la_m] = a0.x; As[la_k + 1][la_m] = a0.y;
        As[la_k + 2][la_m] = a0.z; As[la_k + 3][la_m] = a0.w;
        As[la_k + 0][la_m + 64] = a1.x; As[la_k + 1][la_m + 64] = a1.y;
        As[la_k + 2][la_m + 64] = a1.z; As[la_k + 3][la_m + 64] = a1.w;
        Ws[la_k + 0][la_m] = wv.x; Ws[la_k + 1][la_m] = wv.y;
        Ws[la_k + 2][la_m] = wv.z; Ws[la_k + 3][la_m] = wv.w;
        __syncthreads();
        #pragma unroll
        for (int kk = 0; kk < 16; ++kk) {
            float4 af0 = *(const float4*)&As[kk][ty * 8];
            float4 af1 = *(const float4*)&As[kk][ty * 8 + 4];
            float4 wf  = *(const float4*)&Ws[kk][tx * 4];
            float am[8] = {af0.x, af0.y, af0.z, af0.w, af1.x, af1.y, af1.z, af1.w};
            float wn[4] = {wf.x, wf.y, wf.z, wf.w};
            #pragma unroll
            for (int i = 0; i < 8; ++i)
                #pragma unroll
                for (int j = 0; j < 4; ++j)
                    acc[i][j] += am[i] * wn[j];
        }
    }
}

__global__ __launch_bounds__(256) void bgemm(
    const float* A0, int lda0, const float* W0, int ldw0, int K0,
    const float* A1, int lda1, const float* W1, int ldw1, int K1,
    const float* A2, int lda2, const float* W2, int ldw2, int K2,
    float* __restrict__ C, int ldc, int addTo)
{
    __shared__ float As[16][132];
    __shared__ float Ws[16][68];
    float acc[8][4] = {};
    int tid = threadIdx.x;
    int m0 = blockIdx.y * 128, n0 = blockIdx.x * 64;

    if (K0 > 0) bg_seg(A0, lda0, W0, ldw0, K0, m0, n0, tid, acc, As, Ws);
    if (K1 > 0) bg_seg(A1, lda1, W1, ldw1, K1, m0, n0, tid, acc, As, Ws);
    if (K2 > 0) bg_seg(A2, lda2, W2, ldw2, K2, m0, n0, tid, acc, As, Ws);

    int tx = tid & 15, ty = tid >> 4;
    #pragma unroll
    for (int i = 0; i < 8; ++i) {
        float* cp = C + (size_t)(m0 + ty * 8 + i) * ldc + n0 + tx * 4;
        float4 v = make_float4(acc[i][0], acc[i][1], acc[i][2], acc[i][3]);
        if (addTo) {
            float4 o = *(const float4*)cp;
            v.x += o.x; v.y += o.y; v.z += o.z; v.w += o.w;
        }
        *(float4*)cp = v;
    }
}

// ---------------- in-block sequential tanh recurrence ----------------------
// block b: w[:, b*64+i] = tanh(base[:, b*64+i] + sum_{j<i in block} w_j*D11[i][j])
// (cross-block contributions were already folded into base by a GEMM)
__global__ __launch_bounds__(256) void scan_block(int b)
{
    __shared__ float ds[64][64];
    int tid = threadIdx.x;
    for (int idx = tid; idx < 4096; idx += 256) {
        int i = idx >> 6, j = idx & 63;
        ds[i][j] = g_D11[(size_t)(b * 64 + i) * NQc + b * 64 + j];
    }
    __syncthreads();

    int r = blockIdx.x * 256 + tid;
    float bb[64];
    const float4* bp = (const float4*)(g_base + (size_t)r * NQc + b * 64);
    #pragma unroll
    for (int q = 0; q < 16; ++q) {
        float4 v = bp[q];
        bb[q * 4 + 0] = v.x; bb[q * 4 + 1] = v.y;
        bb[q * 4 + 2] = v.z; bb[q * 4 + 3] = v.w;
    }
    float wv[64];
    #pragma unroll
    for (int i = 0; i < 64; ++i) {
        float s0 = 0.f, s1 = 0.f, s2 = 0.f, s3 = 0.f;
        #pragma unroll
        for (int j = 0; j < 64; ++j) {
            if (j < i) {
                float p = wv[j] * ds[i][j];
                if      ((j & 3) == 0) s0 += p;
                else if ((j & 3) == 1) s1 += p;
                else if ((j & 3) == 2) s2 += p;
                else                   s3 += p;
            }
        }
        wv[i] = ftanh(bb[i] + ((s0 + s1) + (s2 + s3)));
    }
    float4* wp = (float4*)(g_w + (size_t)r * NQc + b * 64);
    #pragma unroll
    for (int q = 0; q < 16; ++q)
        wp[q] = make_float4(wv[q * 4], wv[q * 4 + 1], wv[q * 4 + 2], wv[q * 4 + 3]);
}

// ---------------- host orchestration ----------------------------------------
extern "C" void kernel_launch(void* const* d_in, const int* in_sizes, int n_in,
                              void* d_out, int out_size)
{
    const float* xi    = (const float*)d_in[1];
    const float* u     = (const float*)d_in[2];
    const float* Pstar = (const float*)d_in[3];
    const float* Chi   = (const float*)d_in[4];
    const float* Y1    = (const float*)d_in[5];
    const float* B2    = (const float*)d_in[6];
    const float* D12   = (const float*)d_in[7];
    const float* X     = (const float*)d_in[8];
    float* out = (float*)d_out;

    float *H, *P, *Linv, *RHS, *Z, *S, *D11, *C1, *base, *w;
    cudaGetSymbolAddress((void**)&H,    g_H);
    cudaGetSymbolAddress((void**)&P,    g_P);
    cudaGetSymbolAddress((void**)&Linv, g_Linv);
    cudaGetSymbolAddress((void**)&RHS,  g_RHS);
    cudaGetSymbolAddress((void**)&Z,    g_Z);
    cudaGetSymbolAddress((void**)&S,    g_S);
    cudaGetSymbolAddress((void**)&D11,  g_D11);
    cudaGetSymbolAddress((void**)&C1,   g_C1);
    cudaGetSymbolAddress((void**)&base, g_base);
    cudaGetSymbolAddress((void**)&w,    g_w);

    // H = X X^T + eps I  (1024^3), P = 0.5 Pstar Pstar^T + eps I (512^3)
    sgemm64<0, 1><<<dim3(16, 16), 256>>>(X, 1024, X, 1024, H, 1024, 1024, 1.0f, 0.0f, EPSc);
    sgemm64<0, 1><<<dim3(8, 8), 256>>>(Pstar, 512, Pstar, 512, P, 512, 512, 0.5f, 0.0f, EPSc);
    prep_lam<<<1, 512>>>();
    prep_mats<<<1024, 256>>>(Y1, Chi);

    // Blocked Cholesky P = L L^T (block 64), with diag-block inverses
    for (int k = 0; k < 8; ++k) {
        potf2_inv<<<1, 256>>>(k);
        int Mrem = 512 - 64 * (k + 1);
        if (Mrem > 0) {
            float* panel = P + (size_t)(k + 1) * 64 * 512 + k * 64;
            // panel = panel * W_k^T  (in place; each CTA reads only its own rows)
            sgemm64<0, 1><<<dim3(1, Mrem / 64), 256>>>(
                panel, 512, Linv + k * 4096, 64, panel, 512, 64, 1.0f, 0.0f, 0.0f);
            // trailing -= panel * panel^T
            sgemm64<0, 1><<<dim3(Mrem / 64, Mrem / 64), 256>>>(
                panel, 512, panel, 512,
                P + (size_t)(k + 1) * 64 * 512 + (k + 1) * 64, 512, 64, -1.0f, 1.0f, 0.0f);
        }
    }

    // Forward solve L Z = [Y|R]
    for (int ib = 0; ib < 8; ++ib) {
        if (ib > 0)
            sgemm64<0, 0><<<dim3(16, 1), 256>>>(
                P + (size_t)ib * 64 * 512, 512, Z, 1024,
                RHS + (size_t)ib * 64 * 1024, 1024, 64 * ib, -1.0f, 1.0f, 0.0f);
        sgemm64<0, 0><<<dim3(16, 1), 256>>>(
            Linv + ib * 4096, 64, RHS + (size_t)ib * 64 * 1024, 1024,
            Z + (size_t)ib * 64 * 1024, 1024, 64, 1.0f, 0.0f, 0.0f);
    }
    // Backward solve L^T S = Z,  S = [A | B1]
    for (int ib = 7; ib >= 0; --ib) {
        if (ib < 7)
            sgemm64<1, 0><<<dim3(16, 1), 256>>>(
                P + (size_t)(ib + 1) * 64 * 512 + ib * 64, 512,
                S + (size_t)(ib + 1) * 64 * 1024, 1024,
                Z + (size_t)ib * 64 * 1024, 1024, 64 * (7 - ib), -1.0f, 1.0f, 0.0f);
        sgemm64<1, 0><<<dim3(16, 1), 256>>>(
            Linv + ib * 4096, 64, Z + (size_t)ib * 64 * 1024, 1024,
            S + (size_t)ib * 64 * 1024, 1024, 64, 1.0f, 0.0f, 0.0f);
    }

    // base = xi C1^T + u D12^T
    bgemm<<<dim3(8, 256), 256>>>(
        xi, 512, C1, 512, 512,
        u, 128, D12, 128, 128,
        (const float*)0, 0, (const float*)0, 0, 0,
        base, 512, 0);

    // Blocked scan over NQ: cross-block GEMM + in-block sequential recurrence
    for (int b = 0; b < 8; ++b) {
        if (b > 0)
            bgemm<<<dim3(1, 256), 256>>>(
                w, 512, D11 + (size_t)b * 64 * 512, 512, 64 * b,
                (const float*)0, 0, (const float*)0, 0, 0,
                (const float*)0, 0, (const float*)0, 0, 0,
                base + b * 64, 512, 1);
        scan_block<<<128, 256>>>(b);
    }

    // out = xi A^T + w B1^T + u B2^T   (A = S[:, :512], B1 = S[:, 512:])
    bgemm<<<dim3(8, 256), 256>>>(
        xi, 512, S, 1024, 512,
        w, 512, S + 512, 1024, 512,
        u, 128, B2, 128, 128,
        out, 512, 0);
}

// round 3
// speedup vs baseline: 1.3542x; 1.3542x over previous
#include <cuda_runtime.h>
#include <cuda_bf16.h>
#include <cstdint>
#include <math.h>

#define NXc 512
#define NQc 512
#define NUc 128
#define Bc  32768
#define EPSc 1e-3f

// ================= baseline-ISA helpers (compute_103-safe) ==================
__device__ __forceinline__ uint32_t smem_to_u32(const void* p) {
    uint32_t a;
    asm("{ .reg .u64 t; cvta.to.shared.u64 t, %1; cvt.u32.u64 %0, t; }" : "=r"(a) : "l"(p));
    return a;
}
__device__ __forceinline__ void cpasync16(uint32_t d, const void* s) {
    asm volatile("cp.async.cg.shared.global [%0], [%1], 16;" :: "r"(d), "l"(s));
}
#define CP_COMMIT() asm volatile("cp.async.commit_group;" ::: "memory")
#define CP_WAIT(N)  asm volatile("cp.async.wait_group %0;" :: "n"(N) : "memory")

__device__ __forceinline__ void ldsm4(uint32_t* r, uint32_t addr) {
    asm volatile("ldmatrix.sync.aligned.m8n8.x4.shared.b16 {%0,%1,%2,%3}, [%4];"
        : "=r"(r[0]), "=r"(r[1]), "=r"(r[2]), "=r"(r[3]) : "r"(addr));
}
__device__ __forceinline__ void ldsm2(uint32_t* r, uint32_t addr) {
    asm volatile("ldmatrix.sync.aligned.m8n8.x2.shared.b16 {%0,%1}, [%2];"
        : "=r"(r[0]), "=r"(r[1]) : "r"(addr));
}
__device__ __forceinline__ void mma16816(float* d, const uint32_t* a, const uint32_t* b) {
    asm volatile("mma.sync.aligned.m16n8k16.row.col.f32.bf16.bf16.f32 "
        "{%0,%1,%2,%3}, {%4,%5,%6,%7}, {%8,%9}, {%0,%1,%2,%3};"
        : "+f"(d[0]), "+f"(d[1]), "+f"(d[2]), "+f"(d[3])
        : "r"(a[0]), "r"(a[1]), "r"(a[2]), "r"(a[3]), "r"(b[0]), "r"(b[1]));
}
__device__ __forceinline__ uint32_t swz(uint32_t off) { return off ^ ((off >> 3) & 0x70); }

// ================= scratch (device globals) =================================
__device__ float g_H[1024 * 1024];
__device__ float g_P[NXc * NXc];
__device__ float g_Linv[8 * 64 * 64];
__device__ float g_rlam[NQc];
__device__ float g_D11[NQc * NQc];
__device__ float g_RHS[NXc * 1024];
__device__ float g_Z[NXc * 1024];
__device__ float g_S[NXc * 1024];
__device__ float g_base[(size_t)Bc * NQc];
__device__ __nv_bfloat16 g_xih[(size_t)Bc * NXc], g_xil[(size_t)Bc * NXc];
__device__ __nv_bfloat16 g_uh[(size_t)Bc * NUc],  g_ul[(size_t)Bc * NUc];
__device__ __nv_bfloat16 g_wh[(size_t)Bc * NQc],  g_wl[(size_t)Bc * NQc];
__device__ __nv_bfloat16 g_C1h[NQc * NXc],  g_C1l[NQc * NXc];
__device__ __nv_bfloat16 g_D11h[NQc * NQc], g_D11l[NQc * NQc];
__device__ __nv_bfloat16 g_Sh[NXc * 1024],  g_Sl[NXc * 1024];
__device__ __nv_bfloat16 g_D12h[NQc * NUc], g_D12l[NQc * NUc];
__device__ __nv_bfloat16 g_B2h[NXc * NUc],  g_B2l[NXc * NUc];

// ================= misc small kernels =======================================
__device__ __forceinline__ float ftanh(float x) {
    float a = fabsf(x);
    float t = __expf(-2.0f * a);
    float r = __fdividef(1.0f - t, 1.0f + t);
    return copysignf(r, x);
}

__global__ void splitk(const float* __restrict__ in, __nv_bfloat16* __restrict__ hi,
                       __nv_bfloat16* __restrict__ lo, int n4) {
    int i = blockIdx.x * 256 + threadIdx.x;
    if (i >= n4) return;
    float4 v = ((const float4*)in)[i];
    __nv_bfloat162 h0, h1, l0, l1;
    h0.x = __float2bfloat16(v.x); h0.y = __float2bfloat16(v.y);
    h1.x = __float2bfloat16(v.z); h1.y = __float2bfloat16(v.w);
    l0.x = __float2bfloat16(v.x - __bfloat162float(h0.x));
    l0.y = __float2bfloat16(v.y - __bfloat162float(h0.y));
    l1.x = __float2bfloat16(v.z - __bfloat162float(h1.x));
    l1.y = __float2bfloat16(v.w - __bfloat162float(h1.y));
    ((__nv_bfloat162*)hi)[i * 2] = h0; ((__nv_bfloat162*)hi)[i * 2 + 1] = h1;
    ((__nv_bfloat162*)lo)[i * 2] = l0; ((__nv_bfloat162*)lo)[i * 2 + 1] = l1;
}

__global__ void prep_lam() {
    int i = threadIdx.x;
    if (i < NQc) g_rlam[i] = 2.0f / (g_H[(size_t)(NXc + i) * 1024 + NXc + i] + EPSc);
}

__global__ void prep_mats(const float* __restrict__ Y1, const float* __restrict__ Chi) {
    int idx = blockIdx.x * 256 + threadIdx.x;
    int i = idx >> 9, j = idx & 511;
    float h1 = g_H[(size_t)i * 1024 + j];
    g_RHS[(size_t)i * 1024 + j] =
        -0.5f * (h1 + ((i == j) ? EPSc : 0.0f) + Y1[(size_t)i * 512 + j] - Y1[(size_t)j * 512 + i]);
    g_RHS[(size_t)i * 1024 + 512 + j] =
        -g_H[(size_t)i * 1024 + 512 + j] - Chi[(size_t)i * 512 + j];
    float rl = g_rlam[i];
    float d = (j < i) ? -g_H[(size_t)(512 + i) * 1024 + 512 + j] * rl : 0.0f;
    g_D11[(size_t)i * 512 + j] = d;
    __nv_bfloat16 dh = __float2bfloat16(d);
    g_D11h[(size_t)i * 512 + j] = dh;
    g_D11l[(size_t)i * 512 + j] = __float2bfloat16(d - __bfloat162float(dh));
    float c1 = Chi[(size_t)j * 512 + i] * rl;
    __nv_bfloat16 ch = __float2bfloat16(c1);
    g_C1h[(size_t)i * 512 + j] = ch;
    g_C1l[(size_t)i * 512 + j] = __float2bfloat16(c1 - __bfloat162float(ch));
}

// ================= fp32 SIMT GEMMs for prep path ============================
template <int TA, int TB>
__global__ __launch_bounds__(256) void sgemm64(
    const float* __restrict__ A, int lda,
    const float* __restrict__ B, int ldb,
    float* __restrict__ C, int ldc,
    int K, float alpha, float beta, float diagAdd)
{
    __shared__ float As[16][68];
    __shared__ float Bs[16][68];
    int tid = threadIdx.x;
    int m0 = blockIdx.y * 64, n0 = blockIdx.x * 64;
    int tx = tid & 15, ty = tid >> 4;
    float acc[4][4] = {};
    for (int kt = 0; kt < K; kt += 16) {
        __syncthreads();
        if (TA == 0) {
            int r = tid >> 2, kq = (tid & 3) * 4;
            float4 v = *(const float4*)(A + (size_t)(m0 + r) * lda + kt + kq);
            As[kq + 0][r] = v.x; As[kq + 1][r] = v.y; As[kq + 2][r] = v.z; As[kq + 3][r] = v.w;
        } else {
            int m4 = (tid & 15) * 4, k = tid >> 4;
            float4 v = *(const float4*)(A + (size_t)(kt + k) * lda + m0 + m4);
            As[k][m4 + 0] = v.x; As[k][m4 + 1] = v.y; As[k][m4 + 2] = v.z; As[k][m4 + 3] = v.w;
        }
        if (TB == 0) {
            int n4 = (tid & 15) * 4, k = tid >> 4;
            float4 v = *(const float4*)(B + (size_t)(kt + k) * ldb + n0 + n4);
            Bs[k][n4 + 0] = v.x; Bs[k][n4 + 1] = v.y; Bs[k][n4 + 2] = v.z; Bs[k][n4 + 3] = v.w;
        } else {
            int r = tid >> 2, kq = (tid & 3) * 4;
            float4 v = *(const float4*)(B + (size_t)(n0 + r) * ldb + kt + kq);
            Bs[kq + 0][r] = v.x; Bs[kq + 1][r] = v.y; Bs[kq + 2][r] = v.z; Bs[kq + 3][r] = v.w;
        }
        __syncthreads();
        #pragma unroll
        for (int kk = 0; kk < 16; ++kk) {
            float4 a = *(const float4*)&As[kk][ty * 4];
            float4 b = *(const float4*)&Bs[kk][tx * 4];
            float am[4] = {a.x, a.y, a.z, a.w};
            float bm[4] = {b.x, b.y, b.z, b.w};
            #pragma unroll
            for (int i = 0; i < 4; ++i)
                #pragma unroll
                for (int j = 0; j < 4; ++j)
                    acc[i][j] += am[i] * bm[j];
        }
    }
    #pragma unroll
    for (int i = 0; i < 4; ++i) {
        int gr = m0 + ty * 4 + i;
        #pragma unroll
        for (int j = 0; j < 4; ++j) {
            int gc = n0 + tx * 4 + j;
            float v = alpha * acc[i][j];
            if (beta != 0.0f) v += beta * C[(size_t)gr * ldc + gc];
            if (gr == gc) v += diagAdd;
            C[(size_t)gr * ldc + gc] = v;
        }
    }
}

// 128x64-tile fp32 GEMM (used for H = X X^T)
__global__ __launch_bounds__(256) void bgemm_f32(
    const float* __restrict__ A, int lda,
    const float* __restrict__ W, int ldw, int K,
    float* __restrict__ C, int ldc)
{
    __shared__ float As[16][132];
    __shared__ float Ws[16][68];
    float acc[8][4] = {};
    int tid = threadIdx.x;
    int m0 = blockIdx.y * 128, n0 = blockIdx.x * 64;
    int la_m = tid >> 2, la_k = (tid & 3) * 4;
    int tx = tid & 15, ty = tid >> 4;
    for (int kt = 0; kt < K; kt += 16) {
        __syncthreads();
        float4 a0 = *(const float4*)(A + (size_t)(m0 + la_m) * lda + kt + la_k);
        float4 a1 = *(const float4*)(A + (size_t)(m0 + la_m + 64) * lda + kt + la_k);
        float4 wv = *(const float4*)(W + (size_t)(n0 + la_m) * ldw + kt + la_k);
        As[la_k + 0][la_m] = a0.x; As[la_k + 1][la_m] = a0.y;
        As[la_k + 2][la_m] = a0.z; As[la_k + 3][la_m] = a0.w;
        As[la_k + 0][la_m + 64] = a1.x; As[la_k + 1][la_m + 64] = a1.y;
        As[la_k + 2][la_m + 64] = a1.z; As[la_k + 3][la_m + 64] = a1.w;
        Ws[la_k + 0][la_m] = wv.x; Ws[la_k + 1][la_m] = wv.y;
        Ws[la_k + 2][la_m] = wv.z; Ws[la_k + 3][la_m] = wv.w;
        __syncthreads();
        #pragma unroll
        for (int kk = 0; kk < 16; ++kk) {
            float4 af0 = *(const float4*)&As[kk][ty * 8];
            float4 af1 = *(const float4*)&As[kk][ty * 8 + 4];
            float4 wf  = *(const float4*)&Ws[kk][tx * 4];
            float am[8] = {af0.x, af0.y, af0.z, af0.w, af1.x, af1.y, af1.z, af1.w};
            float wn[4] = {wf.x, wf.y, wf.z, wf.w};
            #pragma unroll
            for (int i = 0; i < 8; ++i)
                #pragma unroll
                for (int j = 0; j < 4; ++j)
                    acc[i][j] += am[i] * wn[j];
        }
    }
    #pragma unroll
    for (int i = 0; i < 8; ++i) {
        float* cp = C + (size_t)(m0 + ty * 8 + i) * ldc + n0 + tx * 4;
        *(float4*)cp = make_float4(acc[i][0], acc[i][1], acc[i][2], acc[i][3]);
    }
}

// ================= Cholesky diag block + inverse ============================
__global__ __launch_bounds__(256) void potf2_inv(int k)
{
    __shared__ float S[64][65];
    __shared__ float Dinv[64];
    __shared__ float sd;
    int tid = threadIdx.x;
    for (int idx = tid; idx < 4096; idx += 256) {
        int i = idx >> 6, j = idx & 63;
        S[i][j] = g_P[(size_t)(k * 64 + i) * NXc + k * 64 + j];
    }
    __syncthreads();
    for (int j = 0; j < 64; ++j) {
        if (tid == 0) sd = rsqrtf(S[j][j]);
        __syncthreads();
        if (tid >= j && tid < 64) S[tid][j] *= sd;
        __syncthreads();
        for (int idx = tid; idx < 4096; idx += 256) {
            int i = idx >> 6, c = idx & 63;
            if (i > j && c > j) S[i][c] -= S[i][j] * S[c][j];
        }
        __syncthreads();
    }
    if (tid < 64) Dinv[tid] = 1.0f / S[tid][tid];
    __syncthreads();
    int wd = tid >> 5, lane = tid & 31;
    for (int cc = 0; cc < 8; ++cc) {
        int c = wd * 8 + cc;
        float x0 = (lane == c) ? 1.0f : 0.0f;
        float x1 = (lane + 32 == c) ? 1.0f : 0.0f;
        for (int i = c; i < 64; ++i) {
            float src = (i < 32) ? x0 : x1;
            float part = __shfl_sync(0xffffffffu, src, i & 31);
            float xv = part * Dinv[i];
            if (i < 32) { if (lane == i) x0 = xv; }
            else        { if (lane == i - 32) x1 = xv; }
            if (lane > i)      x0 -= S[lane][i] * xv;
            if (lane + 32 > i) x1 -= S[lane + 32][i] * xv;
        }
        g_Linv[k * 4096 + lane * 64 + c] = x0;
        g_Linv[k * 4096 + (lane + 32) * 64 + c] = x1;
    }
}

// ================= fused block triangular solves ============================
__global__ __launch_bounds__(256) void fwd_solve()
{
    __shared__ float Lt[64][65];
    __shared__ float Zt[64][65];
    int tid = threadIdx.x;
    int c0 = blockIdx.x * 64;
    int tx = tid & 15, ty = tid >> 4;
    for (int ib = 0; ib < 8; ++ib) {
        float acc[4][4] = {};
        for (int jb = 0; jb < ib; ++jb) {
            for (int idx = tid; idx < 4096; idx += 256) {
                int i = idx >> 6, j = idx & 63;
                Lt[i][j] = g_P[(size_t)(ib * 64 + i) * 512 + jb * 64 + j];
                Zt[i][j] = g_Z[(size_t)(jb * 64 + i) * 1024 + c0 + j];
            }
            __syncthreads();
            #pragma unroll 8
            for (int kk = 0; kk < 64; ++kk)
                #pragma unroll
                for (int ii = 0; ii < 4; ++ii)
                    #pragma unroll
                    for (int jj = 0; jj < 4; ++jj)
                        acc[ii][jj] += Lt[ty * 4 + ii][kk] * Zt[kk][tx * 4 + jj];
            __syncthreads();
        }
        #pragma unroll
        for (int ii = 0; ii < 4; ++ii)
            #pragma unroll
            for (int jj = 0; jj < 4; ++jj)
                Zt[ty * 4 + ii][tx * 4 + jj] =
                    g_RHS[(size_t)(ib * 64 + ty * 4 + ii) * 1024 + c0 + tx * 4 + jj] - acc[ii][jj];
        for (int idx = tid; idx < 4096; idx += 256) {
            int i = idx >> 6, j = idx & 63;
            Lt[i][j] = g_Linv[ib * 4096 + i * 64 + j];
        }
        __syncthreads();
        float z[4][4] = {};
        #pragma unroll 8
        for (int kk = 0; kk < 64; ++kk)
            #pragma unroll
            for (int ii = 0; ii < 4; ++ii)
                #pragma unroll
                for (int jj = 0; jj < 4; ++jj)
                    z[ii][jj] += Lt[ty * 4 + ii][kk] * Zt[kk][tx * 4 + jj];
        #pragma unroll
        for (int ii = 0; ii < 4; ++ii)
            #pragma unroll
            for (int jj = 0; jj < 4; ++jj)
                g_Z[(size_t)(ib * 64 + ty * 4 + ii) * 1024 + c0 + tx * 4 + jj] = z[ii][jj];
        __syncthreads();
    }
}

__global__ __launch_bounds__(256) void bwd_solve()
{
    __shared__ float Lt[64][65];
    __shared__ float Zt[64][65];
    int tid = threadIdx.x;
    int c0 = blockIdx.x * 64;
    int tx = tid & 15, ty = tid >> 4;
    for (int ib = 7; ib >= 0; --ib) {
        float acc[4][4] = {};
        for (int jb = ib + 1; jb < 8; ++jb) {
            for (int idx = tid; idx < 4096; idx += 256) {
                int i = idx >> 6, j = idx & 63;
                Lt[i][j] = g_P[(size_t)(jb * 64 + i) * 512 + ib * 64 + j];
                Zt[i][j] = g_S[(size_t)(jb * 64 + i) * 1024 + c0 + j];
            }
            __syncthreads();
            #pragma unroll 8
            for (int kk = 0; kk < 64; ++kk)
                #pragma unroll
                for (int ii = 0; ii < 4; ++ii)
                    #pragma unroll
                    for (int jj = 0; jj < 4; ++jj)
                        acc[ii][jj] += Lt[kk][ty * 4 + ii] * Zt[kk][tx * 4 + jj];
            __syncthreads();
        }
        #pragma unroll
        for (int ii = 0; ii < 4; ++ii)
            #pragma unroll
            for (int jj = 0; jj < 4; ++jj)
                Zt[ty * 4 + ii][tx * 4 + jj] =
                    g_Z[(size_t)(ib * 64 + ty * 4 + ii) * 1024 + c0 + tx * 4 + jj] - acc[ii][jj];
        for (int idx = tid; idx < 4096; idx += 256) {
            int i = idx >> 6, j = idx & 63;
            Lt[i][j] = g_Linv[ib * 4096 + i * 64 + j];
        }
        __syncthreads();
        float z[4][4] = {};
        #pragma unroll 8
        for (int kk = 0; kk < 64; ++kk)
            #pragma unroll
            for (int ii = 0; ii < 4; ++ii)
                #pragma unroll
                for (int jj = 0; jj < 4; ++jj)
                    z[ii][jj] += Lt[kk][ty * 4 + ii] * Zt[kk][tx * 4 + jj];
        #pragma unroll
        for (int ii = 0; ii < 4; ++ii)
            #pragma unroll
            for (int jj = 0; jj < 4; ++jj)
                g_S[(size_t)(ib * 64 + ty * 4 + ii) * 1024 + c0 + tx * 4 + jj] = z[ii][jj];
        __syncthreads();
    }
}

// ================= mma.sync split-bf16 batch GEMM ===========================
// C[128 x NT] tile = sum over segments of A(hi+lo) @ W(hi+lo)^T, fp32 acc.
// 8 warps as 4(m) x 2(n); warp tile 32 x NT/2; K-chunk 64; cp.async 2-stage.
struct Seg {
    const __nv_bfloat16 *Ah, *Al, *Wh, *Wl;
    int lda, ldw, K;
};

template <int NT>
__global__ __launch_bounds__(256) void mma_gemm(
    Seg s0, Seg s1, Seg s2, float* __restrict__ C, int ldc, int addTo)
{
    extern __shared__ __align__(1024) char smem[];
    constexpr int AP  = 128 * 128;        // bytes per A plane per stage
    constexpr int WP  = NT * 128;         // bytes per W plane per stage
    constexpr int STG = 2 * AP + 2 * WP;
    constexpr int NA  = NT / 16;          // n-atoms per warp (warp covers NT/2 cols)

    uint32_t sb = smem_to_u32(smem);
    int tid = threadIdx.x;
    int wid = tid >> 5, lane = tid & 31;
    int m0 = blockIdx.y * 128, n0 = blockIdx.x * NT;
    int wm = (wid & 3) * 32;
    int wn = (wid >> 2) * (NT / 2);

    int nk0 = s0.K >> 6, nk1 = s1.K >> 6, nk2 = s2.K >> 6;
    int nk = nk0 + nk1 + nk2;

    auto issue = [&](int c) {
        int cs = c;
        const Seg* sg = &s0;
        if (cs >= nk0) { cs -= nk0; sg = &s1; if (cs >= nk1) { cs -= nk1; sg = &s2; } }
        int kt = cs << 6;
        uint32_t stu = sb + (c & 1) * STG;
        for (int s = tid; s < 2048; s += 256) {
            int pl = s >> 10, idx = s & 1023;
            int row = idx >> 3, q = idx & 7;
            const __nv_bfloat16* src =
                (pl ? sg->Al : sg->Ah) + (size_t)(m0 + row) * sg->lda + kt + q * 8;
            cpasync16(stu + pl * AP + swz(row * 128 + q * 16), src);
        }
        for (int s = tid; s < NT * 16; s += 256) {
            int pl = (s >= NT * 8) ? 1 : 0;
            int idx = pl ? s - NT * 8 : s;
            int row = idx >> 3, q = idx & 7;
            const __nv_bfloat16* src =
                (pl ? sg->Wl : sg->Wh) + (size_t)(n0 + row) * sg->ldw + kt + q * 8;
            cpasync16(stu + 2 * AP + pl * WP + swz(row * 128 + q * 16), src);
        }
        CP_COMMIT();
    };

    float acc[2][NA][4] = {};

    issue(0);
    for (int c = 0; c < nk; ++c) {
        if (c + 1 < nk) { issue(c + 1); CP_WAIT(1); }
        else            { CP_WAIT(0); }
        __syncthreads();

        uint32_t stu = sb + (c & 1) * STG;
        #pragma unroll
        for (int ks = 0; ks < 4; ++ks) {
            uint32_t ah[2][4], al[2][4];
            #pragma unroll
            for (int am = 0; am < 2; ++am) {
                uint32_t off = (uint32_t)(wm + am * 16 + (lane & 15)) * 128
                               + ks * 32 + (lane >> 4) * 16;
                ldsm4(ah[am], stu + swz(off));
                ldsm4(al[am], stu + AP + swz(off));
            }
            uint32_t bh[NA][2], bl[NA][2];
            #pragma unroll
            for (int j = 0; j < NA; ++j) {
                uint32_t off = (uint32_t)(wn + j * 8 + (lane & 7)) * 128
                               + ks * 32 + ((lane >> 3) & 1) * 16;
                ldsm2(bh[j], stu + 2 * AP + swz(off));
                ldsm2(bl[j], stu + 2 * AP + WP + swz(off));
            }
            #pragma unroll
            for (int am = 0; am < 2; ++am)
                #pragma unroll
                for (int j = 0; j < NA; ++j) {
                    mma16816(acc[am][j], ah[am], bh[j]);
                    mma16816(acc[am][j], ah[am], bl[j]);
                    mma16816(acc[am][j], al[am], bh[j]);
                }
        }
        __syncthreads();
    }

    #pragma unroll
    for (int am = 0; am < 2; ++am) {
        int r0 = m0 + wm + am * 16 + (lane >> 2);
        #pragma unroll
        for (int j = 0; j < NA; ++j) {
            int cc = n0 + wn + j * 8 + (lane & 3) * 2;
            float* p0 = C + (size_t)r0 * ldc + cc;
            float* p1 = C + (size_t)(r0 + 8) * ldc + cc;
            float2 v0 = make_float2(acc[am][j][0], acc[am][j][1]);
            float2 v1 = make_float2(acc[am][j][2], acc[am][j][3]);
            if (addTo) {
                float2 o0 = *(const float2*)p0, o1 = *(const float2*)p1;
                v0.x += o0.x; v0.y += o0.y; v1.x += o1.x; v1.y += o1.y;
            }
            *(float2*)p0 = v0;
            *(float2*)p1 = v1;
        }
    }
}

// ================= in-block sequential tanh recurrence ======================
__global__ __launch_bounds__(256) void scan_block(int b)
{
    __shared__ float ds[64][64];
    int tid = threadIdx.x;
    for (int idx = tid; idx < 4096; idx += 256) {
        int i = idx >> 6, j = idx & 63;
        ds[i][j] = g_D11[(size_t)(b * 64 + i) * NQc + b * 64 + j];
    }
    __syncthreads();

    int r = blockIdx.x * 256 + tid;
    float bb[64];
    const float4* bp = (const float4*)(g_base + (size_t)r * NQc + b * 64);
    #pragma unroll
    for (int q = 0; q < 16; ++q) {
        float4 v = bp[q];
        bb[q * 4 + 0] = v.x; bb[q * 4 + 1] = v.y;
        bb[q * 4 + 2] = v.z; bb[q * 4 + 3] = v.w;
    }
    float wv[64];
    #pragma unroll
    for (int i = 0; i < 64; ++i) {
        float s0 = 0.f, s1 = 0.f, s2 = 0.f, s3 = 0.f;
        #pragma unroll
        for (int j = 0; j < 64; ++j) {
            if (j < i) {
                float p = wv[j] * ds[i][j];
                if      ((j & 3) == 0) s0 += p;
                else if ((j & 3) == 1) s1 += p;
                else if ((j & 3) == 2) s2 += p;
                else                   s3 += p;
            }
        }
        wv[i] = ftanh(bb[i] + ((s0 + s1) + (s2 + s3)));
    }
    __nv_bfloat162* whp = (__nv_bfloat162*)(g_wh + (size_t)r * NQc + b * 64);
    __nv_bfloat162* wlp = (__nv_bfloat162*)(g_wl + (size_t)r * NQc + b * 64);
    #pragma unroll
    for (int q = 0; q < 32; ++q) {
        float a = wv[q * 2], c = wv[q * 2 + 1];
        __nv_bfloat162 h, l;
        h.x = __float2bfloat16(a); h.y = __float2bfloat16(c);
        l.x = __float2bfloat16(a - __bfloat162float(h.x));
        l.y = __float2bfloat16(c - __bfloat162float(h.y));
        whp[q] = h; wlp[q] = l;
    }
}

// ================= host orchestration =======================================
extern "C" void kernel_launch(void* const* d_in, const int* in_sizes, int n_in,
                              void* d_out, int out_size)
{
    const float* xi    = (const float*)d_in[1];
    const float* u     = (const float*)d_in[2];
    const float* Pstar = (const float*)d_in[3];
    const float* Chi   = (const float*)d_in[4];
    const float* Y1    = (const float*)d_in[5];
    const float* B2    = (const float*)d_in[6];
    const float* D12   = (const float*)d_in[7];
    const float* X     = (const float*)d_in[8];
    float* out = (float*)d_out;

    float *H, *P, *Linv, *base;
    __nv_bfloat16 *xih, *xil, *uh, *ul, *wh, *wl, *C1h, *C1l, *D11h, *D11l;
    __nv_bfloat16 *Sh, *Sl, *D12h, *D12l, *B2h, *B2l;
    float* S;
    cudaGetSymbolAddress((void**)&H, g_H);       cudaGetSymbolAddress((void**)&P, g_P);
    cudaGetSymbolAddress((void**)&Linv, g_Linv); cudaGetSymbolAddress((void**)&S, g_S);
    cudaGetSymbolAddress((void**)&base, g_base);
    cudaGetSymbolAddress((void**)&xih, g_xih);   cudaGetSymbolAddress((void**)&xil, g_xil);
    cudaGetSymbolAddress((void**)&uh, g_uh);     cudaGetSymbolAddress((void**)&ul, g_ul);
    cudaGetSymbolAddress((void**)&wh, g_wh);     cudaGetSymbolAddress((void**)&wl, g_wl);
    cudaGetSymbolAddress((void**)&C1h, g_C1h);   cudaGetSymbolAddress((void**)&C1l, g_C1l);
    cudaGetSymbolAddress((void**)&D11h, g_D11h); cudaGetSymbolAddress((void**)&D11l, g_D11l);
    cudaGetSymbolAddress((void**)&Sh, g_Sh);     cudaGetSymbolAddress((void**)&Sl, g_Sl);
    cudaGetSymbolAddress((void**)&D12h, g_D12h); cudaGetSymbolAddress((void**)&D12l, g_D12l);
    cudaGetSymbolAddress((void**)&B2h, g_B2h);   cudaGetSymbolAddress((void**)&B2l, g_B2l);

    constexpr int SM128 = 2 * (2 * 128 * 128 + 2 * 128 * 128);  // 131072
    constexpr int SM64  = 2 * (2 * 128 * 128 + 2 * 64 * 128);   // 98304
    cudaFuncSetAttribute(mma_gemm<128>, cudaFuncAttributeMaxDynamicSharedMemorySize, SM128);
    cudaFuncSetAttribute(mma_gemm<64>,  cudaFuncAttributeMaxDynamicSharedMemorySize, SM64);

    // split fp32 inputs into bf16 hi/lo planes
    splitk<<<16384, 256>>>(xi, xih, xil, Bc * NXc / 4);
    splitk<<<4096, 256>>>(u, uh, ul, Bc * NUc / 4);
    splitk<<<64, 256>>>(D12, D12h, D12l, NQc * NUc / 4);
    splitk<<<64, 256>>>(B2, B2h, B2l, NXc * NUc / 4);

    // H = X X^T (fp32, eps analytic); P = 0.5 Pstar Pstar^T + eps I
    bgemm_f32<<<dim3(16, 8), 256>>>(X, 1024, X, 1024, 1024, H, 1024);
    sgemm64<0, 1><<<dim3(8, 8), 256>>>(Pstar, 512, Pstar, 512, P, 512, 512, 0.5f, 0.0f, EPSc);
    prep_lam<<<1, 512>>>();
    prep_mats<<<1024, 256>>>(Y1, Chi);

    // Blocked Cholesky of P (fp32)
    for (int k = 0; k < 8; ++k) {
        potf2_inv<<<1, 256>>>(k);
        int Mrem = 512 - 64 * (k + 1);
        if (Mrem > 0) {
            float* panel = P + (size_t)(k + 1) * 64 * 512 + k * 64;
            sgemm64<0, 1><<<dim3(1, Mrem / 64), 256>>>(
                panel, 512, Linv + k * 4096, 64, panel, 512, 64, 1.0f, 0.0f, 0.0f);
            sgemm64<0, 1><<<dim3(Mrem / 64, Mrem / 64), 256>>>(
                panel, 512, panel, 512,
                P + (size_t)(k + 1) * 64 * 512 + (k + 1) * 64, 512, 64, -1.0f, 1.0f, 0.0f);
        }
    }

    // Fused triangular solves (fp32) -> S = [A | B1], then split to bf16 planes
    fwd_solve<<<16, 256>>>();
    bwd_solve<<<16, 256>>>();
    splitk<<<512, 256>>>(S, Sh, Sl, NXc * 1024 / 4);

    Seg zs = { nullptr, nullptr, nullptr, nullptr, 0, 0, 0 };

    // base = xi C1^T + u D12^T  (tensor cores via mma.sync)
    Seg sXC1 = { xih, xil, C1h, C1l, NXc, NXc, NXc };
    Seg sUD  = { uh, ul, D12h, D12l, NUc, NUc, NUc };
    mma_gemm<128><<<dim3(4, 256), 256, SM128>>>(sXC1, sUD, zs, base, NQc, 0);

    // blocked scan: cross-block tc GEMM + in-block sequential recurrence
    for (int b = 0; b < 8; ++b) {
        if (b > 0) {
            Seg sWD = { wh, wl, D11h + (size_t)b * 64 * NQc, D11l + (size_t)b * 64 * NQc,
                        NQc, NQc, 64 * b };
            mma_gemm<64><<<dim3(1, 256), 256, SM64>>>(sWD, zs, zs, base + b * 64, NQc, 1);
        }
        scan_block<<<128, 256>>>(b);
    }

    // out = xi A^T + w B1^T + u B2^T  (A = S[:,:512], B1 = S[:,512:])
    Seg sXA = { xih, xil, Sh, Sl, NXc, 1024, NXc };
    Seg sWB = { wh, wl, Sh + 512, Sl + 512, NQc, 1024, NQc };
    Seg sUB = { uh, ul, B2h, B2l, NUc, NUc, NUc };
    mma_gemm<128><<<dim3(4, 256), 256, SM128>>>(sXA, sWB, sUB, out, NXc, 0);
}

// round 4
// speedup vs baseline: 1.3695x; 1.0113x over previous
#include <cuda_runtime.h>
#include <cuda_bf16.h>
#include <cstdint>
#include <math.h>

#define NXc 512
#define NQc 512
#define NUc 128
#define Bc  32768
#define EPSc 1e-3f

// ================= baseline-ISA helpers (compute_103-safe) ==================
__device__ __forceinline__ uint32_t smem_to_u32(const void* p) {
    uint32_t a;
    asm("{ .reg .u64 t; cvta.to.shared.u64 t, %1; cvt.u32.u64 %0, t; }" : "=r"(a) : "l"(p));
    return a;
}
__device__ __forceinline__ void cpasync16(uint32_t d, const void* s) {
    asm volatile("cp.async.cg.shared.global [%0], [%1], 16;" :: "r"(d), "l"(s));
}
#define CP_COMMIT() asm volatile("cp.async.commit_group;" ::: "memory")
#define CP_WAIT(N)  asm volatile("cp.async.wait_group %0;" :: "n"(N) : "memory")

__device__ __forceinline__ void ldsm4(uint32_t* r, uint32_t addr) {
    asm volatile("ldmatrix.sync.aligned.m8n8.x4.shared.b16 {%0,%1,%2,%3}, [%4];"
        : "=r"(r[0]), "=r"(r[1]), "=r"(r[2]), "=r"(r[3]) : "r"(addr));
}
__device__ __forceinline__ void mma16816(float* d, const uint32_t* a, const uint32_t* b) {
    asm volatile("mma.sync.aligned.m16n8k16.row.col.f32.bf16.bf16.f32 "
        "{%0,%1,%2,%3}, {%4,%5,%6,%7}, {%8,%9}, {%0,%1,%2,%3};"
        : "+f"(d[0]), "+f"(d[1]), "+f"(d[2]), "+f"(d[3])
        : "r"(a[0]), "r"(a[1]), "r"(a[2]), "r"(a[3]), "r"(b[0]), "r"(b[1]));
}
// swizzle for 64-byte rows (SW64-style): xor 16B-column bits with row bits
__device__ __forceinline__ uint32_t swz64(uint32_t off) { return off ^ ((off >> 3) & 0x30); }

// ================= scratch (device globals) =================================
__device__ float g_H[1024 * 1024];
__device__ float g_P[NXc * NXc];
__device__ float g_Linv[8 * 64 * 64];
__device__ float g_rlam[NQc];
__device__ float g_D11[NQc * NQc];
__device__ float g_RHS[NXc * 1024];
__device__ float g_Z[NXc * 1024];
__device__ float g_S[NXc * 1024];
__device__ float g_base[(size_t)Bc * NQc];
__device__ unsigned g_barCnt;
__device__ __nv_bfloat16 g_xih[(size_t)Bc * NXc], g_xil[(size_t)Bc * NXc];
__device__ __nv_bfloat16 g_uh[(size_t)Bc * NUc],  g_ul[(size_t)Bc * NUc];
__device__ __nv_bfloat16 g_wh[(size_t)Bc * NQc],  g_wl[(size_t)Bc * NQc];
__device__ __nv_bfloat16 g_C1h[NQc * NXc],  g_C1l[NQc * NXc];
__device__ __nv_bfloat16 g_D11h[NQc * NQc], g_D11l[NQc * NQc];
__device__ __nv_bfloat16 g_Sh[NXc * 1024],  g_Sl[NXc * 1024];
__device__ __nv_bfloat16 g_D12h[NQc * NUc], g_D12l[NQc * NUc];
__device__ __nv_bfloat16 g_B2h[NXc * NUc],  g_B2l[NXc * NUc];

// ================= misc small kernels =======================================
__device__ __forceinline__ float ftanh(float x) {
    float a = fabsf(x);
    float t = __expf(-2.0f * a);
    float r = __fdividef(1.0f - t, 1.0f + t);
    return copysignf(r, x);
}

__global__ void splitk(const float* __restrict__ in, __nv_bfloat16* __restrict__ hi,
                       __nv_bfloat16* __restrict__ lo, int n4) {
    int i = blockIdx.x * 256 + threadIdx.x;
    if (i >= n4) return;
    float4 v = ((const float4*)in)[i];
    __nv_bfloat162 h0, h1, l0, l1;
    h0.x = __float2bfloat16(v.x); h0.y = __float2bfloat16(v.y);
    h1.x = __float2bfloat16(v.z); h1.y = __float2bfloat16(v.w);
    l0.x = __float2bfloat16(v.x - __bfloat162float(h0.x));
    l0.y = __float2bfloat16(v.y - __bfloat162float(h0.y));
    l1.x = __float2bfloat16(v.z - __bfloat162float(h1.x));
    l1.y = __float2bfloat16(v.w - __bfloat162float(h1.y));
    ((__nv_bfloat162*)hi)[i * 2] = h0; ((__nv_bfloat162*)hi)[i * 2 + 1] = h1;
    ((__nv_bfloat162*)lo)[i * 2] = l0; ((__nv_bfloat162*)lo)[i * 2 + 1] = l1;
}

__global__ void prep_lam() {
    int i = threadIdx.x;
    if (i < NQc) g_rlam[i] = 2.0f / (g_H[(size_t)(NXc + i) * 1024 + NXc + i] + EPSc);
}

__global__ void prep_mats(const float* __restrict__ Y1, const float* __restrict__ Chi) {
    int idx = blockIdx.x * 256 + threadIdx.x;
    int i = idx >> 9, j = idx & 511;
    float h1 = g_H[(size_t)i * 1024 + j];
    g_RHS[(size_t)i * 1024 + j] =
        -0.5f * (h1 + ((i == j) ? EPSc : 0.0f) + Y1[(size_t)i * 512 + j] - Y1[(size_t)j * 512 + i]);
    g_RHS[(size_t)i * 1024 + 512 + j] =
        -g_H[(size_t)i * 1024 + 512 + j] - Chi[(size_t)i * 512 + j];
    float rl = g_rlam[i];
    float d = (j < i) ? -g_H[(size_t)(512 + i) * 1024 + 512 + j] * rl : 0.0f;
    g_D11[(size_t)i * 512 + j] = d;
    __nv_bfloat16 dh = __float2bfloat16(d);
    g_D11h[(size_t)i * 512 + j] = dh;
    g_D11l[(size_t)i * 512 + j] = __float2bfloat16(d - __bfloat162float(dh));
    float c1 = Chi[(size_t)j * 512 + i] * rl;
    __nv_bfloat16 ch = __float2bfloat16(c1);
    g_C1h[(size_t)i * 512 + j] = ch;
    g_C1l[(size_t)i * 512 + j] = __float2bfloat16(c1 - __bfloat162float(ch));
}

__global__ void reset_bar() { if (threadIdx.x == 0) g_barCnt = 0u; }

// ================= fp32 SIMT GEMMs for prep path ============================
template <int TA, int TB>
__global__ __launch_bounds__(256) void sgemm64(
    const float* __restrict__ A, int lda,
    const float* __restrict__ B, int ldb,
    float* __restrict__ C, int ldc,
    int K, float alpha, float beta, float diagAdd)
{
    __shared__ float As[16][68];
    __shared__ float Bs[16][68];
    int tid = threadIdx.x;
    int m0 = blockIdx.y * 64, n0 = blockIdx.x * 64;
    int tx = tid & 15, ty = tid >> 4;
    float acc[4][4] = {};
    for (int kt = 0; kt < K; kt += 16) {
        __syncthreads();
        if (TA == 0) {
            int r = tid >> 2, kq = (tid & 3) * 4;
            float4 v = *(const float4*)(A + (size_t)(m0 + r) * lda + kt + kq);
            As[kq + 0][r] = v.x; As[kq + 1][r] = v.y; As[kq + 2][r] = v.z; As[kq + 3][r] = v.w;
        } else {
            int m4 = (tid & 15) * 4, k = tid >> 4;
            float4 v = *(const float4*)(A + (size_t)(kt + k) * lda + m0 + m4);
            As[k][m4 + 0] = v.x; As[k][m4 + 1] = v.y; As[k][m4 + 2] = v.z; As[k][m4 + 3] = v.w;
        }
        if (TB == 0) {
            int n4 = (tid & 15) * 4, k = tid >> 4;
            float4 v = *(const float4*)(B + (size_t)(kt + k) * ldb + n0 + n4);
            Bs[k][n4 + 0] = v.x; Bs[k][n4 + 1] = v.y; Bs[k][n4 + 2] = v.z; Bs[k][n4 + 3] = v.w;
        } else {
            int r = tid >> 2, kq = (tid & 3) * 4;
            float4 v = *(const float4*)(B + (size_t)(n0 + r) * ldb + kt + kq);
            Bs[kq + 0][r] = v.x; Bs[kq + 1][r] = v.y; Bs[kq + 2][r] = v.z; Bs[kq + 3][r] = v.w;
        }
        __syncthreads();
        #pragma unroll
        for (int kk = 0; kk < 16; ++kk) {
            float4 a = *(const float4*)&As[kk][ty * 4];
            float4 b = *(const float4*)&Bs[kk][tx * 4];
            float am[4] = {a.x, a.y, a.z, a.w};
            float bm[4] = {b.x, b.y, b.z, b.w};
            #pragma unroll
            for (int i = 0; i < 4; ++i)
                #pragma unroll
                for (int j = 0; j < 4; ++j)
                    acc[i][j] += am[i] * bm[j];
        }
    }
    #pragma unroll
    for (int i = 0; i < 4; ++i) {
        int gr = m0 + ty * 4 + i;
        #pragma unroll
        for (int j = 0; j < 4; ++j) {
            int gc = n0 + tx * 4 + j;
            float v = alpha * acc[i][j];
            if (beta != 0.0f) v += beta * C[(size_t)gr * ldc + gc];
            if (gr == gc) v += diagAdd;
            C[(size_t)gr * ldc + gc] = v;
        }
    }
}

// 128x64-tile fp32 GEMM (H = X X^T)
__global__ __launch_bounds__(256) void bgemm_f32(
    const float* __restrict__ A, int lda,
    const float* __restrict__ W, int ldw, int K,
    float* __restrict__ C, int ldc)
{
    __shared__ float As[16][132];
    __shared__ float Ws[16][68];
    float acc[8][4] = {};
    int tid = threadIdx.x;
    int m0 = blockIdx.y * 128, n0 = blockIdx.x * 64;
    int la_m = tid >> 2, la_k = (tid & 3) * 4;
    int tx = tid & 15, ty = tid >> 4;
    for (int kt = 0; kt < K; kt += 16) {
        __syncthreads();
        float4 a0 = *(const float4*)(A + (size_t)(m0 + la_m) * lda + kt + la_k);
        float4 a1 = *(const float4*)(A + (size_t)(m0 + la_m + 64) * lda + kt + la_k);
        float4 wv = *(const float4*)(W + (size_t)(n0 + la_m) * ldw + kt + la_k);
        As[la_k + 0][la_m] = a0.x; As[la_k + 1][la_m] = a0.y;
        As[la_k + 2][la_m] = a0.z; As[la_k + 3][la_m] = a0.w;
        As[la_k + 0][la_m + 64] = a1.x; As[la_k + 1][la_m + 64] = a1.y;
        As[la_k + 2][la_m + 64] = a1.z; As[la_k + 3][la_m + 64] = a1.w;
        Ws[la_k + 0][la_m] = wv.x; Ws[la_k + 1][la_m] = wv.y;
        Ws[la_k + 2][la_m] = wv.z; Ws[la_k + 3][la_m] = wv.w;
        __syncthreads();
        #pragma unroll
        for (int kk = 0; kk < 16; ++kk) {
            float4 af0 = *(const float4*)&As[kk][ty * 8];
            float4 af1 = *(const float4*)&As[kk][ty * 8 + 4];
            float4 wf  = *(const float4*)&Ws[kk][tx * 4];
            float am[8] = {af0.x, af0.y, af0.z, af0.w, af1.x, af1.y, af1.z, af1.w};
            float wn[4] = {wf.x, wf.y, wf.z, wf.w};
            #pragma unroll
            for (int i = 0; i < 8; ++i)
                #pragma unroll
                for (int j = 0; j < 4; ++j)
                    acc[i][j] += am[i] * wn[j];
        }
    }
    #pragma unroll
    for (int i = 0; i < 8; ++i) {
        float* cp = C + (size_t)(m0 + ty * 8 + i) * ldc + n0 + tx * 4;
        *(float4*)cp = make_float4(acc[i][0], acc[i][1], acc[i][2], acc[i][3]);
    }
}

// ================= fused solver (Cholesky + solves + split), 16 CTAs ========
__device__ __forceinline__ void gbar(unsigned& gen) {
    __syncthreads();
    gen += 16;
    if (threadIdx.x == 0) {
        __threadfence();
        atomicAdd(&g_barCnt, 1u);
        while (*(volatile unsigned*)&g_barCnt < gen) { }
        __threadfence();
    }
    __syncthreads();
}

__device__ void dev_potf2_inv(int k, float (*S)[65], float* Dinv, float* sdp)
{
    int tid = threadIdx.x;
    for (int idx = tid; idx < 4096; idx += 256) {
        int i = idx >> 6, j = idx & 63;
        S[i][j] = g_P[(size_t)(k * 64 + i) * NXc + k * 64 + j];
    }
    __syncthreads();
    for (int j = 0; j < 64; ++j) {
        if (tid == 0) *sdp = rsqrtf(S[j][j]);
        __syncthreads();
        if (tid >= j && tid < 64) S[tid][j] *= *sdp;
        __syncthreads();
        for (int idx = tid; idx < 4096; idx += 256) {
            int i = idx >> 6, c = idx & 63;
            if (i > j && c > j) S[i][c] -= S[i][j] * S[c][j];
        }
        __syncthreads();
    }
    if (tid < 64) Dinv[tid] = 1.0f / S[tid][tid];
    __syncthreads();
    int wd = tid >> 5, lane = tid & 31;
    for (int cc = 0; cc < 8; ++cc) {
        int c = wd * 8 + cc;
        float x0 = (lane == c) ? 1.0f : 0.0f;
        float x1 = (lane + 32 == c) ? 1.0f : 0.0f;
        for (int i = c; i < 64; ++i) {
            float src = (i < 32) ? x0 : x1;
            float part = __shfl_sync(0xffffffffu, src, i & 31);
            float xv = part * Dinv[i];
            if (i < 32) { if (lane == i) x0 = xv; }
            else        { if (lane == i - 32) x1 = xv; }
            if (lane > i)      x0 -= S[lane][i] * xv;
            if (lane + 32 > i) x1 -= S[lane + 32][i] * xv;
        }
        g_Linv[k * 4096 + lane * 64 + c] = x0;
        g_Linv[k * 4096 + (lane + 32) * 64 + c] = x1;
    }
}

// C(64x64) = beta*C + alpha * A(64x64) * B(64x64)^T   (row-major, K=64)
__device__ void dev_gemm_ABt64(const float* A, int lda, const float* B, int ldb,
                               float* C, int ldc, float alpha, float beta,
                               float (*As)[68], float (*Bs)[68])
{
    int tid = threadIdx.x;
    int tx = tid & 15, ty = tid >> 4;
    float acc[4][4] = {};
    for (int kt = 0; kt < 64; kt += 16) {
        __syncthreads();
        {
            int r = tid >> 2, kq = (tid & 3) * 4;
            float4 v = *(const float4*)(A + (size_t)r * lda + kt + kq);
            As[kq + 0][r] = v.x; As[kq + 1][r] = v.y; As[kq + 2][r] = v.z; As[kq + 3][r] = v.w;
            float4 w = *(const float4*)(B + (size_t)r * ldb + kt + kq);
            Bs[kq + 0][r] = w.x; Bs[kq + 1][r] = w.y; Bs[kq + 2][r] = w.z; Bs[kq + 3][r] = w.w;
        }
        __syncthreads();
        #pragma unroll
        for (int kk = 0; kk < 16; ++kk) {
            float4 a = *(const float4*)&As[kk][ty * 4];
            float4 b = *(const float4*)&Bs[kk][tx * 4];
            float am[4] = {a.x, a.y, a.z, a.w};
            float bm[4] = {b.x, b.y, b.z, b.w};
            #pragma unroll
            for (int i = 0; i < 4; ++i)
                #pragma unroll
                for (int j = 0; j < 4; ++j)
                    acc[i][j] += am[i] * bm[j];
        }
    }
    __syncthreads();
    #pragma unroll
    for (int i = 0; i < 4; ++i)
        #pragma unroll
        for (int j = 0; j < 4; ++j) {
            float v = alpha * acc[i][j];
            if (beta != 0.0f) v += beta * C[(size_t)(ty * 4 + i) * ldc + tx * 4 + j];
            C[(size_t)(ty * 4 + i) * ldc + tx * 4 + j] = v;
        }
}

__device__ void dev_fwd(int c0, float (*Lt)[65], float (*Zt)[65])
{
    int tid = threadIdx.x;
    int tx = tid & 15, ty = tid >> 4;
    for (int ib = 0; ib < 8; ++ib) {
        float acc[4][4] = {};
        for (int jb = 0; jb < ib; ++jb) {
            for (int idx = tid; idx < 4096; idx += 256) {
                int i = idx >> 6, j = idx & 63;
                Lt[i][j] = g_P[(size_t)(ib * 64 + i) * 512 + jb * 64 + j];
                Zt[i][j] = g_Z[(size_t)(jb * 64 + i) * 1024 + c0 + j];
            }
            __syncthreads();
            #pragma unroll 8
            for (int kk = 0; kk < 64; ++kk)
                #pragma unroll
                for (int ii = 0; ii < 4; ++ii)
                    #pragma unroll
                    for (int jj = 0; jj < 4; ++jj)
                        acc[ii][jj] += Lt[ty * 4 + ii][kk] * Zt[kk][tx * 4 + jj];
            __syncthreads();
        }
        #pragma unroll
        for (int ii = 0; ii < 4; ++ii)
            #pragma unroll
            for (int jj = 0; jj < 4; ++jj)
                Zt[ty * 4 + ii][tx * 4 + jj] =
                    g_RHS[(size_t)(ib * 64 + ty * 4 + ii) * 1024 + c0 + tx * 4 + jj] - acc[ii][jj];
        for (int idx = tid; idx < 4096; idx += 256) {
            int i = idx >> 6, j = idx & 63;
            Lt[i][j] = g_Linv[ib * 4096 + i * 64 + j];
        }
        __syncthreads();
        float z[4][4] = {};
        #pragma unroll 8
        for (int kk = 0; kk < 64; ++kk)
            #pragma unroll
            for (int ii = 0; ii < 4; ++ii)
                #pragma unroll
                for (int jj = 0; jj < 4; ++jj)
                    z[ii][jj] += Lt[ty * 4 + ii][kk] * Zt[kk][tx * 4 + jj];
        #pragma unroll
        for (int ii = 0; ii < 4; ++ii)
            #pragma unroll
            for (int jj = 0; jj < 4; ++jj)
                g_Z[(size_t)(ib * 64 + ty * 4 + ii) * 1024 + c0 + tx * 4 + jj] = z[ii][jj];
        __syncthreads();
    }
}

__device__ void dev_bwd(int c0, float (*Lt)[65], float (*Zt)[65])
{
    int tid = threadIdx.x;
    int tx = tid & 15, ty = tid >> 4;
    for (int ib = 7; ib >= 0; --ib) {
        float acc[4][4] = {};
        for (int jb = ib + 1; jb < 8; ++jb) {
            for (int idx = tid; idx < 4096; idx += 256) {
                int i = idx >> 6, j = idx & 63;
                Lt[i][j] = g_P[(size_t)(jb * 64 + i) * 512 + ib * 64 + j];
                Zt[i][j] = g_S[(size_t)(jb * 64 + i) * 1024 + c0 + j];
            }
            __syncthreads();
            #pragma unroll 8
            for (int kk = 0; kk < 64; ++kk)
                #pragma unroll
                for (int ii = 0; ii < 4; ++ii)
                    #pragma unroll
                    for (int jj = 0; jj < 4; ++jj)
                        acc[ii][jj] += Lt[kk][ty * 4 + ii] * Zt[kk][tx * 4 + jj];
            __syncthreads();
        }
        #pragma unroll
        for (int ii = 0; ii < 4; ++ii)
            #pragma unroll
            for (int jj = 0; jj < 4; ++jj)
                Zt[ty * 4 + ii][tx * 4 + jj] =
                    g_Z[(size_t)(ib * 64 + ty * 4 + ii) * 1024 + c0 + tx * 4 + jj] - acc[ii][jj];
        for (int idx = tid; idx < 4096; idx += 256) {
            int i = idx >> 6, j = idx & 63;
            Lt[i][j] = g_Linv[ib * 4096 + i * 64 + j];
        }
        __syncthreads();
        float z[4][4] = {};
        #pragma unroll 8
        for (int kk = 0; kk < 64; ++kk)
            #pragma unroll
            for (int ii = 0; ii < 4; ++ii)
                #pragma unroll
                for (int jj = 0; jj < 4; ++jj)
                    z[ii][jj] += Lt[kk][ty * 4 + ii] * Zt[kk][tx * 4 + jj];
        #pragma unroll
        for (int ii = 0; ii < 4; ++ii)
            #pragma unroll
            for (int jj = 0; jj < 4; ++jj)
                g_S[(size_t)(ib * 64 + ty * 4 + ii) * 1024 + c0 + tx * 4 + jj] = z[ii][jj];
        __syncthreads();
    }
}

__global__ __launch_bounds__(256) void solve_all()
{
    __shared__ float shA[16][68];
    __shared__ float shB[16][68];
    __shared__ float S64[64][65];
    __shared__ float T64[64][65];
    __shared__ float Dinv[64];
    __shared__ float sdv;
    int cta = blockIdx.x;
    int tid = threadIdx.x;
    unsigned gen = 0;

    // --- Blocked Cholesky of P (block 64) ---
    for (int k = 0; k < 8; ++k) {
        if (cta == 0) dev_potf2_inv(k, S64, Dinv, &sdv);
        gbar(gen);
        int nrem = 7 - k;
        if (nrem > 0) {
            if (cta < nrem) {
                int i = k + 1 + cta;
                float* panel = g_P + (size_t)i * 64 * 512 + k * 64;
                dev_gemm_ABt64(panel, 512, g_Linv + k * 4096, 64,
                               panel, 512, 1.0f, 0.0f, shA, shB);
            }
            gbar(gen);
            int t = 0;
            for (int i = k + 1; i < 8; ++i)
                for (int j = k + 1; j <= i; ++j, ++t)
                    if ((t & 15) == cta)
                        dev_gemm_ABt64(g_P + (size_t)i * 64 * 512 + k * 64, 512,
                                       g_P + (size_t)j * 64 * 512 + k * 64, 512,
                                       g_P + (size_t)i * 64 * 512 + j * 64, 512,
                                       -1.0f, 1.0f, shA, shB);
            gbar(gen);
        }
    }
    // --- fwd + bwd solves (per-CTA column slab, no cross deps) ---
    dev_fwd(cta * 64, S64, T64);
    dev_bwd(cta * 64, S64, T64);
    gbar(gen);
    // --- split S into bf16 hi/lo planes ---
    for (int i = cta * 256 + tid; i < NXc * 1024 / 4; i += 4096) {
        float4 v = ((const float4*)g_S)[i];
        __nv_bfloat162 h0, h1, l0, l1;
        h0.x = __float2bfloat16(v.x); h0.y = __float2bfloat16(v.y);
        h1.x = __float2bfloat16(v.z); h1.y = __float2bfloat16(v.w);
        l0.x = __float2bfloat16(v.x - __bfloat162float(h0.x));
        l0.y = __float2bfloat16(v.y - __bfloat162float(h0.y));
        l1.x = __float2bfloat16(v.z - __bfloat162float(h1.x));
        l1.y = __float2bfloat16(v.w - __bfloat162float(h1.y));
        ((__nv_bfloat162*)g_Sh)[i * 2] = h0; ((__nv_bfloat162*)g_Sh)[i * 2 + 1] = h1;
        ((__nv_bfloat162*)g_Sl)[i * 2] = l0; ((__nv_bfloat162*)g_Sl)[i * 2 + 1] = l1;
    }
}

// ================= mma.sync split-bf16 batch GEMM (v2) ======================
// Tile 128 x NT, 512 threads (16 warps: 4m x 4n, warp tile 32 x NT/4),
// K-chunk 32, 3-stage cp.async pipeline, 64B-row swizzled smem, all-ldsm4.
struct Seg {
    const __nv_bfloat16 *Ah, *Al, *Wh, *Wl;
    int lda, ldw, K;
};

template <int NT>
__global__ __launch_bounds__(512) void mma_gemm(
    Seg s0, Seg s1, Seg s2, float* __restrict__ C, int ldc, int addTo)
{
    extern __shared__ __align__(128) char smem[];
    constexpr int AP  = 128 * 64;      // bytes per A plane per stage (8 KB)
    constexpr int WP  = NT * 64;       // bytes per W plane per stage
    constexpr int STG = 2 * AP + 2 * WP;
    constexpr int NAw = NT / 32;       // n-atoms per warp

    uint32_t sb = smem_to_u32(smem);
    int tid = threadIdx.x;
    int wid = tid >> 5, lane = tid & 31;
    int m0 = blockIdx.y * 128, n0 = blockIdx.x * NT;
    int wm = (wid & 3) * 32;
    int wn = (wid >> 2) * (NT / 4);

    int nk0 = s0.K >> 5, nk1 = s1.K >> 5, nk2 = s2.K >> 5;
    int nk = nk0 + nk1 + nk2;

    auto issue = [&](int c) {
        int cs = c;
        const Seg* sg = &s0;
        if (cs >= nk0) { cs -= nk0; sg = &s1; if (cs >= nk1) { cs -= nk1; sg = &s2; } }
        int kt = cs << 5;
        uint32_t stu = sb + (c % 3) * STG;
        #pragma unroll
        for (int s = tid; s < 1024; s += 512) {
            int pl = s >> 9, rem = s & 511, row = rem >> 2, q = rem & 3;
            const __nv_bfloat16* src =
                (pl ? sg->Al : sg->Ah) + (size_t)(m0 + row) * sg->lda + kt + q * 8;
            cpasync16(stu + pl * AP + swz64(row * 64 + q * 16), src);
        }
        #pragma unroll
        for (int s = tid; s < NT * 8; s += 512) {
            int pl = (s >= NT * 4) ? 1 : 0;
            int rem = pl ? s - NT * 4 : s;
            int row = rem >> 2, q = rem & 3;
            const __nv_bfloat16* src =
                (pl ? sg->Wl : sg->Wh) + (size_t)(n0 + row) * sg->ldw + kt + q * 8;
            cpasync16(stu + 2 * AP + pl * WP + swz64(row * 64 + q * 16), src);
        }
        CP_COMMIT();
    };

    float acc[2][NAw][4] = {};

    issue(0); issue(1);
    for (int c = 0; c < nk; ++c) {
        if (c + 1 < nk) { CP_WAIT(1); } else { CP_WAIT(0); }
        __syncthreads();
        if (c + 2 < nk) issue(c + 2);
        uint32_t stu = sb + (c % 3) * STG;
        #pragma unroll
        for (int ks = 0; ks < 2; ++ks) {
            uint32_t ah[2][4], al[2][4];
            #pragma unroll
            for (int am = 0; am < 2; ++am) {
                uint32_t off = (uint32_t)(wm + am * 16 + (lane & 15)) * 64
                               + ks * 32 + (lane >> 4) * 16;
                ldsm4(ah[am], stu + swz64(off));
                ldsm4(al[am], stu + AP + swz64(off));
            }
            uint32_t bh[NAw][2], bl[NAw][2];
            #pragma unroll
            for (int p = 0; p < NAw / 2; ++p) {
                int g = lane >> 3;
                uint32_t off = (uint32_t)(wn + p * 16 + ((g >> 1) << 3) + (lane & 7)) * 64
                               + ks * 32 + (g & 1) * 16;
                uint32_t t4[4];
                ldsm4(t4, stu + 2 * AP + swz64(off));
                bh[2 * p][0] = t4[0]; bh[2 * p][1] = t4[1];
                bh[2 * p + 1][0] = t4[2]; bh[2 * p + 1][1] = t4[3];
                ldsm4(t4, stu + 2 * AP + WP + swz64(off));
                bl[2 * p][0] = t4[0]; bl[2 * p][1] = t4[1];
                bl[2 * p + 1][0] = t4[2]; bl[2 * p + 1][1] = t4[3];
            }
            #pragma unroll
            for (int am = 0; am < 2; ++am)
                #pragma unroll
                for (int j = 0; j < NAw; ++j) {
                    mma16816(acc[am][j], ah[am], bh[j]);
                    mma16816(acc[am][j], ah[am], bl[j]);
                    mma16816(acc[am][j], al[am], bh[j]);
                }
        }
        __syncthreads();
    }

    #pragma unroll
    for (int am = 0; am < 2; ++am) {
        int r0 = m0 + wm + am * 16 + (lane >> 2);
        #pragma unroll
        for (int j = 0; j < NAw; ++j) {
            int cc = n0 + wn + j * 8 + (lane & 3) * 2;
            float* p0 = C + (size_t)r0 * ldc + cc;
            float* p1 = C + (size_t)(r0 + 8) * ldc + cc;
            float2 v0 = make_float2(acc[am][j][0], acc[am][j][1]);
            float2 v1 = make_float2(acc[am][j][2], acc[am][j][3]);
            if (addTo) {
                float2 o0 = *(const float2*)p0, o1 = *(const float2*)p1;
                v0.x += o0.x; v0.y += o0.y; v1.x += o1.x; v1.y += o1.y;
            }
            *(float2*)p0 = v0;
            *(float2*)p1 = v1;
        }
    }
}

// ================= in-block sequential tanh recurrence ======================
__global__ __launch_bounds__(256) void scan_block(int b)
{
    __shared__ float ds[64][64];
    int tid = threadIdx.x;
    for (int idx = tid; idx < 4096; idx += 256) {
        int i = idx >> 6, j = idx & 63;
        ds[i][j] = g_D11[(size_t)(b * 64 + i) * NQc + b * 64 + j];
    }
    __syncthreads();

    int r = blockIdx.x * 256 + tid;
    float bb[64];
    const float4* bp = (const float4*)(g_base + (size_t)r * NQc + b * 64);
    #pragma unroll
    for (int q = 0; q < 16; ++q) {
        float4 v = bp[q];
        bb[q * 4 + 0] = v.x; bb[q * 4 + 1] = v.y;
        bb[q * 4 + 2] = v.z; bb[q * 4 + 3] = v.w;
    }
    float wv[64];
    #pragma unroll
    for (int i = 0; i < 64; ++i) {
        float s0 = 0.f, s1 = 0.f, s2 = 0.f, s3 = 0.f;
        #pragma unroll
        for (int j = 0; j < 64; ++j) {
            if (j < i) {
                float p = wv[j] * ds[i][j];
                if      ((j & 3) == 0) s0 += p;
                else if ((j & 3) == 1) s1 += p;
                else if ((j & 3) == 2) s2 += p;
                else                   s3 += p;
            }
        }
        wv[i] = ftanh(bb[i] + ((s0 + s1) + (s2 + s3)));
    }
    __nv_bfloat162* whp = (__nv_bfloat162*)(g_wh + (size_t)r * NQc + b * 64);
    __nv_bfloat162* wlp = (__nv_bfloat162*)(g_wl + (size_t)r * NQc + b * 64);
    #pragma unroll
    for (int q = 0; q < 32; ++q) {
        float a = wv[q * 2], c = wv[q * 2 + 1];
        __nv_bfloat162 h, l;
        h.x = __float2bfloat16(a); h.y = __float2bfloat16(c);
        l.x = __float2bfloat16(a - __bfloat162float(h.x));
        l.y = __float2bfloat16(c - __bfloat162float(h.y));
        whp[q] = h; wlp[q] = l;
    }
}

// ================= host orchestration =======================================
extern "C" void kernel_launch(void* const* d_in, const int* in_sizes, int n_in,
                              void* d_out, int out_size)
{
    const float* xi    = (const float*)d_in[1];
    const float* u     = (const float*)d_in[2];
    const float* Pstar = (const float*)d_in[3];
    const float* Chi   = (const float*)d_in[4];
    const float* Y1    = (const float*)d_in[5];
    const float* B2    = (const float*)d_in[6];
    const float* D12   = (const float*)d_in[7];
    const float* X     = (const float*)d_in[8];
    float* out = (float*)d_out;

    float *H, *P, *base;
    __nv_bfloat16 *xih, *xil, *uh, *ul, *wh, *wl, *C1h, *C1l, *D11h, *D11l;
    __nv_bfloat16 *Sh, *Sl, *D12h, *D12l, *B2h, *B2l;
    cudaGetSymbolAddress((void**)&H, g_H);       cudaGetSymbolAddress((void**)&P, g_P);
    cudaGetSymbolAddress((void**)&base, g_base);
    cudaGetSymbolAddress((void**)&xih, g_xih);   cudaGetSymbolAddress((void**)&xil, g_xil);
    cudaGetSymbolAddress((void**)&uh, g_uh);     cudaGetSymbolAddress((void**)&ul, g_ul);
    cudaGetSymbolAddress((void**)&wh, g_wh);     cudaGetSymbolAddress((void**)&wl, g_wl);
    cudaGetSymbolAddress((void**)&C1h, g_C1h);   cudaGetSymbolAddress((void**)&C1l, g_C1l);
    cudaGetSymbolAddress((void**)&D11h, g_D11h); cudaGetSymbolAddress((void**)&D11l, g_D11l);
    cudaGetSymbolAddress((void**)&Sh, g_Sh);     cudaGetSymbolAddress((void**)&Sl, g_Sl);
    cudaGetSymbolAddress((void**)&D12h, g_D12h); cudaGetSymbolAddress((void**)&D12l, g_D12l);
    cudaGetSymbolAddress((void**)&B2h, g_B2h);   cudaGetSymbolAddress((void**)&B2l, g_B2l);

    constexpr int SM128 = 3 * (2 * 128 * 64 + 2 * 128 * 64);  // 98304
    constexpr int SM64  = 3 * (2 * 128 * 64 + 2 * 64 * 64);   // 73728
    cudaFuncSetAttribute(mma_gemm<128>, cudaFuncAttributeMaxDynamicSharedMemorySize, SM128);
    cudaFuncSetAttribute(mma_gemm<64>,  cudaFuncAttributeMaxDynamicSharedMemorySize, SM64);

    // split fp32 inputs into bf16 hi/lo planes
    splitk<<<16384, 256>>>(xi, xih, xil, Bc * NXc / 4);
    splitk<<<4096, 256>>>(u, uh, ul, Bc * NUc / 4);
    splitk<<<64, 256>>>(D12, D12h, D12l, NQc * NUc / 4);
    splitk<<<64, 256>>>(B2, B2h, B2l, NXc * NUc / 4);

    // H = X X^T (fp32, eps analytic); P = 0.5 Pstar Pstar^T + eps I
    bgemm_f32<<<dim3(16, 8), 256>>>(X, 1024, X, 1024, 1024, H, 1024);
    sgemm64<0, 1><<<dim3(8, 8), 256>>>(Pstar, 512, Pstar, 512, P, 512, 512, 0.5f, 0.0f, EPSc);
    prep_lam<<<1, 512>>>();
    prep_mats<<<1024, 256>>>(Y1, Chi);

    // Fused Cholesky + triangular solves + S split (one kernel, 16 CTAs)
    reset_bar<<<1, 32>>>();
    solve_all<<<16, 256>>>();

    Seg zs = { nullptr, nullptr, nullptr, nullptr, 0, 0, 0 };

    // base = xi C1^T + u D12^T
    Seg sXC1 = { xih, xil, C1h, C1l, NXc, NXc, NXc };
    Seg sUD  = { uh, ul, D12h, D12l, NUc, NUc, NUc };
    mma_gemm<128><<<dim3(4, 256), 512, SM128>>>(sXC1, sUD, zs, base, NQc, 0);

    // blocked scan: cross-block tc GEMM + in-block sequential recurrence
    for (int b = 0; b < 8; ++b) {
        if (b > 0) {
            Seg sWD = { wh, wl, D11h + (size_t)b * 64 * NQc, D11l + (size_t)b * 64 * NQc,
                        NQc, NQc, 64 * b };
            mma_gemm<64><<<dim3(1, 256), 512, SM64>>>(sWD, zs, zs, base + b * 64, NQc, 1);
        }
        scan_block<<<128, 256>>>(b);
    }

    // out = xi A^T + w B1^T + u B2^T  (A = S[:,:512], B1 = S[:,512:])
    Seg sXA = { xih, xil, Sh, Sl, NXc, 1024, NXc };
    Seg sWB = { wh, wl, Sh + 512, Sl + 512, NQc, 1024, NQc };
    Seg sUB = { uh, ul, B2h, B2l, NUc, NUc, NUc };
    mma_gemm<128><<<dim3(4, 256), 512, SM128>>>(sXA, sWB, sUB, out, NXc, 0);
}

// round 7
// speedup vs baseline: 1.4940x; 1.0909x over previous
#include <cuda_runtime.h>
#include <cuda_bf16.h>
#include <cstdint>
#include <math.h>

#define NXc 512
#define NQc 512
#define NUc 128
#define Bc  32768
#define EPSc 1e-3f

// ================= baseline-ISA helpers (compute_103-safe) ==================
__device__ __forceinline__ uint32_t smem_to_u32(const void* p) {
    uint32_t a;
    asm("{ .reg .u64 t; cvta.to.shared.u64 t, %1; cvt.u32.u64 %0, t; }" : "=r"(a) : "l"(p));
    return a;
}
__device__ __forceinline__ void cpasync16(uint32_t d, const void* s) {
    asm volatile("cp.async.cg.shared.global [%0], [%1], 16;" :: "r"(d), "l"(s));
}
#define CP_COMMIT() asm volatile("cp.async.commit_group;" ::: "memory")
#define CP_WAIT(N)  asm volatile("cp.async.wait_group %0;" :: "n"(N) : "memory")

__device__ __forceinline__ void ldsm4(uint32_t* r, uint32_t addr) {
    asm volatile("ldmatrix.sync.aligned.m8n8.x4.shared.b16 {%0,%1,%2,%3}, [%4];"
        : "=r"(r[0]), "=r"(r[1]), "=r"(r[2]), "=r"(r[3]) : "r"(addr));
}
__device__ __forceinline__ void mma16816(float* d, const uint32_t* a, const uint32_t* b) {
    asm volatile("mma.sync.aligned.m16n8k16.row.col.f32.bf16.bf16.f32 "
        "{%0,%1,%2,%3}, {%4,%5,%6,%7}, {%8,%9}, {%0,%1,%2,%3};"
        : "+f"(d[0]), "+f"(d[1]), "+f"(d[2]), "+f"(d[3])
        : "r"(a[0]), "r"(a[1]), "r"(a[2]), "r"(a[3]), "r"(b[0]), "r"(b[1]));
}
__device__ __forceinline__ uint32_t swz64(uint32_t off) { return off ^ ((off >> 3) & 0x30); }

// ================= scratch (device globals) =================================
__device__ float g_H[1024 * 1024];
__device__ float g_P[NXc * NXc];
__device__ float g_Linv[8 * 64 * 64];
__device__ float g_D11[NQc * NQc];
__device__ float g_RHS[NXc * 1024];
__device__ float g_Z[NXc * 1024];
__device__ float g_S[NXc * 1024];
__device__ float g_base[(size_t)Bc * NQc];
__device__ unsigned g_barCnt;
__device__ __nv_bfloat16 g_xih[(size_t)Bc * NXc], g_xil[(size_t)Bc * NXc];
__device__ __nv_bfloat16 g_uh[(size_t)Bc * NUc],  g_ul[(size_t)Bc * NUc];
__device__ __nv_bfloat16 g_wh[(size_t)Bc * NQc],  g_wl[(size_t)Bc * NQc];
__device__ __nv_bfloat16 g_Xh[1024 * 1024], g_Xl[1024 * 1024];
__device__ __nv_bfloat16 g_C1h[NQc * NXc],  g_C1l[NQc * NXc];
__device__ __nv_bfloat16 g_D11h[NQc * NQc], g_D11l[NQc * NQc];
__device__ __nv_bfloat16 g_Sh[NXc * 1024],  g_Sl[NXc * 1024];
__device__ __nv_bfloat16 g_D12h[NQc * NUc], g_D12l[NQc * NUc];
__device__ __nv_bfloat16 g_B2h[NXc * NUc],  g_B2l[NXc * NUc];

// ================= misc small kernels =======================================
__device__ __forceinline__ float ftanh(float x) {
    float a = fabsf(x);
    float t = __expf(-2.0f * a);
    float r = __fdividef(1.0f - t, 1.0f + t);
    return copysignf(r, x);
}

__global__ void splitk(const float* __restrict__ in, __nv_bfloat16* __restrict__ hi,
                       __nv_bfloat16* __restrict__ lo, int n4) {
    int i = blockIdx.x * 256 + threadIdx.x;
    if (i >= n4) return;
    float4 v = ((const float4*)in)[i];
    __nv_bfloat162 h0, h1, l0, l1;
    h0.x = __float2bfloat16(v.x); h0.y = __float2bfloat16(v.y);
    h1.x = __float2bfloat16(v.z); h1.y = __float2bfloat16(v.w);
    l0.x = __float2bfloat16(v.x - __bfloat162float(h0.x));
    l0.y = __float2bfloat16(v.y - __bfloat162float(h0.y));
    l1.x = __float2bfloat16(v.z - __bfloat162float(h1.x));
    l1.y = __float2bfloat16(v.w - __bfloat162float(h1.y));
    ((__nv_bfloat162*)hi)[i * 2] = h0; ((__nv_bfloat162*)hi)[i * 2 + 1] = h1;
    ((__nv_bfloat162*)lo)[i * 2] = l0; ((__nv_bfloat162*)lo)[i * 2 + 1] = l1;
}

// prep: RHS, D11 (+planes), C1 planes, D12/B2 planes; rlam computed inline
__global__ void prep_mats2(const float* __restrict__ Y1, const float* __restrict__ Chi,
                           const float* __restrict__ D12, const float* __restrict__ B2) {
    int idx = blockIdx.x * 256 + threadIdx.x;
    int i = idx >> 9, j = idx & 511;
    float h1 = g_H[(size_t)i * 1024 + j];
    g_RHS[(size_t)i * 1024 + j] =
        -0.5f * (h1 + ((i == j) ? EPSc : 0.0f) + Y1[(size_t)i * 512 + j] - Y1[(size_t)j * 512 + i]);
    g_RHS[(size_t)i * 1024 + 512 + j] =
        -g_H[(size_t)i * 1024 + 512 + j] - Chi[(size_t)i * 512 + j];
    float rl = 2.0f / (g_H[(size_t)(NXc + i) * 1024 + NXc + i] + EPSc);
    float d = (j < i) ? -g_H[(size_t)(512 + i) * 1024 + 512 + j] * rl : 0.0f;
    g_D11[(size_t)i * 512 + j] = d;
    __nv_bfloat16 dh = __float2bfloat16(d);
    g_D11h[(size_t)i * 512 + j] = dh;
    g_D11l[(size_t)i * 512 + j] = __float2bfloat16(d - __bfloat162float(dh));
    float c1 = Chi[(size_t)j * 512 + i] * rl;
    __nv_bfloat16 ch = __float2bfloat16(c1);
    g_C1h[(size_t)i * 512 + j] = ch;
    g_C1l[(size_t)i * 512 + j] = __float2bfloat16(c1 - __bfloat162float(ch));
    if (j < NUc) {
        float v = D12[(size_t)i * NUc + j];
        __nv_bfloat16 vh = __float2bfloat16(v);
        g_D12h[(size_t)i * NUc + j] = vh;
        g_D12l[(size_t)i * NUc + j] = __float2bfloat16(v - __bfloat162float(vh));
        float w = B2[(size_t)i * NUc + j];
        __nv_bfloat16 wh = __float2bfloat16(w);
        g_B2h[(size_t)i * NUc + j] = wh;
        g_B2l[(size_t)i * NUc + j] = __float2bfloat16(w - __bfloat162float(wh));
    }
}

__global__ void reset_bar() { if (threadIdx.x == 0) g_barCnt = 0u; }

// ================= fp32 SIMT GEMM (P = 0.5 Pstar Pstar^T + eps I) ===========
template <int TA, int TB>
__global__ __launch_bounds__(256) void sgemm64(
    const float* __restrict__ A, int lda,
    const float* __restrict__ B, int ldb,
    float* __restrict__ C, int ldc,
    int K, float alpha, float beta, float diagAdd)
{
    __shared__ float As[16][68];
    __shared__ float Bs[16][68];
    int tid = threadIdx.x;
    int m0 = blockIdx.y * 64, n0 = blockIdx.x * 64;
    int tx = tid & 15, ty = tid >> 4;
    float acc[4][4] = {};
    for (int kt = 0; kt < K; kt += 16) {
        __syncthreads();
        if (TA == 0) {
            int r = tid >> 2, kq = (tid & 3) * 4;
            float4 v = *(const float4*)(A + (size_t)(m0 + r) * lda + kt + kq);
            As[kq + 0][r] = v.x; As[kq + 1][r] = v.y; As[kq + 2][r] = v.z; As[kq + 3][r] = v.w;
        } else {
            int m4 = (tid & 15) * 4, k = tid >> 4;
            float4 v = *(const float4*)(A + (size_t)(kt + k) * lda + m0 + m4);
            As[k][m4 + 0] = v.x; As[k][m4 + 1] = v.y; As[k][m4 + 2] = v.z; As[k][m4 + 3] = v.w;
        }
        if (TB == 0) {
            int n4 = (tid & 15) * 4, k = tid >> 4;
            float4 v = *(const float4*)(B + (size_t)(kt + k) * ldb + n0 + n4);
            Bs[k][n4 + 0] = v.x; Bs[k][n4 + 1] = v.y; Bs[k][n4 + 2] = v.z; Bs[k][n4 + 3] = v.w;
        } else {
            int r = tid >> 2, kq = (tid & 3) * 4;
            float4 v = *(const float4*)(B + (size_t)(n0 + r) * ldb + kt + kq);
            Bs[kq + 0][r] = v.x; Bs[kq + 1][r] = v.y; Bs[kq + 2][r] = v.z; Bs[kq + 3][r] = v.w;
        }
        __syncthreads();
        #pragma unroll
        for (int kk = 0; kk < 16; ++kk) {
            float4 a = *(const float4*)&As[kk][ty * 4];
            float4 b = *(const float4*)&Bs[kk][tx * 4];
            float am[4] = {a.x, a.y, a.z, a.w};
            float bm[4] = {b.x, b.y, b.z, b.w};
            #pragma unroll
            for (int i = 0; i < 4; ++i)
                #pragma unroll
                for (int j = 0; j < 4; ++j)
                    acc[i][j] += am[i] * bm[j];
        }
    }
    #pragma unroll
    for (int i = 0; i < 4; ++i) {
        int gr = m0 + ty * 4 + i;
        #pragma unroll
        for (int j = 0; j < 4; ++j) {
            int gc = n0 + tx * 4 + j;
            float v = alpha * acc[i][j];
            if (beta != 0.0f) v += beta * C[(size_t)gr * ldc + gc];
            if (gr == gc) v += diagAdd;
            C[(size_t)gr * ldc + gc] = v;
        }
    }
}

// ================= fused solver (Cholesky + solves + split), 16 CTAs ========
__device__ __forceinline__ void gbar(unsigned& gen) {
    __syncthreads();
    gen += 16;
    if (threadIdx.x == 0) {
        __threadfence();
        atomicAdd(&g_barCnt, 1u);
        while (*(volatile unsigned*)&g_barCnt < gen) { }
        __threadfence();
    }
    __syncthreads();
}

__device__ void dev_potf2_inv(int k, float (*S)[65], float* Dinv, float* sdp)
{
    int tid = threadIdx.x;
    for (int idx = tid; idx < 4096; idx += 256) {
        int i = idx >> 6, j = idx & 63;
        S[i][j] = g_P[(size_t)(k * 64 + i) * NXc + k * 64 + j];
    }
    __syncthreads();
    for (int j = 0; j < 64; ++j) {
        if (tid == 0) *sdp = rsqrtf(S[j][j]);
        __syncthreads();
        if (tid >= j && tid < 64) S[tid][j] *= *sdp;
        __syncthreads();
        for (int idx = tid; idx < 4096; idx += 256) {
            int i = idx >> 6, c = idx & 63;
            if (i > j && c > j) S[i][c] -= S[i][j] * S[c][j];
        }
        __syncthreads();
    }
    if (tid < 64) Dinv[tid] = 1.0f / S[tid][tid];
    __syncthreads();
    int wd = tid >> 5, lane = tid & 31;
    for (int cc = 0; cc < 8; ++cc) {
        int c = wd * 8 + cc;
        float x0 = (lane == c) ? 1.0f : 0.0f;
        float x1 = (lane + 32 == c) ? 1.0f : 0.0f;
        for (int i = c; i < 64; ++i) {
            float src = (i < 32) ? x0 : x1;
            float part = __shfl_sync(0xffffffffu, src, i & 31);
            float xv = part * Dinv[i];
            if (i < 32) { if (lane == i) x0 = xv; }
            else        { if (lane == i - 32) x1 = xv; }
            if (lane > i)      x0 -= S[lane][i] * xv;
            if (lane + 32 > i) x1 -= S[lane + 32][i] * xv;
        }
        g_Linv[k * 4096 + lane * 64 + c] = x0;
        g_Linv[k * 4096 + (lane + 32) * 64 + c] = x1;
    }
}

__device__ void dev_gemm_ABt64(const float* A, int lda, const float* B, int ldb,
                               float* C, int ldc, float alpha, float beta,
                               float (*As)[68], float (*Bs)[68])
{
    int tid = threadIdx.x;
    int tx = tid & 15, ty = tid >> 4;
    float acc[4][4] = {};
    for (int kt = 0; kt < 64; kt += 16) {
        __syncthreads();
        {
            int r = tid >> 2, kq = (tid & 3) * 4;
            float4 v = *(const float4*)(A + (size_t)r * lda + kt + kq);
            As[kq + 0][r] = v.x; As[kq + 1][r] = v.y; As[kq + 2][r] = v.z; As[kq + 3][r] = v.w;
            float4 w = *(const float4*)(B + (size_t)r * ldb + kt + kq);
            Bs[kq + 0][r] = w.x; Bs[kq + 1][r] = w.y; Bs[kq + 2][r] = w.z; Bs[kq + 3][r] = w.w;
        }
        __syncthreads();
        #pragma unroll
        for (int kk = 0; kk < 16; ++kk) {
            float4 a = *(const float4*)&As[kk][ty * 4];
            float4 b = *(const float4*)&Bs[kk][tx * 4];
            float am[4] = {a.x, a.y, a.z, a.w};
            float bm[4] = {b.x, b.y, b.z, b.w};
            #pragma unroll
            for (int i = 0; i < 4; ++i)
                #pragma unroll
                for (int j = 0; j < 4; ++j)
                    acc[i][j] += am[i] * bm[j];
        }
    }
    __syncthreads();
    #pragma unroll
    for (int i = 0; i < 4; ++i)
        #pragma unroll
        for (int j = 0; j < 4; ++j) {
            float v = alpha * acc[i][j];
            if (beta != 0.0f) v += beta * C[(size_t)(ty * 4 + i) * ldc + tx * 4 + j];
            C[(size_t)(ty * 4 + i) * ldc + tx * 4 + j] = v;
        }
}

__device__ void dev_fwd(int c0, float (*Lt)[65], float (*Zt)[65])
{
    int tid = threadIdx.x;
    int tx = tid & 15, ty = tid >> 4;
    for (int ib = 0; ib < 8; ++ib) {
        float acc[4][4] = {};
        for (int jb = 0; jb < ib; ++jb) {
            for (int idx = tid; idx < 4096; idx += 256) {
                int i = idx >> 6, j = idx & 63;
                Lt[i][j] = g_P[(size_t)(ib * 64 + i) * 512 + jb * 64 + j];
                Zt[i][j] = g_Z[(size_t)(jb * 64 + i) * 1024 + c0 + j];
            }
            __syncthreads();
            #pragma unroll 8
            for (int kk = 0; kk < 64; ++kk)
                #pragma unroll
                for (int ii = 0; ii < 4; ++ii)
                    #pragma unroll
                    for (int jj = 0; jj < 4; ++jj)
                        acc[ii][jj] += Lt[ty * 4 + ii][kk] * Zt[kk][tx * 4 + jj];
            __syncthreads();
        }
        #pragma unroll
        for (int ii = 0; ii < 4; ++ii)
            #pragma unroll
            for (int jj = 0; jj < 4; ++jj)
                Zt[ty * 4 + ii][tx * 4 + jj] =
                    g_RHS[(size_t)(ib * 64 + ty * 4 + ii) * 1024 + c0 + tx * 4 + jj] - acc[ii][jj];
        for (int idx = tid; idx < 4096; idx += 256) {
            int i = idx >> 6, j = idx & 63;
            Lt[i][j] = g_Linv[ib * 4096 + i * 64 + j];
        }
        __syncthreads();
        float z[4][4] = {};
        #pragma unroll 8
        for (int kk = 0; kk < 64; ++kk)
            #pragma unroll
            for (int ii = 0; ii < 4; ++ii)
                #pragma unroll
                for (int jj = 0; jj < 4; ++jj)
                    z[ii][jj] += Lt[ty * 4 + ii][kk] * Zt[kk][tx * 4 + jj];
        #pragma unroll
        for (int ii = 0; ii < 4; ++ii)
            #pragma unroll
            for (int jj = 0; jj < 4; ++jj)
                g_Z[(size_t)(ib * 64 + ty * 4 + ii) * 1024 + c0 + tx * 4 + jj] = z[ii][jj];
        __syncthreads();
    }
}

__device__ void dev_bwd(int c0, float (*Lt)[65], float (*Zt)[65])
{
    int tid = threadIdx.x;
    int tx = tid & 15, ty = tid >> 4;
    for (int ib = 7; ib >= 0; --ib) {
        float acc[4][4] = {};
        for (int jb = ib + 1; jb < 8; ++jb) {
            for (int idx = tid; idx < 4096; idx += 256) {
                int i = idx >> 6, j = idx & 63;
                Lt[i][j] = g_P[(size_t)(jb * 64 + i) * 512 + ib * 64 + j];
                Zt[i][j] = g_S[(size_t)(jb * 64 + i) * 1024 + c0 + j];
            }
            __syncthreads();
            #pragma unroll 8
            for (int kk = 0; kk < 64; ++kk)
                #pragma unroll
                for (int ii = 0; ii < 4; ++ii)
                    #pragma unroll
                    for (int jj = 0; jj < 4; ++jj)
                        acc[ii][jj] += Lt[kk][ty * 4 + ii] * Zt[kk][tx * 4 + jj];
            __syncthreads();
        }
        #pragma unroll
        for (int ii = 0; ii < 4; ++ii)
            #pragma unroll
            for (int jj = 0; jj < 4; ++jj)
                Zt[ty * 4 + ii][tx * 4 + jj] =
                    g_Z[(size_t)(ib * 64 + ty * 4 + ii) * 1024 + c0 + tx * 4 + jj] - acc[ii][jj];
        for (int idx = tid; idx < 4096; idx += 256) {
            int i = idx >> 6, j = idx & 63;
            Lt[i][j] = g_Linv[ib * 4096 + i * 64 + j];
        }
        __syncthreads();
        float z[4][4] = {};
        #pragma unroll 8
        for (int kk = 0; kk < 64; ++kk)
            #pragma unroll
            for (int ii = 0; ii < 4; ++ii)
                #pragma unroll
                for (int jj = 0; jj < 4; ++jj)
                    z[ii][jj] += Lt[kk][ty * 4 + ii] * Zt[kk][tx * 4 + jj];
        #pragma unroll
        for (int ii = 0; ii < 4; ++ii)
            #pragma unroll
            for (int jj = 0; jj < 4; ++jj)
                g_S[(size_t)(ib * 64 + ty * 4 + ii) * 1024 + c0 + tx * 4 + jj] = z[ii][jj];
        __syncthreads();
    }
}

__global__ __launch_bounds__(256) void solve_all()
{
    __shared__ float shA[16][68];
    __shared__ float shB[16][68];
    __shared__ float S64[64][65];
    __shared__ float T64[64][65];
    __shared__ float Dinv[64];
    __shared__ float sdv;
    int cta = blockIdx.x;
    int tid = threadIdx.x;
    unsigned gen = 0;

    for (int k = 0; k < 8; ++k) {
        if (cta == 0) dev_potf2_inv(k, S64, Dinv, &sdv);
        gbar(gen);
        int nrem = 7 - k;
        if (nrem > 0) {
            if (cta < nrem) {
                int i = k + 1 + cta;
                float* panel = g_P + (size_t)i * 64 * 512 + k * 64;
                dev_gemm_ABt64(panel, 512, g_Linv + k * 4096, 64,
                               panel, 512, 1.0f, 0.0f, shA, shB);
            }
            gbar(gen);
            int t = 0;
            for (int i = k + 1; i < 8; ++i)
                for (int j = k + 1; j <= i; ++j, ++t)
                    if ((t & 15) == cta)
                        dev_gemm_ABt64(g_P + (size_t)i * 64 * 512 + k * 64, 512,
                                       g_P + (size_t)j * 64 * 512 + k * 64, 512,
                                       g_P + (size_t)i * 64 * 512 + j * 64, 512,
                                       -1.0f, 1.0f, shA, shB);
            gbar(gen);
        }
    }
    dev_fwd(cta * 64, S64, T64);
    dev_bwd(cta * 64, S64, T64);
    gbar(gen);
    for (int i = cta * 256 + tid; i < NXc * 1024 / 4; i += 4096) {
        float4 v = ((const float4*)g_S)[i];
        __nv_bfloat162 h0, h1, l0, l1;
        h0.x = __float2bfloat16(v.x); h0.y = __float2bfloat16(v.y);
        h1.x = __float2bfloat16(v.z); h1.y = __float2bfloat16(v.w);
        l0.x = __float2bfloat16(v.x - __bfloat162float(h0.x));
        l0.y = __float2bfloat16(v.y - __bfloat162float(h0.y));
        l1.x = __float2bfloat16(v.z - __bfloat162float(h1.x));
        l1.y = __float2bfloat16(v.w - __bfloat162float(h1.y));
        ((__nv_bfloat162*)g_Sh)[i * 2] = h0; ((__nv_bfloat162*)g_Sh)[i * 2 + 1] = h1;
        ((__nv_bfloat162*)g_Sl)[i * 2] = l0; ((__nv_bfloat162*)g_Sl)[i * 2 + 1] = l1;
    }
}

// ================= mma.sync split-bf16 batch GEMM ===========================
struct Seg {
    const __nv_bfloat16 *Ah, *Al, *Wh, *Wl;
    int lda, ldw, K;
};

template <int NT>
__global__ __launch_bounds__(512) void mma_gemm(
    Seg s0, Seg s1, Seg s2, float* __restrict__ C, int ldc, int addTo)
{
    extern __shared__ __align__(128) char smem[];
    constexpr int AP  = 128 * 64;
    constexpr int WP  = NT * 64;
    constexpr int STG = 2 * AP + 2 * WP;
    constexpr int NAw = NT / 32;

    uint32_t sb = smem_to_u32(smem);
    int tid = threadIdx.x;
    int wid = tid >> 5, lane = tid & 31;
    int m0 = blockIdx.y * 128, n0 = blockIdx.x * NT;
    int wm = (wid & 3) * 32;
    int wn = (wid >> 2) * (NT / 4);

    int nk0 = s0.K >> 5, nk1 = s1.K >> 5, nk2 = s2.K >> 5;
    int nk = nk0 + nk1 + nk2;

    auto issue = [&](int c) {
        int cs = c;
        const Seg* sg = &s0;
        if (cs >= nk0) { cs -= nk0; sg = &s1; if (cs >= nk1) { cs -= nk1; sg = &s2; } }
        int kt = cs << 5;
        uint32_t stu = sb + (c % 3) * STG;
        #pragma unroll
        for (int s = tid; s < 1024; s += 512) {
            int pl = s >> 9, rem = s & 511, row = rem >> 2, q = rem & 3;
            const __nv_bfloat16* src =
                (pl ? sg->Al : sg->Ah) + (size_t)(m0 + row) * sg->lda + kt + q * 8;
            cpasync16(stu + pl * AP + swz64(row * 64 + q * 16), src);
        }
        #pragma unroll
        for (int s = tid; s < NT * 8; s += 512) {
            int pl = (s >= NT * 4) ? 1 : 0;
            int rem = pl ? s - NT * 4 : s;
            int row = rem >> 2, q = rem & 3;
            const __nv_bfloat16* src =
                (pl ? sg->Wl : sg->Wh) + (size_t)(n0 + row) * sg->ldw + kt + q * 8;
            cpasync16(stu + 2 * AP + pl * WP + swz64(row * 64 + q * 16), src);
        }
        CP_COMMIT();
    };

    float acc[2][NAw][4] = {};

    issue(0); issue(1);
    for (int c = 0; c < nk; ++c) {
        if (c + 1 < nk) { CP_WAIT(1); } else { CP_WAIT(0); }
        __syncthreads();
        if (c + 2 < nk) issue(c + 2);
        uint32_t stu = sb + (c % 3) * STG;
        #pragma unroll
        for (int ks = 0; ks < 2; ++ks) {
            uint32_t ah[2][4], al[2][4];
            #pragma unroll
            for (int am = 0; am < 2; ++am) {
                uint32_t off = (uint32_t)(wm + am * 16 + (lane & 15)) * 64
                               + ks * 32 + (lane >> 4) * 16;
                ldsm4(ah[am], stu + swz64(off));
                ldsm4(al[am], stu + AP + swz64(off));
            }
            uint32_t bh[NAw][2], bl[NAw][2];
            #pragma unroll
            for (int p = 0; p < NAw / 2; ++p) {
                int g = lane >> 3;
                uint32_t off = (uint32_t)(wn + p * 16 + ((g >> 1) << 3) + (lane & 7)) * 64
                               + ks * 32 + (g & 1) * 16;
                uint32_t t4[4];
                ldsm4(t4, stu + 2 * AP + swz64(off));
                bh[2 * p][0] = t4[0]; bh[2 * p][1] = t4[1];
                bh[2 * p + 1][0] = t4[2]; bh[2 * p + 1][1] = t4[3];
                ldsm4(t4, stu + 2 * AP + WP + swz64(off));
                bl[2 * p][0] = t4[0]; bl[2 * p][1] = t4[1];
                bl[2 * p + 1][0] = t4[2]; bl[2 * p + 1][1] = t4[3];
            }
            #pragma unroll
            for (int am = 0; am < 2; ++am)
                #pragma unroll
                for (int j = 0; j < NAw; ++j) {
                    mma16816(acc[am][j], ah[am], bh[j]);
                    mma16816(acc[am][j], ah[am], bl[j]);
                    mma16816(acc[am][j], al[am], bh[j]);
                }
        }
        __syncthreads();
    }

    #pragma unroll
    for (int am = 0; am < 2; ++am) {
        int r0 = m0 + wm + am * 16 + (lane >> 2);
        #pragma unroll
        for (int j = 0; j < NAw; ++j) {
            int cc = n0 + wn + j * 8 + (lane & 3) * 2;
            float* p0 = C + (size_t)r0 * ldc + cc;
            float* p1 = C + (size_t)(r0 + 8) * ldc + cc;
            float2 v0 = make_float2(acc[am][j][0], acc[am][j][1]);
            float2 v1 = make_float2(acc[am][j][2], acc[am][j][3]);
            if (addTo) {
                float2 o0 = *(const float2*)p0, o1 = *(const float2*)p1;
                v0.x += o0.x; v0.y += o0.y; v1.x += o1.x; v1.y += o1.y;
            }
            *(float2*)p0 = v0;
            *(float2*)p1 = v1;
        }
    }
}

// ================= fused cross-GEMM + in-block scan =========================
// One launch per 64-col block b. 128 CTAs x 256 threads; CTA strip = 256 rows.
// Phase 1 (b>0): cross[256x64] = w_strip(256 x 64b) @ D11[b-block rows]^T (mma)
// Phase 2: per-row sequential tanh recurrence, base + cross, write wh/wl.
// NOTE 2-stage pipeline: issue(c+1) THEN CP_WAIT(1) — outstanding groups are
// {c, c+1}; chunk c+1 fills buffer (c+1)&1 while we read buffer c&1.
__global__ __launch_bounds__(256) void scan_fused(int b)
{
    extern __shared__ __align__(128) char smem[];
    constexpr int APc  = 256 * 64;            // A plane stage bytes
    constexpr int WPc  = 64 * 64;             // W plane stage bytes
    constexpr int STGc = 2 * APc + 2 * WPc;   // 40960
    constexpr int CRo  = 2 * STGc;            // cross at 81920
    constexpr int DSo  = CRo + 256 * 68 * 4;  // ds at 151552
    uint32_t sb = smem_to_u32(smem);
    float* cross = (float*)(smem + CRo);
    float* ds    = (float*)(smem + DSo);
    int tid = threadIdx.x;
    int wid = tid >> 5, lane = tid & 31;
    int strip0 = blockIdx.x * 256;
    int nk = (64 * b) >> 5;

    auto issue = [&](int c) {
        int kt = c << 5;
        uint32_t stu = sb + (c & 1) * STGc;
        #pragma unroll
        for (int s = tid; s < 2048; s += 256) {
            int pl = s >> 10, rem = s & 1023, row = rem >> 2, q = rem & 3;
            const __nv_bfloat16* src =
                (pl ? g_wl : g_wh) + (size_t)(strip0 + row) * NQc + kt + q * 8;
            cpasync16(stu + pl * APc + swz64(row * 64 + q * 16), src);
        }
        #pragma unroll
        for (int s = tid; s < 512; s += 256) {
            int pl = s >> 8, rem = s & 255, row = rem >> 2, q = rem & 3;
            const __nv_bfloat16* src =
                (pl ? g_D11l : g_D11h) + (size_t)(b * 64 + row) * NQc + kt + q * 8;
            cpasync16(stu + 2 * APc + pl * WPc + swz64(row * 64 + q * 16), src);
        }
        CP_COMMIT();
    };

    float acc[2][8][4] = {};
    if (nk > 0) {
        issue(0);
        for (int c = 0; c < nk; ++c) {
            if (c + 1 < nk) { issue(c + 1); CP_WAIT(1); }
            else            { CP_WAIT(0); }
            __syncthreads();
            uint32_t stu = sb + (c & 1) * STGc;
            int wm = wid * 32;
            #pragma unroll
            for (int ks = 0; ks < 2; ++ks) {
                uint32_t ah[2][4], al[2][4];
                #pragma unroll
                for (int am = 0; am < 2; ++am) {
                    uint32_t off = (uint32_t)(wm + am * 16 + (lane & 15)) * 64
                                   + ks * 32 + (lane >> 4) * 16;
                    ldsm4(ah[am], stu + swz64(off));
                    ldsm4(al[am], stu + APc + swz64(off));
                }
                uint32_t bh[8][2], bl[8][2];
                #pragma unroll
                for (int p = 0; p < 4; ++p) {
                    int g = lane >> 3;
                    uint32_t off = (uint32_t)(p * 16 + ((g >> 1) << 3) + (lane & 7)) * 64
                                   + ks * 32 + (g & 1) * 16;
                    uint32_t t4[4];
                    ldsm4(t4, stu + 2 * APc + swz64(off));
                    bh[2 * p][0] = t4[0]; bh[2 * p][1] = t4[1];
                    bh[2 * p + 1][0] = t4[2]; bh[2 * p + 1][1] = t4[3];
                    ldsm4(t4, stu + 2 * APc + WPc + swz64(off));
                    bl[2 * p][0] = t4[0]; bl[2 * p][1] = t4[1];
                    bl[2 * p + 1][0] = t4[2]; bl[2 * p + 1][1] = t4[3];
                }
                #pragma unroll
                for (int am = 0; am < 2; ++am)
                    #pragma unroll
                    for (int j = 0; j < 8; ++j) {
                        mma16816(acc[am][j], ah[am], bh[j]);
                        mma16816(acc[am][j], ah[am], bl[j]);
                        mma16816(acc[am][j], al[am], bh[j]);
                    }
            }
            __syncthreads();
        }
    }
    // epilogue: acc -> cross (smem)
    {
        int wm = wid * 32;
        #pragma unroll
        for (int am = 0; am < 2; ++am) {
            int r0 = wm + am * 16 + (lane >> 2);
            #pragma unroll
            for (int j = 0; j < 8; ++j) {
                int cc = j * 8 + (lane & 3) * 2;
                cross[r0 * 68 + cc]           = acc[am][j][0];
                cross[r0 * 68 + cc + 1]       = acc[am][j][1];
                cross[(r0 + 8) * 68 + cc]     = acc[am][j][2];
                cross[(r0 + 8) * 68 + cc + 1] = acc[am][j][3];
            }
        }
    }
    for (int idx = tid; idx < 4096; idx += 256) {
        int i = idx >> 6, j = idx & 63;
        ds[i * 65 + j] = g_D11[(size_t)(b * 64 + i) * NQc + b * 64 + j];
    }
    __syncthreads();

    // scan: thread owns one row
    int r = strip0 + tid;
    float bb[64];
    const float4* bp = (const float4*)(g_base + (size_t)r * NQc + b * 64);
    #pragma unroll
    for (int q = 0; q < 16; ++q) {
        float4 v = bp[q];
        bb[q * 4 + 0] = v.x + cross[tid * 68 + q * 4 + 0];
        bb[q * 4 + 1] = v.y + cross[tid * 68 + q * 4 + 1];
        bb[q * 4 + 2] = v.z + cross[tid * 68 + q * 4 + 2];
        bb[q * 4 + 3] = v.w + cross[tid * 68 + q * 4 + 3];
    }
    float wv[64];
    #pragma unroll
    for (int i = 0; i < 64; ++i) {
        float s0 = 0.f, s1 = 0.f, s2 = 0.f, s3 = 0.f;
        #pragma unroll
        for (int j = 0; j < 64; ++j) {
            if (j < i) {
                float p = wv[j] * ds[i * 65 + j];
                if      ((j & 3) == 0) s0 += p;
                else if ((j & 3) == 1) s1 += p;
                else if ((j & 3) == 2) s2 += p;
                else                   s3 += p;
            }
        }
        wv[i] = ftanh(bb[i] + ((s0 + s1) + (s2 + s3)));
    }
    __nv_bfloat162* whp = (__nv_bfloat162*)(g_wh + (size_t)r * NQc + b * 64);
    __nv_bfloat162* wlp = (__nv_bfloat162*)(g_wl + (size_t)r * NQc + b * 64);
    #pragma unroll
    for (int q = 0; q < 32; ++q) {
        float a = wv[q * 2], c = wv[q * 2 + 1];
        __nv_bfloat162 h, l;
        h.x = __float2bfloat16(a); h.y = __float2bfloat16(c);
        l.x = __float2bfloat16(a - __bfloat162float(h.x));
        l.y = __float2bfloat16(c - __bfloat162float(h.y));
        whp[q] = h; wlp[q] = l;
    }
}

// ================= host orchestration =======================================
extern "C" void kernel_launch(void* const* d_in, const int* in_sizes, int n_in,
                              void* d_out, int out_size)
{
    const float* xi    = (const float*)d_in[1];
    const float* u     = (const float*)d_in[2];
    const float* Pstar = (const float*)d_in[3];
    const float* Chi   = (const float*)d_in[4];
    const float* Y1    = (const float*)d_in[5];
    const float* B2    = (const float*)d_in[6];
    const float* D12   = (const float*)d_in[7];
    const float* X     = (const float*)d_in[8];
    float* out = (float*)d_out;

    float *H, *P, *base;
    __nv_bfloat16 *xih, *xil, *uh, *ul, *wh, *wl, *Xh, *Xl, *C1h, *C1l, *D11h, *D11l;
    __nv_bfloat16 *Sh, *Sl, *D12h, *D12l, *B2h, *B2l;
    cudaGetSymbolAddress((void**)&H, g_H);       cudaGetSymbolAddress((void**)&P, g_P);
    cudaGetSymbolAddress((void**)&base, g_base);
    cudaGetSymbolAddress((void**)&xih, g_xih);   cudaGetSymbolAddress((void**)&xil, g_xil);
    cudaGetSymbolAddress((void**)&uh, g_uh);     cudaGetSymbolAddress((void**)&ul, g_ul);
    cudaGetSymbolAddress((void**)&wh, g_wh);     cudaGetSymbolAddress((void**)&wl, g_wl);
    cudaGetSymbolAddress((void**)&Xh, g_Xh);     cudaGetSymbolAddress((void**)&Xl, g_Xl);
    cudaGetSymbolAddress((void**)&C1h, g_C1h);   cudaGetSymbolAddress((void**)&C1l, g_C1l);
    cudaGetSymbolAddress((void**)&D11h, g_D11h); cudaGetSymbolAddress((void**)&D11l, g_D11l);
    cudaGetSymbolAddress((void**)&Sh, g_Sh);     cudaGetSymbolAddress((void**)&Sl, g_Sl);
    cudaGetSymbolAddress((void**)&D12h, g_D12h); cudaGetSymbolAddress((void**)&D12l, g_D12l);
    cudaGetSymbolAddress((void**)&B2h, g_B2h);   cudaGetSymbolAddress((void**)&B2l, g_B2l);

    constexpr int SM128 = 3 * (2 * 128 * 64 + 2 * 128 * 64);     // 98304
    constexpr int SMSF  = 2 * (2 * 256 * 64 + 2 * 64 * 64) + 256 * 68 * 4 + 64 * 65 * 4; // 168192
    cudaFuncSetAttribute(mma_gemm<128>, cudaFuncAttributeMaxDynamicSharedMemorySize, SM128);
    cudaFuncSetAttribute(scan_fused,    cudaFuncAttributeMaxDynamicSharedMemorySize, SMSF);

    Seg zs = { nullptr, nullptr, nullptr, nullptr, 0, 0, 0 };

    // 0-2: split fp32 inputs into bf16 hi/lo planes
    splitk<<<16384, 256>>>(xi, xih, xil, Bc * NXc / 4);
    splitk<<<4096, 256>>>(u, uh, ul, Bc * NUc / 4);
    splitk<<<1024, 256>>>(X, Xh, Xl, 1024 * 1024 / 4);

    // 3: H = X X^T via tensor path (eps handled analytically downstream)
    Seg sXX = { Xh, Xl, Xh, Xl, 1024, 1024, 1024 };
    mma_gemm<128><<<dim3(8, 8), 512, SM128>>>(sXX, zs, zs, H, 1024, 0);

    // 4: prep (RHS, D11(+planes), C1 planes, D12/B2 planes)
    prep_mats2<<<1024, 256>>>(Y1, Chi, D12, B2);

    // 5: base = xi C1^T + u D12^T   (capture slot target)
    Seg sXC1 = { xih, xil, C1h, C1l, NXc, NXc, NXc };
    Seg sUD  = { uh, ul, D12h, D12l, NUc, NUc, NUc };
    mma_gemm<128><<<dim3(4, 256), 512, SM128>>>(sXC1, sUD, zs, base, NQc, 0);

    // 6: P = 0.5 Pstar Pstar^T + eps I (fp32, feeds Cholesky)
    sgemm64<0, 1><<<dim3(8, 8), 256>>>(Pstar, 512, Pstar, 512, P, 512, 512, 0.5f, 0.0f, EPSc);

    // 7-8: fused Cholesky + triangular solves + S split
    reset_bar<<<1, 32>>>();
    solve_all<<<16, 256>>>();

    // 9-16: fused cross-GEMM + scan per 64-col block
    for (int b = 0; b < 8; ++b)
        scan_fused<<<128, 256, SMSF>>>(b);

    // 17: out = xi A^T + w B1^T + u B2^T
    Seg sXA = { xih, xil, Sh, Sl, NXc, 1024, NXc };
    Seg sWB = { wh, wl, Sh + 512, Sl + 512, NQc, 1024, NQc };
    Seg sUB = { uh, ul, B2h, B2l, NUc, NUc, NUc };
    mma_gemm<128><<<dim3(4, 256), 512, SM128>>>(sXA, sWB, sUB, out, NXc, 0);
}

// round 8
// speedup vs baseline: 1.8340x; 1.2276x over previous
#include <cuda_runtime.h>
#include <cuda_bf16.h>
#include <cstdint>
#include <math.h>

#define NXc 512
#define NQc 512
#define NUc 128
#define Bc  32768
#define EPSc 1e-3f

// ================= baseline-ISA helpers (compute_103-safe) ==================
__device__ __forceinline__ uint32_t smem_to_u32(const void* p) {
    uint32_t a;
    asm("{ .reg .u64 t; cvta.to.shared.u64 t, %1; cvt.u32.u64 %0, t; }" : "=r"(a) : "l"(p));
    return a;
}
__device__ __forceinline__ void cpasync16(uint32_t d, const void* s) {
    asm volatile("cp.async.cg.shared.global [%0], [%1], 16;" :: "r"(d), "l"(s));
}
#define CP_COMMIT() asm volatile("cp.async.commit_group;" ::: "memory")
#define CP_WAIT(N)  asm volatile("cp.async.wait_group %0;" :: "n"(N) : "memory")

__device__ __forceinline__ void ldsm4(uint32_t* r, uint32_t addr) {
    asm volatile("ldmatrix.sync.aligned.m8n8.x4.shared.b16 {%0,%1,%2,%3}, [%4];"
        : "=r"(r[0]), "=r"(r[1]), "=r"(r[2]), "=r"(r[3]) : "r"(addr));
}
__device__ __forceinline__ void mma16816(float* d, const uint32_t* a, const uint32_t* b) {
    asm volatile("mma.sync.aligned.m16n8k16.row.col.f32.bf16.bf16.f32 "
        "{%0,%1,%2,%3}, {%4,%5,%6,%7}, {%8,%9}, {%0,%1,%2,%3};"
        : "+f"(d[0]), "+f"(d[1]), "+f"(d[2]), "+f"(d[3])
        : "r"(a[0]), "r"(a[1]), "r"(a[2]), "r"(a[3]), "r"(b[0]), "r"(b[1]));
}
__device__ __forceinline__ uint32_t swz64(uint32_t off) { return off ^ ((off >> 3) & 0x30); }

// ================= scratch (device globals) =================================
__device__ float g_H[1024 * 1024];
__device__ float g_P[NXc * NXc];
__device__ float g_Linv[8 * 64 * 64];
__device__ float g_D11[NQc * NQc];
__device__ float g_RHS[NXc * 1024];
__device__ float g_Z[NXc * 1024];
__device__ float g_S[NXc * 1024];
__device__ float g_base[(size_t)Bc * NQc];
__device__ unsigned g_barCnt;
__device__ __nv_bfloat16 g_xih[(size_t)Bc * NXc], g_xil[(size_t)Bc * NXc];
__device__ __nv_bfloat16 g_uh[(size_t)Bc * NUc],  g_ul[(size_t)Bc * NUc];
__device__ __nv_bfloat16 g_wh[(size_t)Bc * NQc],  g_wl[(size_t)Bc * NQc];
__device__ __nv_bfloat16 g_Xh[1024 * 1024], g_Xl[1024 * 1024];
__device__ __nv_bfloat16 g_C1h[NQc * NXc],  g_C1l[NQc * NXc];
__device__ __nv_bfloat16 g_D11h[NQc * NQc], g_D11l[NQc * NQc];
__device__ __nv_bfloat16 g_Sh[NXc * 1024],  g_Sl[NXc * 1024];
__device__ __nv_bfloat16 g_D12h[NQc * NUc], g_D12l[NQc * NUc];
__device__ __nv_bfloat16 g_B2h[NXc * NUc],  g_B2l[NXc * NUc];

// ================= misc small kernels =======================================
__device__ __forceinline__ float ftanh(float x) {
    float a = fabsf(x);
    float t = __expf(-2.0f * a);
    float r = __fdividef(1.0f - t, 1.0f + t);
    return copysignf(r, x);
}

__global__ void splitk(const float* __restrict__ in, __nv_bfloat16* __restrict__ hi,
                       __nv_bfloat16* __restrict__ lo, int n4) {
    int i = blockIdx.x * 256 + threadIdx.x;
    if (i >= n4) return;
    float4 v = ((const float4*)in)[i];
    __nv_bfloat162 h0, h1, l0, l1;
    h0.x = __float2bfloat16(v.x); h0.y = __float2bfloat16(v.y);
    h1.x = __float2bfloat16(v.z); h1.y = __float2bfloat16(v.w);
    l0.x = __float2bfloat16(v.x - __bfloat162float(h0.x));
    l0.y = __float2bfloat16(v.y - __bfloat162float(h0.y));
    l1.x = __float2bfloat16(v.z - __bfloat162float(h1.x));
    l1.y = __float2bfloat16(v.w - __bfloat162float(h1.y));
    ((__nv_bfloat162*)hi)[i * 2] = h0; ((__nv_bfloat162*)hi)[i * 2 + 1] = h1;
    ((__nv_bfloat162*)lo)[i * 2] = l0; ((__nv_bfloat162*)lo)[i * 2 + 1] = l1;
}

__global__ void prep_mats2(const float* __restrict__ Y1, const float* __restrict__ Chi,
                           const float* __restrict__ D12, const float* __restrict__ B2) {
    int idx = blockIdx.x * 256 + threadIdx.x;
    int i = idx >> 9, j = idx & 511;
    float h1 = g_H[(size_t)i * 1024 + j];
    g_RHS[(size_t)i * 1024 + j] =
        -0.5f * (h1 + ((i == j) ? EPSc : 0.0f) + Y1[(size_t)i * 512 + j] - Y1[(size_t)j * 512 + i]);
    g_RHS[(size_t)i * 1024 + 512 + j] =
        -g_H[(size_t)i * 1024 + 512 + j] - Chi[(size_t)i * 512 + j];
    float rl = 2.0f / (g_H[(size_t)(NXc + i) * 1024 + NXc + i] + EPSc);
    float d = (j < i) ? -g_H[(size_t)(512 + i) * 1024 + 512 + j] * rl : 0.0f;
    g_D11[(size_t)i * 512 + j] = d;
    __nv_bfloat16 dh = __float2bfloat16(d);
    g_D11h[(size_t)i * 512 + j] = dh;
    g_D11l[(size_t)i * 512 + j] = __float2bfloat16(d - __bfloat162float(dh));
    float c1 = Chi[(size_t)j * 512 + i] * rl;
    __nv_bfloat16 ch = __float2bfloat16(c1);
    g_C1h[(size_t)i * 512 + j] = ch;
    g_C1l[(size_t)i * 512 + j] = __float2bfloat16(c1 - __bfloat162float(ch));
    if (j < NUc) {
        float v = D12[(size_t)i * NUc + j];
        __nv_bfloat16 vh = __float2bfloat16(v);
        g_D12h[(size_t)i * NUc + j] = vh;
        g_D12l[(size_t)i * NUc + j] = __float2bfloat16(v - __bfloat162float(vh));
        float w = B2[(size_t)i * NUc + j];
        __nv_bfloat16 wh = __float2bfloat16(w);
        g_B2h[(size_t)i * NUc + j] = wh;
        g_B2l[(size_t)i * NUc + j] = __float2bfloat16(w - __bfloat162float(wh));
    }
}

__global__ void reset_bar() { if (threadIdx.x == 0) g_barCnt = 0u; }

// ================= fp32 SIMT GEMM (P = 0.5 Pstar Pstar^T + eps I) ===========
template <int TA, int TB>
__global__ __launch_bounds__(256) void sgemm64(
    const float* __restrict__ A, int lda,
    const float* __restrict__ B, int ldb,
    float* __restrict__ C, int ldc,
    int K, float alpha, float beta, float diagAdd)
{
    __shared__ float As[16][68];
    __shared__ float Bs[16][68];
    int tid = threadIdx.x;
    int m0 = blockIdx.y * 64, n0 = blockIdx.x * 64;
    int tx = tid & 15, ty = tid >> 4;
    float acc[4][4] = {};
    for (int kt = 0; kt < K; kt += 16) {
        __syncthreads();
        if (TA == 0) {
            int r = tid >> 2, kq = (tid & 3) * 4;
            float4 v = *(const float4*)(A + (size_t)(m0 + r) * lda + kt + kq);
            As[kq + 0][r] = v.x; As[kq + 1][r] = v.y; As[kq + 2][r] = v.z; As[kq + 3][r] = v.w;
        } else {
            int m4 = (tid & 15) * 4, k = tid >> 4;
            float4 v = *(const float4*)(A + (size_t)(kt + k) * lda + m0 + m4);
            As[k][m4 + 0] = v.x; As[k][m4 + 1] = v.y; As[k][m4 + 2] = v.z; As[k][m4 + 3] = v.w;
        }
        if (TB == 0) {
            int n4 = (tid & 15) * 4, k = tid >> 4;
            float4 v = *(const float4*)(B + (size_t)(kt + k) * ldb + n0 + n4);
            Bs[k][n4 + 0] = v.x; Bs[k][n4 + 1] = v.y; Bs[k][n4 + 2] = v.z; Bs[k][n4 + 3] = v.w;
        } else {
            int r = tid >> 2, kq = (tid & 3) * 4;
            float4 v = *(const float4*)(B + (size_t)(n0 + r) * ldb + kt + kq);
            Bs[kq + 0][r] = v.x; Bs[kq + 1][r] = v.y; Bs[kq + 2][r] = v.z; Bs[kq + 3][r] = v.w;
        }
        __syncthreads();
        #pragma unroll
        for (int kk = 0; kk < 16; ++kk) {
            float4 a = *(const float4*)&As[kk][ty * 4];
            float4 b = *(const float4*)&Bs[kk][tx * 4];
            float am[4] = {a.x, a.y, a.z, a.w};
            float bm[4] = {b.x, b.y, b.z, b.w};
            #pragma unroll
            for (int i = 0; i < 4; ++i)
                #pragma unroll
                for (int j = 0; j < 4; ++j)
                    acc[i][j] += am[i] * bm[j];
        }
    }
    #pragma unroll
    for (int i = 0; i < 4; ++i) {
        int gr = m0 + ty * 4 + i;
        #pragma unroll
        for (int j = 0; j < 4; ++j) {
            int gc = n0 + tx * 4 + j;
            float v = alpha * acc[i][j];
            if (beta != 0.0f) v += beta * C[(size_t)gr * ldc + gc];
            if (gr == gc) v += diagAdd;
            C[(size_t)gr * ldc + gc] = v;
        }
    }
}

// ================= solver device pieces (fp32, 256 threads) =================
__device__ __forceinline__ void gbar(unsigned& gen) {
    __syncthreads();
    gen += 16;
    if (threadIdx.x == 0) {
        __threadfence();
        atomicAdd(&g_barCnt, 1u);
        while (*(volatile unsigned*)&g_barCnt < gen) { }
        __threadfence();
    }
    __syncthreads();
}

__device__ void dev_potf2_inv(int k, float (*S)[65], float* Dinv, float* sdp)
{
    int tid = threadIdx.x;
    for (int idx = tid; idx < 4096; idx += 256) {
        int i = idx >> 6, j = idx & 63;
        S[i][j] = g_P[(size_t)(k * 64 + i) * NXc + k * 64 + j];
    }
    __syncthreads();
    for (int j = 0; j < 64; ++j) {
        if (tid == 0) *sdp = rsqrtf(S[j][j]);
        __syncthreads();
        if (tid >= j && tid < 64) S[tid][j] *= *sdp;
        __syncthreads();
        for (int idx = tid; idx < 4096; idx += 256) {
            int i = idx >> 6, c = idx & 63;
            if (i > j && c > j) S[i][c] -= S[i][j] * S[c][j];
        }
        __syncthreads();
    }
    if (tid < 64) Dinv[tid] = 1.0f / S[tid][tid];
    __syncthreads();
    int wd = tid >> 5, lane = tid & 31;
    for (int cc = 0; cc < 8; ++cc) {
        int c = wd * 8 + cc;
        float x0 = (lane == c) ? 1.0f : 0.0f;
        float x1 = (lane + 32 == c) ? 1.0f : 0.0f;
        for (int i = c; i < 64; ++i) {
            float src = (i < 32) ? x0 : x1;
            float part = __shfl_sync(0xffffffffu, src, i & 31);
            float xv = part * Dinv[i];
            if (i < 32) { if (lane == i) x0 = xv; }
            else        { if (lane == i - 32) x1 = xv; }
            if (lane > i)      x0 -= S[lane][i] * xv;
            if (lane + 32 > i) x1 -= S[lane + 32][i] * xv;
        }
        g_Linv[k * 4096 + lane * 64 + c] = x0;
        g_Linv[k * 4096 + (lane + 32) * 64 + c] = x1;
    }
}

__device__ void dev_gemm_ABt64(const float* A, int lda, const float* B, int ldb,
                               float* C, int ldc, float alpha, float beta,
                               float (*As)[68], float (*Bs)[68])
{
    int tid = threadIdx.x;
    int tx = tid & 15, ty = tid >> 4;
    float acc[4][4] = {};
    for (int kt = 0; kt < 64; kt += 16) {
        __syncthreads();
        {
            int r = tid >> 2, kq = (tid & 3) * 4;
            float4 v = *(const float4*)(A + (size_t)r * lda + kt + kq);
            As[kq + 0][r] = v.x; As[kq + 1][r] = v.y; As[kq + 2][r] = v.z; As[kq + 3][r] = v.w;
            float4 w = *(const float4*)(B + (size_t)r * ldb + kt + kq);
            Bs[kq + 0][r] = w.x; Bs[kq + 1][r] = w.y; Bs[kq + 2][r] = w.z; Bs[kq + 3][r] = w.w;
        }
        __syncthreads();
        #pragma unroll
        for (int kk = 0; kk < 16; ++kk) {
            float4 a = *(const float4*)&As[kk][ty * 4];
            float4 b = *(const float4*)&Bs[kk][tx * 4];
            float am[4] = {a.x, a.y, a.z, a.w};
            float bm[4] = {b.x, b.y, b.z, b.w};
            #pragma unroll
            for (int i = 0; i < 4; ++i)
                #pragma unroll
                for (int j = 0; j < 4; ++j)
                    acc[i][j] += am[i] * bm[j];
        }
    }
    __syncthreads();
    #pragma unroll
    for (int i = 0; i < 4; ++i)
        #pragma unroll
        for (int j = 0; j < 4; ++j) {
            float v = alpha * acc[i][j];
            if (beta != 0.0f) v += beta * C[(size_t)(ty * 4 + i) * ldc + tx * 4 + j];
            C[(size_t)(ty * 4 + i) * ldc + tx * 4 + j] = v;
        }
}

__device__ void dev_fwd(int c0, float (*Lt)[65], float (*Zt)[65])
{
    int tid = threadIdx.x;
    int tx = tid & 15, ty = tid >> 4;
    for (int ib = 0; ib < 8; ++ib) {
        float acc[4][4] = {};
        for (int jb = 0; jb < ib; ++jb) {
            for (int idx = tid; idx < 4096; idx += 256) {
                int i = idx >> 6, j = idx & 63;
                Lt[i][j] = g_P[(size_t)(ib * 64 + i) * 512 + jb * 64 + j];
                Zt[i][j] = g_Z[(size_t)(jb * 64 + i) * 1024 + c0 + j];
            }
            __syncthreads();
            #pragma unroll 8
            for (int kk = 0; kk < 64; ++kk)
                #pragma unroll
                for (int ii = 0; ii < 4; ++ii)
                    #pragma unroll
                    for (int jj = 0; jj < 4; ++jj)
                        acc[ii][jj] += Lt[ty * 4 + ii][kk] * Zt[kk][tx * 4 + jj];
            __syncthreads();
        }
        #pragma unroll
        for (int ii = 0; ii < 4; ++ii)
            #pragma unroll
            for (int jj = 0; jj < 4; ++jj)
                Zt[ty * 4 + ii][tx * 4 + jj] =
                    g_RHS[(size_t)(ib * 64 + ty * 4 + ii) * 1024 + c0 + tx * 4 + jj] - acc[ii][jj];
        for (int idx = tid; idx < 4096; idx += 256) {
            int i = idx >> 6, j = idx & 63;
            Lt[i][j] = g_Linv[ib * 4096 + i * 64 + j];
        }
        __syncthreads();
        float z[4][4] = {};
        #pragma unroll 8
        for (int kk = 0; kk < 64; ++kk)
            #pragma unroll
            for (int ii = 0; ii < 4; ++ii)
                #pragma unroll
                for (int jj = 0; jj < 4; ++jj)
                    z[ii][jj] += Lt[ty * 4 + ii][kk] * Zt[kk][tx * 4 + jj];
        #pragma unroll
        for (int ii = 0; ii < 4; ++ii)
            #pragma unroll
            for (int jj = 0; jj < 4; ++jj)
                g_Z[(size_t)(ib * 64 + ty * 4 + ii) * 1024 + c0 + tx * 4 + jj] = z[ii][jj];
        __syncthreads();
    }
}

__device__ void dev_bwd(int c0, float (*Lt)[65], float (*Zt)[65])
{
    int tid = threadIdx.x;
    int tx = tid & 15, ty = tid >> 4;
    for (int ib = 7; ib >= 0; --ib) {
        float acc[4][4] = {};
        for (int jb = ib + 1; jb < 8; ++jb) {
            for (int idx = tid; idx < 4096; idx += 256) {
                int i = idx >> 6, j = idx & 63;
                Lt[i][j] = g_P[(size_t)(jb * 64 + i) * 512 + ib * 64 + j];
                Zt[i][j] = g_S[(size_t)(jb * 64 + i) * 1024 + c0 + j];
            }
            __syncthreads();
            #pragma unroll 8
            for (int kk = 0; kk < 64; ++kk)
                #pragma unroll
                for (int ii = 0; ii < 4; ++ii)
                    #pragma unroll
                    for (int jj = 0; jj < 4; ++jj)
                        acc[ii][jj] += Lt[kk][ty * 4 + ii] * Zt[kk][tx * 4 + jj];
            __syncthreads();
        }
        #pragma unroll
        for (int ii = 0; ii < 4; ++ii)
            #pragma unroll
            for (int jj = 0; jj < 4; ++jj)
                Zt[ty * 4 + ii][tx * 4 + jj] =
                    g_Z[(size_t)(ib * 64 + ty * 4 + ii) * 1024 + c0 + tx * 4 + jj] - acc[ii][jj];
        for (int idx = tid; idx < 4096; idx += 256) {
            int i = idx >> 6, j = idx & 63;
            Lt[i][j] = g_Linv[ib * 4096 + i * 64 + j];
        }
        __syncthreads();
        float z[4][4] = {};
        #pragma unroll 8
        for (int kk = 0; kk < 64; ++kk)
            #pragma unroll
            for (int ii = 0; ii < 4; ++ii)
                #pragma unroll
                for (int jj = 0; jj < 4; ++jj)
                    z[ii][jj] += Lt[kk][ty * 4 + ii] * Zt[kk][tx * 4 + jj];
        #pragma unroll
        for (int ii = 0; ii < 4; ++ii)
            #pragma unroll
            for (int jj = 0; jj < 4; ++jj)
                g_S[(size_t)(ib * 64 + ty * 4 + ii) * 1024 + c0 + tx * 4 + jj] = z[ii][jj];
        __syncthreads();
    }
}

// ================= mma.sync split-bf16 batch GEMM ===========================
struct Seg {
    const __nv_bfloat16 *Ah, *Al, *Wh, *Wl;
    int lda, ldw, K;
};

template <int NT>
__global__ __launch_bounds__(512) void mma_gemm(
    Seg s0, Seg s1, Seg s2, float* __restrict__ C, int ldc, int addTo)
{
    extern __shared__ __align__(128) char smem[];
    constexpr int AP  = 128 * 64;
    constexpr int WP  = NT * 64;
    constexpr int STG = 2 * AP + 2 * WP;
    constexpr int NAw = NT / 32;

    uint32_t sb = smem_to_u32(smem);
    int tid = threadIdx.x;
    int wid = tid >> 5, lane = tid & 31;
    int m0 = blockIdx.y * 128, n0 = blockIdx.x * NT;
    int wm = (wid & 3) * 32;
    int wn = (wid >> 2) * (NT / 4);

    int nk0 = s0.K >> 5, nk1 = s1.K >> 5, nk2 = s2.K >> 5;
    int nk = nk0 + nk1 + nk2;

    auto issue = [&](int c) {
        int cs = c;
        const Seg* sg = &s0;
        if (cs >= nk0) { cs -= nk0; sg = &s1; if (cs >= nk1) { cs -= nk1; sg = &s2; } }
        int kt = cs << 5;
        uint32_t stu = sb + (c % 3) * STG;
        #pragma unroll
        for (int s = tid; s < 1024; s += 512) {
            int pl = s >> 9, rem = s & 511, row = rem >> 2, q = rem & 3;
            const __nv_bfloat16* src =
                (pl ? sg->Al : sg->Ah) + (size_t)(m0 + row) * sg->lda + kt + q * 8;
            cpasync16(stu + pl * AP + swz64(row * 64 + q * 16), src);
        }
        #pragma unroll
        for (int s = tid; s < NT * 8; s += 512) {
            int pl = (s >= NT * 4) ? 1 : 0;
            int rem = pl ? s - NT * 4 : s;
            int row = rem >> 2, q = rem & 3;
            const __nv_bfloat16* src =
                (pl ? sg->Wl : sg->Wh) + (size_t)(n0 + row) * sg->ldw + kt + q * 8;
            cpasync16(stu + 2 * AP + pl * WP + swz64(row * 64 + q * 16), src);
        }
        CP_COMMIT();
    };

    float acc[2][NAw][4] = {};

    issue(0); issue(1);
    for (int c = 0; c < nk; ++c) {
        if (c + 1 < nk) { CP_WAIT(1); } else { CP_WAIT(0); }
        __syncthreads();
        if (c + 2 < nk) issue(c + 2);
        uint32_t stu = sb + (c % 3) * STG;
        #pragma unroll
        for (int ks = 0; ks < 2; ++ks) {
            uint32_t ah[2][4], al[2][4];
            #pragma unroll
            for (int am = 0; am < 2; ++am) {
                uint32_t off = (uint32_t)(wm + am * 16 + (lane & 15)) * 64
                               + ks * 32 + (lane >> 4) * 16;
                ldsm4(ah[am], stu + swz64(off));
                ldsm4(al[am], stu + AP + swz64(off));
            }
            uint32_t bh[NAw][2], bl[NAw][2];
            #pragma unroll
            for (int p = 0; p < NAw / 2; ++p) {
                int g = lane >> 3;
                uint32_t off = (uint32_t)(wn + p * 16 + ((g >> 1) << 3) + (lane & 7)) * 64
                               + ks * 32 + (g & 1) * 16;
                uint32_t t4[4];
                ldsm4(t4, stu + 2 * AP + swz64(off));
                bh[2 * p][0] = t4[0]; bh[2 * p][1] = t4[1];
                bh[2 * p + 1][0] = t4[2]; bh[2 * p + 1][1] = t4[3];
                ldsm4(t4, stu + 2 * AP + WP + swz64(off));
                bl[2 * p][0] = t4[0]; bl[2 * p][1] = t4[1];
                bl[2 * p + 1][0] = t4[2]; bl[2 * p + 1][1] = t4[3];
            }
            #pragma unroll
            for (int am = 0; am < 2; ++am)
                #pragma unroll
                for (int j = 0; j < NAw; ++j) {
                    mma16816(acc[am][j], ah[am], bh[j]);
                    mma16816(acc[am][j], ah[am], bl[j]);
                    mma16816(acc[am][j], al[am], bh[j]);
                }
        }
        __syncthreads();
    }

    #pragma unroll
    for (int am = 0; am < 2; ++am) {
        int r0 = m0 + wm + am * 16 + (lane >> 2);
        #pragma unroll
        for (int j = 0; j < NAw; ++j) {
            int cc = n0 + wn + j * 8 + (lane & 3) * 2;
            float* p0 = C + (size_t)r0 * ldc + cc;
            float* p1 = C + (size_t)(r0 + 8) * ldc + cc;
            float2 v0 = make_float2(acc[am][j][0], acc[am][j][1]);
            float2 v1 = make_float2(acc[am][j][2], acc[am][j][3]);
            if (addTo) {
                float2 o0 = *(const float2*)p0, o1 = *(const float2*)p1;
                v0.x += o0.x; v0.y += o0.y; v1.x += o1.x; v1.y += o1.y;
            }
            *(float2*)p0 = v0;
            *(float2*)p1 = v1;
        }
    }
}

// ================= fused scan (all 8 blocks) + solver, one launch ===========
// grid = 144 CTAs x 256 threads.
//   CTAs 0-15:  blocked Cholesky + fwd/bwd solves + S split (gbar among 16).
//   CTAs 16-143: per-strip scan; strip = 256 rows; all 8 column blocks looped
//                internally. Cross-GEMM reads only the CTA's OWN strip of w
//                (written in earlier b iterations) -> no cross-CTA sync.
__global__ __launch_bounds__(256) void scan_solve()
{
    extern __shared__ __align__(128) char smem[];
    int tid = threadIdx.x;

    if (blockIdx.x < 16) {
        // ---------------- solver path ----------------
        float (*shA)[68] = (float(*)[68])(smem);
        float (*shB)[68] = (float(*)[68])(smem + 16 * 68 * 4);
        float (*S64)[65] = (float(*)[65])(smem + 2 * 16 * 68 * 4);
        float (*T64)[65] = (float(*)[65])(smem + 2 * 16 * 68 * 4 + 64 * 65 * 4);
        float* Dinv      = (float*)(smem + 2 * 16 * 68 * 4 + 2 * 64 * 65 * 4);
        float* sdv       = Dinv + 64;
        int cta = blockIdx.x;
        unsigned gen = 0;

        for (int k = 0; k < 8; ++k) {
            if (cta == 0) dev_potf2_inv(k, S64, Dinv, sdv);
            gbar(gen);
            int nrem = 7 - k;
            if (nrem > 0) {
                if (cta < nrem) {
                    int i = k + 1 + cta;
                    float* panel = g_P + (size_t)i * 64 * 512 + k * 64;
                    dev_gemm_ABt64(panel, 512, g_Linv + k * 4096, 64,
                                   panel, 512, 1.0f, 0.0f, shA, shB);
                }
                gbar(gen);
                int t = 0;
                for (int i = k + 1; i < 8; ++i)
                    for (int j = k + 1; j <= i; ++j, ++t)
                        if ((t & 15) == cta)
                            dev_gemm_ABt64(g_P + (size_t)i * 64 * 512 + k * 64, 512,
                                           g_P + (size_t)j * 64 * 512 + k * 64, 512,
                                           g_P + (size_t)i * 64 * 512 + j * 64, 512,
                                           -1.0f, 1.0f, shA, shB);
                gbar(gen);
            }
        }
        dev_fwd(cta * 64, S64, T64);
        dev_bwd(cta * 64, S64, T64);
        gbar(gen);
        for (int i = cta * 256 + tid; i < NXc * 1024 / 4; i += 4096) {
            float4 v = ((const float4*)g_S)[i];
            __nv_bfloat162 h0, h1, l0, l1;
            h0.x = __float2bfloat16(v.x); h0.y = __float2bfloat16(v.y);
            h1.x = __float2bfloat16(v.z); h1.y = __float2bfloat16(v.w);
            l0.x = __float2bfloat16(v.x - __bfloat162float(h0.x));
            l0.y = __float2bfloat16(v.y - __bfloat162float(h0.y));
            l1.x = __float2bfloat16(v.z - __bfloat162float(h1.x));
            l1.y = __float2bfloat16(v.w - __bfloat162float(h1.y));
            ((__nv_bfloat162*)g_Sh)[i * 2] = h0; ((__nv_bfloat162*)g_Sh)[i * 2 + 1] = h1;
            ((__nv_bfloat162*)g_Sl)[i * 2] = l0; ((__nv_bfloat162*)g_Sl)[i * 2 + 1] = l1;
        }
        return;
    }

    // ---------------- scan path ----------------
    constexpr int APc  = 256 * 64;
    constexpr int WPc  = 64 * 64;
    constexpr int STGc = 2 * APc + 2 * WPc;   // 40960
    constexpr int CRo  = 2 * STGc;            // cross
    constexpr int DSo  = CRo + 256 * 68 * 4;  // ds
    uint32_t sb = smem_to_u32(smem);
    float* cross = (float*)(smem + CRo);
    float* ds    = (float*)(smem + DSo);
    int wid = tid >> 5, lane = tid & 31;
    int strip0 = (blockIdx.x - 16) * 256;

    for (int b = 0; b < 8; ++b) {
        int nk = (64 * b) >> 5;

        auto issue = [&](int c) {
            int kt = c << 5;
            uint32_t stu = sb + (c & 1) * STGc;
            #pragma unroll
            for (int s = tid; s < 2048; s += 256) {
                int pl = s >> 10, rem = s & 1023, row = rem >> 2, q = rem & 3;
                const __nv_bfloat16* src =
                    (pl ? g_wl : g_wh) + (size_t)(strip0 + row) * NQc + kt + q * 8;
                cpasync16(stu + pl * APc + swz64(row * 64 + q * 16), src);
            }
            #pragma unroll
            for (int s = tid; s < 512; s += 256) {
                int pl = s >> 8, rem = s & 255, row = rem >> 2, q = rem & 3;
                const __nv_bfloat16* src =
                    (pl ? g_D11l : g_D11h) + (size_t)(b * 64 + row) * NQc + kt + q * 8;
                cpasync16(stu + 2 * APc + pl * WPc + swz64(row * 64 + q * 16), src);
            }
            CP_COMMIT();
        };

        float acc[2][8][4] = {};
        if (nk > 0) {
            issue(0);
            for (int c = 0; c < nk; ++c) {
                if (c + 1 < nk) { issue(c + 1); CP_WAIT(1); }
                else            { CP_WAIT(0); }
                __syncthreads();
                uint32_t stu = sb + (c & 1) * STGc;
                int wm = wid * 32;
                #pragma unroll
                for (int ks = 0; ks < 2; ++ks) {
                    uint32_t ah[2][4], al[2][4];
                    #pragma unroll
                    for (int am = 0; am < 2; ++am) {
                        uint32_t off = (uint32_t)(wm + am * 16 + (lane & 15)) * 64
                                       + ks * 32 + (lane >> 4) * 16;
                        ldsm4(ah[am], stu + swz64(off));
                        ldsm4(al[am], stu + APc + swz64(off));
                    }
                    uint32_t bh[8][2], bl[8][2];
                    #pragma unroll
                    for (int p = 0; p < 4; ++p) {
                        int g = lane >> 3;
                        uint32_t off = (uint32_t)(p * 16 + ((g >> 1) << 3) + (lane & 7)) * 64
                                       + ks * 32 + (g & 1) * 16;
                        uint32_t t4[4];
                        ldsm4(t4, stu + 2 * APc + swz64(off));
                        bh[2 * p][0] = t4[0]; bh[2 * p][1] = t4[1];
                        bh[2 * p + 1][0] = t4[2]; bh[2 * p + 1][1] = t4[3];
                        ldsm4(t4, stu + 2 * APc + WPc + swz64(off));
                        bl[2 * p][0] = t4[0]; bl[2 * p][1] = t4[1];
                        bl[2 * p + 1][0] = t4[2]; bl[2 * p + 1][1] = t4[3];
                    }
                    #pragma unroll
                    for (int am = 0; am < 2; ++am)
                        #pragma unroll
                        for (int j = 0; j < 8; ++j) {
                            mma16816(acc[am][j], ah[am], bh[j]);
                            mma16816(acc[am][j], ah[am], bl[j]);
                            mma16816(acc[am][j], al[am], bh[j]);
                        }
                }
                __syncthreads();
            }
        }
        // epilogue: acc -> cross (smem)
        {
            int wm = wid * 32;
            #pragma unroll
            for (int am = 0; am < 2; ++am) {
                int r0 = wm + am * 16 + (lane >> 2);
                #pragma unroll
                for (int j = 0; j < 8; ++j) {
                    int cc = j * 8 + (lane & 3) * 2;
                    cross[r0 * 68 + cc]           = acc[am][j][0];
                    cross[r0 * 68 + cc + 1]       = acc[am][j][1];
                    cross[(r0 + 8) * 68 + cc]     = acc[am][j][2];
                    cross[(r0 + 8) * 68 + cc + 1] = acc[am][j][3];
                }
            }
        }
        for (int idx = tid; idx < 4096; idx += 256) {
            int i = idx >> 6, j = idx & 63;
            ds[i * 65 + j] = g_D11[(size_t)(b * 64 + i) * NQc + b * 64 + j];
        }
        __syncthreads();

        // sequential tanh recurrence; thread owns one row
        int r = strip0 + tid;
        float bb[64];
        const float4* bp = (const float4*)(g_base + (size_t)r * NQc + b * 64);
        #pragma unroll
        for (int q = 0; q < 16; ++q) {
            float4 v = bp[q];
            bb[q * 4 + 0] = v.x + cross[tid * 68 + q * 4 + 0];
            bb[q * 4 + 1] = v.y + cross[tid * 68 + q * 4 + 1];
            bb[q * 4 + 2] = v.z + cross[tid * 68 + q * 4 + 2];
            bb[q * 4 + 3] = v.w + cross[tid * 68 + q * 4 + 3];
        }
        float wv[64];
        #pragma unroll
        for (int i = 0; i < 64; ++i) {
            float s0 = 0.f, s1 = 0.f, s2 = 0.f, s3 = 0.f;
            #pragma unroll
            for (int j = 0; j < 64; ++j) {
                if (j < i) {
                    float p = wv[j] * ds[i * 65 + j];
                    if      ((j & 3) == 0) s0 += p;
                    else if ((j & 3) == 1) s1 += p;
                    else if ((j & 3) == 2) s2 += p;
                    else                   s3 += p;
                }
            }
            wv[i] = ftanh(bb[i] + ((s0 + s1) + (s2 + s3)));
        }
        __nv_bfloat162* whp = (__nv_bfloat162*)(g_wh + (size_t)r * NQc + b * 64);
        __nv_bfloat162* wlp = (__nv_bfloat162*)(g_wl + (size_t)r * NQc + b * 64);
        #pragma unroll
        for (int q = 0; q < 32; ++q) {
            float a = wv[q * 2], c = wv[q * 2 + 1];
            __nv_bfloat162 h, l;
            h.x = __float2bfloat16(a); h.y = __float2bfloat16(c);
            l.x = __float2bfloat16(a - __bfloat162float(h.x));
            l.y = __float2bfloat16(c - __bfloat162float(h.y));
            whp[q] = h; wlp[q] = l;
        }
        // make this block's w (global) visible to next iteration's cp.async
        __syncthreads();
    }
}

// ================= host orchestration =======================================
extern "C" void kernel_launch(void* const* d_in, const int* in_sizes, int n_in,
                              void* d_out, int out_size)
{
    const float* xi    = (const float*)d_in[1];
    const float* u     = (const float*)d_in[2];
    const float* Pstar = (const float*)d_in[3];
    const float* Chi   = (const float*)d_in[4];
    const float* Y1    = (const float*)d_in[5];
    const float* B2    = (const float*)d_in[6];
    const float* D12   = (const float*)d_in[7];
    const float* X     = (const float*)d_in[8];
    float* out = (float*)d_out;

    float *H, *P, *base;
    __nv_bfloat16 *xih, *xil, *uh, *ul, *wh, *wl, *Xh, *Xl, *C1h, *C1l, *D11h, *D11l;
    __nv_bfloat16 *Sh, *Sl, *D12h, *D12l, *B2h, *B2l;
    cudaGetSymbolAddress((void**)&H, g_H);       cudaGetSymbolAddress((void**)&P, g_P);
    cudaGetSymbolAddress((void**)&base, g_base);
    cudaGetSymbolAddress((void**)&xih, g_xih);   cudaGetSymbolAddress((void**)&xil, g_xil);
    cudaGetSymbolAddress((void**)&uh, g_uh);     cudaGetSymbolAddress((void**)&ul, g_ul);
    cudaGetSymbolAddress((void**)&wh, g_wh);     cudaGetSymbolAddress((void**)&wl, g_wl);
    cudaGetSymbolAddress((void**)&Xh, g_Xh);     cudaGetSymbolAddress((void**)&Xl, g_Xl);
    cudaGetSymbolAddress((void**)&C1h, g_C1h);   cudaGetSymbolAddress((void**)&C1l, g_C1l);
    cudaGetSymbolAddress((void**)&D11h, g_D11h); cudaGetSymbolAddress((void**)&D11l, g_D11l);
    cudaGetSymbolAddress((void**)&Sh, g_Sh);     cudaGetSymbolAddress((void**)&Sl, g_Sl);
    cudaGetSymbolAddress((void**)&D12h, g_D12h); cudaGetSymbolAddress((void**)&D12l, g_D12l);
    cudaGetSymbolAddress((void**)&B2h, g_B2h);   cudaGetSymbolAddress((void**)&B2l, g_B2l);

    constexpr int SM128 = 3 * (2 * 128 * 64 + 2 * 128 * 64);     // 98304
    constexpr int SM64  = 3 * (2 * 128 * 64 + 2 * 64 * 64);      // 73728
    constexpr int SMSF  = 2 * (2 * 256 * 64 + 2 * 64 * 64) + 256 * 68 * 4 + 64 * 65 * 4; // 168192
    cudaFuncSetAttribute(mma_gemm<128>, cudaFuncAttributeMaxDynamicSharedMemorySize, SM128);
    cudaFuncSetAttribute(mma_gemm<64>,  cudaFuncAttributeMaxDynamicSharedMemorySize, SM64);
    cudaFuncSetAttribute(scan_solve,    cudaFuncAttributeMaxDynamicSharedMemorySize, SMSF);

    Seg zs = { nullptr, nullptr, nullptr, nullptr, 0, 0, 0 };

    // splits
    splitk<<<16384, 256>>>(xi, xih, xil, Bc * NXc / 4);
    splitk<<<4096, 256>>>(u, uh, ul, Bc * NUc / 4);
    splitk<<<1024, 256>>>(X, Xh, Xl, 1024 * 1024 / 4);

    // H = X X^T via tensor path (NT=64 tiles -> 128 CTAs, better SM coverage)
    Seg sXX = { Xh, Xl, Xh, Xl, 1024, 1024, 1024 };
    mma_gemm<64><<<dim3(16, 8), 512, SM64>>>(sXX, zs, zs, H, 1024, 0);

    // prep (RHS, D11(+planes), C1 planes, D12/B2 planes)
    prep_mats2<<<1024, 256>>>(Y1, Chi, D12, B2);

    // P = 0.5 Pstar Pstar^T + eps I (fp32, feeds Cholesky)
    sgemm64<0, 1><<<dim3(8, 8), 256>>>(Pstar, 512, Pstar, 512, P, 512, 512, 0.5f, 0.0f, EPSc);

    // base = xi C1^T + u D12^T
    Seg sXC1 = { xih, xil, C1h, C1l, NXc, NXc, NXc };
    Seg sUD  = { uh, ul, D12h, D12l, NUc, NUc, NUc };
    mma_gemm<128><<<dim3(4, 256), 512, SM128>>>(sXC1, sUD, zs, base, NQc, 0);

    // fused: solver (16 CTAs, gbar) || full 8-block scan (128 strip CTAs)
    reset_bar<<<1, 32>>>();
    scan_solve<<<144, 256, SMSF>>>();

    // out = xi A^T + w B1^T + u B2^T
    Seg sXA = { xih, xil, Sh, Sl, NXc, 1024, NXc };
    Seg sWB = { wh, wl, Sh + 512, Sl + 512, NQc, 1024, NQc };
    Seg sUB = { uh, ul, B2h, B2l, NUc, NUc, NUc };
    mma_gemm<128><<<dim3(4, 256), 512, SM128>>>(sXA, sWB, sUB, out, NXc, 0);
}

// round 9
// speedup vs baseline: 1.8899x; 1.0305x over previous
#include <cuda_runtime.h>
#include <cuda_bf16.h>
#include <cstdint>
#include <math.h>

#define NXc 512
#define NQc 512
#define NUc 128
#define Bc  32768
#define EPSc 1e-3f

// ================= baseline-ISA helpers (compute_103-safe) ==================
__device__ __forceinline__ uint32_t smem_to_u32(const void* p) {
    uint32_t a;
    asm("{ .reg .u64 t; cvta.to.shared.u64 t, %1; cvt.u32.u64 %0, t; }" : "=r"(a) : "l"(p));
    return a;
}
__device__ __forceinline__ void cpasync16(uint32_t d, const void* s) {
    asm volatile("cp.async.cg.shared.global [%0], [%1], 16;" :: "r"(d), "l"(s));
}
#define CP_COMMIT() asm volatile("cp.async.commit_group;" ::: "memory")
#define CP_WAIT(N)  asm volatile("cp.async.wait_group %0;" :: "n"(N) : "memory")

__device__ __forceinline__ void ldsm4(uint32_t* r, uint32_t addr) {
    asm volatile("ldmatrix.sync.aligned.m8n8.x4.shared.b16 {%0,%1,%2,%3}, [%4];"
        : "=r"(r[0]), "=r"(r[1]), "=r"(r[2]), "=r"(r[3]) : "r"(addr));
}
__device__ __forceinline__ void mma16816(float* d, const uint32_t* a, const uint32_t* b) {
    asm volatile("mma.sync.aligned.m16n8k16.row.col.f32.bf16.bf16.f32 "
        "{%0,%1,%2,%3}, {%4,%5,%6,%7}, {%8,%9}, {%0,%1,%2,%3};"
        : "+f"(d[0]), "+f"(d[1]), "+f"(d[2]), "+f"(d[3])
        : "r"(a[0]), "r"(a[1]), "r"(a[2]), "r"(a[3]), "r"(b[0]), "r"(b[1]));
}
__device__ __forceinline__ uint32_t swz64(uint32_t off) { return off ^ ((off >> 3) & 0x30); }

// ================= scratch (device globals) =================================
__device__ float g_H[1024 * 1024];
__device__ float g_P[NXc * NXc];
__device__ float g_Linv[8 * 64 * 64];
__device__ float g_D11[NQc * NQc];
__device__ float g_RHS[NXc * 1024];
__device__ float g_Z[NXc * 1024];
__device__ float g_S[NXc * 1024];
__device__ float g_base[(size_t)Bc * NQc];
__device__ unsigned g_barCnt;
__device__ __nv_bfloat16 g_xih[(size_t)Bc * NXc], g_xil[(size_t)Bc * NXc];
__device__ __nv_bfloat16 g_uh[(size_t)Bc * NUc],  g_ul[(size_t)Bc * NUc];
__device__ __nv_bfloat16 g_wh[(size_t)Bc * NQc],  g_wl[(size_t)Bc * NQc];
__device__ __nv_bfloat16 g_Xh[1024 * 1024], g_Xl[1024 * 1024];
__device__ __nv_bfloat16 g_C1h[NQc * NXc],  g_C1l[NQc * NXc];
__device__ __nv_bfloat16 g_D11h[NQc * NQc], g_D11l[NQc * NQc];
__device__ __nv_bfloat16 g_Sh[NXc * 1024],  g_Sl[NXc * 1024];
__device__ __nv_bfloat16 g_D12h[NQc * NUc], g_D12l[NQc * NUc];
__device__ __nv_bfloat16 g_B2h[NXc * NUc],  g_B2l[NXc * NUc];

// ================= misc small kernels =======================================
__device__ __forceinline__ float ftanh(float x) {
    float a = fabsf(x);
    float t = __expf(-2.0f * a);
    float r = __fdividef(1.0f - t, 1.0f + t);
    return copysignf(r, x);
}

__global__ void splitk(const float* __restrict__ in, __nv_bfloat16* __restrict__ hi,
                       __nv_bfloat16* __restrict__ lo, int n4) {
    int i = blockIdx.x * 256 + threadIdx.x;
    if (i >= n4) return;
    float4 v = ((const float4*)in)[i];
    __nv_bfloat162 h0, h1, l0, l1;
    h0.x = __float2bfloat16(v.x); h0.y = __float2bfloat16(v.y);
    h1.x = __float2bfloat16(v.z); h1.y = __float2bfloat16(v.w);
    l0.x = __float2bfloat16(v.x - __bfloat162float(h0.x));
    l0.y = __float2bfloat16(v.y - __bfloat162float(h0.y));
    l1.x = __float2bfloat16(v.z - __bfloat162float(h1.x));
    l1.y = __float2bfloat16(v.w - __bfloat162float(h1.y));
    ((__nv_bfloat162*)hi)[i * 2] = h0; ((__nv_bfloat162*)hi)[i * 2 + 1] = h1;
    ((__nv_bfloat162*)lo)[i * 2] = l0; ((__nv_bfloat162*)lo)[i * 2 + 1] = l1;
}

__global__ void prep_mats2(const float* __restrict__ Y1, const float* __restrict__ Chi,
                           const float* __restrict__ D12, const float* __restrict__ B2) {
    int idx = blockIdx.x * 256 + threadIdx.x;
    int i = idx >> 9, j = idx & 511;
    float h1 = g_H[(size_t)i * 1024 + j];
    g_RHS[(size_t)i * 1024 + j] =
        -0.5f * (h1 + ((i == j) ? EPSc : 0.0f) + Y1[(size_t)i * 512 + j] - Y1[(size_t)j * 512 + i]);
    g_RHS[(size_t)i * 1024 + 512 + j] =
        -g_H[(size_t)i * 1024 + 512 + j] - Chi[(size_t)i * 512 + j];
    float rl = 2.0f / (g_H[(size_t)(NXc + i) * 1024 + NXc + i] + EPSc);
    float d = (j < i) ? -g_H[(size_t)(512 + i) * 1024 + 512 + j] * rl : 0.0f;
    g_D11[(size_t)i * 512 + j] = d;
    __nv_bfloat16 dh = __float2bfloat16(d);
    g_D11h[(size_t)i * 512 + j] = dh;
    g_D11l[(size_t)i * 512 + j] = __float2bfloat16(d - __bfloat162float(dh));
    float c1 = Chi[(size_t)j * 512 + i] * rl;
    __nv_bfloat16 ch = __float2bfloat16(c1);
    g_C1h[(size_t)i * 512 + j] = ch;
    g_C1l[(size_t)i * 512 + j] = __float2bfloat16(c1 - __bfloat162float(ch));
    if (j < NUc) {
        float v = D12[(size_t)i * NUc + j];
        __nv_bfloat16 vh = __float2bfloat16(v);
        g_D12h[(size_t)i * NUc + j] = vh;
        g_D12l[(size_t)i * NUc + j] = __float2bfloat16(v - __bfloat162float(vh));
        float w = B2[(size_t)i * NUc + j];
        __nv_bfloat16 wh = __float2bfloat16(w);
        g_B2h[(size_t)i * NUc + j] = wh;
        g_B2l[(size_t)i * NUc + j] = __float2bfloat16(w - __bfloat162float(wh));
    }
}

__global__ void reset_bar() { if (threadIdx.x == 0) g_barCnt = 0u; }

// ================= fp32 SIMT GEMM (P = 0.5 Pstar Pstar^T + eps I) ===========
template <int TA, int TB>
__global__ __launch_bounds__(256) void sgemm64(
    const float* __restrict__ A, int lda,
    const float* __restrict__ B, int ldb,
    float* __restrict__ C, int ldc,
    int K, float alpha, float beta, float diagAdd)
{
    __shared__ float As[16][68];
    __shared__ float Bs[16][68];
    int tid = threadIdx.x;
    int m0 = blockIdx.y * 64, n0 = blockIdx.x * 64;
    int tx = tid & 15, ty = tid >> 4;
    float acc[4][4] = {};
    for (int kt = 0; kt < K; kt += 16) {
        __syncthreads();
        if (TA == 0) {
            int r = tid >> 2, kq = (tid & 3) * 4;
            float4 v = *(const float4*)(A + (size_t)(m0 + r) * lda + kt + kq);
            As[kq + 0][r] = v.x; As[kq + 1][r] = v.y; As[kq + 2][r] = v.z; As[kq + 3][r] = v.w;
        } else {
            int m4 = (tid & 15) * 4, k = tid >> 4;
            float4 v = *(const float4*)(A + (size_t)(kt + k) * lda + m0 + m4);
            As[k][m4 + 0] = v.x; As[k][m4 + 1] = v.y; As[k][m4 + 2] = v.z; As[k][m4 + 3] = v.w;
        }
        if (TB == 0) {
            int n4 = (tid & 15) * 4, k = tid >> 4;
            float4 v = *(const float4*)(B + (size_t)(kt + k) * ldb + n0 + n4);
            Bs[k][n4 + 0] = v.x; Bs[k][n4 + 1] = v.y; Bs[k][n4 + 2] = v.z; Bs[k][n4 + 3] = v.w;
        } else {
            int r = tid >> 2, kq = (tid & 3) * 4;
            float4 v = *(const float4*)(B + (size_t)(n0 + r) * ldb + kt + kq);
            Bs[kq + 0][r] = v.x; Bs[kq + 1][r] = v.y; Bs[kq + 2][r] = v.z; Bs[kq + 3][r] = v.w;
        }
        __syncthreads();
        #pragma unroll
        for (int kk = 0; kk < 16; ++kk) {
            float4 a = *(const float4*)&As[kk][ty * 4];
            float4 b = *(const float4*)&Bs[kk][tx * 4];
            float am[4] = {a.x, a.y, a.z, a.w};
            float bm[4] = {b.x, b.y, b.z, b.w};
            #pragma unroll
            for (int i = 0; i < 4; ++i)
                #pragma unroll
                for (int j = 0; j < 4; ++j)
                    acc[i][j] += am[i] * bm[j];
        }
    }
    #pragma unroll
    for (int i = 0; i < 4; ++i) {
        int gr = m0 + ty * 4 + i;
        #pragma unroll
        for (int j = 0; j < 4; ++j) {
            int gc = n0 + tx * 4 + j;
            float v = alpha * acc[i][j];
            if (beta != 0.0f) v += beta * C[(size_t)gr * ldc + gc];
            if (gr == gc) v += diagAdd;
            C[(size_t)gr * ldc + gc] = v;
        }
    }
}

// ================= solver device pieces (fp32, 256 threads) =================
__device__ __forceinline__ void gbar(unsigned& gen) {
    __syncthreads();
    gen += 16;
    if (threadIdx.x == 0) {
        __threadfence();
        atomicAdd(&g_barCnt, 1u);
        while (*(volatile unsigned*)&g_barCnt < gen) { }
        __threadfence();
    }
    __syncthreads();
}

__device__ void dev_potf2_inv(int k, float (*S)[65], float* Dinv, float* sdp)
{
    int tid = threadIdx.x;
    for (int idx = tid; idx < 4096; idx += 256) {
        int i = idx >> 6, j = idx & 63;
        S[i][j] = g_P[(size_t)(k * 64 + i) * NXc + k * 64 + j];
    }
    __syncthreads();
    for (int j = 0; j < 64; ++j) {
        if (tid == 0) *sdp = rsqrtf(S[j][j]);
        __syncthreads();
        if (tid >= j && tid < 64) S[tid][j] *= *sdp;
        __syncthreads();
        for (int idx = tid; idx < 4096; idx += 256) {
            int i = idx >> 6, c = idx & 63;
            if (i > j && c > j) S[i][c] -= S[i][j] * S[c][j];
        }
        __syncthreads();
    }
    if (tid < 64) Dinv[tid] = 1.0f / S[tid][tid];
    __syncthreads();
    int wd = tid >> 5, lane = tid & 31;
    for (int cc = 0; cc < 8; ++cc) {
        int c = wd * 8 + cc;
        float x0 = (lane == c) ? 1.0f : 0.0f;
        float x1 = (lane + 32 == c) ? 1.0f : 0.0f;
        for (int i = c; i < 64; ++i) {
            float src = (i < 32) ? x0 : x1;
            float part = __shfl_sync(0xffffffffu, src, i & 31);
            float xv = part * Dinv[i];
            if (i < 32) { if (lane == i) x0 = xv; }
            else        { if (lane == i - 32) x1 = xv; }
            if (lane > i)      x0 -= S[lane][i] * xv;
            if (lane + 32 > i) x1 -= S[lane + 32][i] * xv;
        }
        g_Linv[k * 4096 + lane * 64 + c] = x0;
        g_Linv[k * 4096 + (lane + 32) * 64 + c] = x1;
    }
}

__device__ void dev_gemm_ABt64(const float* A, int lda, const float* B, int ldb,
                               float* C, int ldc, float alpha, float beta,
                               float (*As)[68], float (*Bs)[68])
{
    int tid = threadIdx.x;
    int tx = tid & 15, ty = tid >> 4;
    float acc[4][4] = {};
    for (int kt = 0; kt < 64; kt += 16) {
        __syncthreads();
        {
            int r = tid >> 2, kq = (tid & 3) * 4;
            float4 v = *(const float4*)(A + (size_t)r * lda + kt + kq);
            As[kq + 0][r] = v.x; As[kq + 1][r] = v.y; As[kq + 2][r] = v.z; As[kq + 3][r] = v.w;
            float4 w = *(const float4*)(B + (size_t)r * ldb + kt + kq);
            Bs[kq + 0][r] = w.x; Bs[kq + 1][r] = w.y; Bs[kq + 2][r] = w.z; Bs[kq + 3][r] = w.w;
        }
        __syncthreads();
        #pragma unroll
        for (int kk = 0; kk < 16; ++kk) {
            float4 a = *(const float4*)&As[kk][ty * 4];
            float4 b = *(const float4*)&Bs[kk][tx * 4];
            float am[4] = {a.x, a.y, a.z, a.w};
            float bm[4] = {b.x, b.y, b.z, b.w};
            #pragma unroll
            for (int i = 0; i < 4; ++i)
                #pragma unroll
                for (int j = 0; j < 4; ++j)
                    acc[i][j] += am[i] * bm[j];
        }
    }
    __syncthreads();
    #pragma unroll
    for (int i = 0; i < 4; ++i)
        #pragma unroll
        for (int j = 0; j < 4; ++j) {
            float v = alpha * acc[i][j];
            if (beta != 0.0f) v += beta * C[(size_t)(ty * 4 + i) * ldc + tx * 4 + j];
            C[(size_t)(ty * 4 + i) * ldc + tx * 4 + j] = v;
        }
}

__device__ void dev_fwd(int c0, float (*Lt)[65], float (*Zt)[65])
{
    int tid = threadIdx.x;
    int tx = tid & 15, ty = tid >> 4;
    for (int ib = 0; ib < 8; ++ib) {
        float acc[4][4] = {};
        for (int jb = 0; jb < ib; ++jb) {
            for (int idx = tid; idx < 4096; idx += 256) {
                int i = idx >> 6, j = idx & 63;
                Lt[i][j] = g_P[(size_t)(ib * 64 + i) * 512 + jb * 64 + j];
                Zt[i][j] = g_Z[(size_t)(jb * 64 + i) * 1024 + c0 + j];
            }
            __syncthreads();
            #pragma unroll 8
            for (int kk = 0; kk < 64; ++kk)
                #pragma unroll
                for (int ii = 0; ii < 4; ++ii)
                    #pragma unroll
                    for (int jj = 0; jj < 4; ++jj)
                        acc[ii][jj] += Lt[ty * 4 + ii][kk] * Zt[kk][tx * 4 + jj];
            __syncthreads();
        }
        #pragma unroll
        for (int ii = 0; ii < 4; ++ii)
            #pragma unroll
            for (int jj = 0; jj < 4; ++jj)
                Zt[ty * 4 + ii][tx * 4 + jj] =
                    g_RHS[(size_t)(ib * 64 + ty * 4 + ii) * 1024 + c0 + tx * 4 + jj] - acc[ii][jj];
        for (int idx = tid; idx < 4096; idx += 256) {
            int i = idx >> 6, j = idx & 63;
            Lt[i][j] = g_Linv[ib * 4096 + i * 64 + j];
        }
        __syncthreads();
        float z[4][4] = {};
        #pragma unroll 8
        for (int kk = 0; kk < 64; ++kk)
            #pragma unroll
            for (int ii = 0; ii < 4; ++ii)
                #pragma unroll
                for (int jj = 0; jj < 4; ++jj)
                    z[ii][jj] += Lt[ty * 4 + ii][kk] * Zt[kk][tx * 4 + jj];
        #pragma unroll
        for (int ii = 0; ii < 4; ++ii)
            #pragma unroll
            for (int jj = 0; jj < 4; ++jj)
                g_Z[(size_t)(ib * 64 + ty * 4 + ii) * 1024 + c0 + tx * 4 + jj] = z[ii][jj];
        __syncthreads();
    }
}

__device__ void dev_bwd(int c0, float (*Lt)[65], float (*Zt)[65])
{
    int tid = threadIdx.x;
    int tx = tid & 15, ty = tid >> 4;
    for (int ib = 7; ib >= 0; --ib) {
        float acc[4][4] = {};
        for (int jb = ib + 1; jb < 8; ++jb) {
            for (int idx = tid; idx < 4096; idx += 256) {
                int i = idx >> 6, j = idx & 63;
                Lt[i][j] = g_P[(size_t)(jb * 64 + i) * 512 + ib * 64 + j];
                Zt[i][j] = g_S[(size_t)(jb * 64 + i) * 1024 + c0 + j];
            }
            __syncthreads();
            #pragma unroll 8
            for (int kk = 0; kk < 64; ++kk)
                #pragma unroll
                for (int ii = 0; ii < 4; ++ii)
                    #pragma unroll
                    for (int jj = 0; jj < 4; ++jj)
                        acc[ii][jj] += Lt[kk][ty * 4 + ii] * Zt[kk][tx * 4 + jj];
            __syncthreads();
        }
        #pragma unroll
        for (int ii = 0; ii < 4; ++ii)
            #pragma unroll
            for (int jj = 0; jj < 4; ++jj)
                Zt[ty * 4 + ii][tx * 4 + jj] =
                    g_Z[(size_t)(ib * 64 + ty * 4 + ii) * 1024 + c0 + tx * 4 + jj] - acc[ii][jj];
        for (int idx = tid; idx < 4096; idx += 256) {
            int i = idx >> 6, j = idx & 63;
            Lt[i][j] = g_Linv[ib * 4096 + i * 64 + j];
        }
        __syncthreads();
        float z[4][4] = {};
        #pragma unroll 8
        for (int kk = 0; kk < 64; ++kk)
            #pragma unroll
            for (int ii = 0; ii < 4; ++ii)
                #pragma unroll
                for (int jj = 0; jj < 4; ++jj)
                    z[ii][jj] += Lt[kk][ty * 4 + ii] * Zt[kk][tx * 4 + jj];
        #pragma unroll
        for (int ii = 0; ii < 4; ++ii)
            #pragma unroll
            for (int jj = 0; jj < 4; ++jj)
                g_S[(size_t)(ib * 64 + ty * 4 + ii) * 1024 + c0 + tx * 4 + jj] = z[ii][jj];
        __syncthreads();
    }
}

// ================= mma.sync split-bf16 batch GEMM (v3: 2 CTAs/SM) ===========
// 2-stage cp.async pipeline (proven schedule), __launch_bounds__(512,2) to
// cap regs at 64 so two CTAs co-reside. B fragments loaded per j-pair to
// minimize register liveness.
struct Seg {
    const __nv_bfloat16 *Ah, *Al, *Wh, *Wl;
    int lda, ldw, K;
};

template <int NT>
__global__ __launch_bounds__(512, 2) void mma_gemm(
    Seg s0, Seg s1, Seg s2, float* __restrict__ C, int ldc, int addTo)
{
    extern __shared__ __align__(128) char smem[];
    constexpr int AP  = 128 * 64;
    constexpr int WP  = NT * 64;
    constexpr int STG = 2 * AP + 2 * WP;
    constexpr int NAw = NT / 32;

    uint32_t sb = smem_to_u32(smem);
    int tid = threadIdx.x;
    int wid = tid >> 5, lane = tid & 31;
    int m0 = blockIdx.y * 128, n0 = blockIdx.x * NT;
    int wm = (wid & 3) * 32;
    int wn = (wid >> 2) * (NT / 4);

    int nk0 = s0.K >> 5, nk1 = s1.K >> 5, nk2 = s2.K >> 5;
    int nk = nk0 + nk1 + nk2;

    auto issue = [&](int c) {
        int cs = c;
        const Seg* sg = &s0;
        if (cs >= nk0) { cs -= nk0; sg = &s1; if (cs >= nk1) { cs -= nk1; sg = &s2; } }
        int kt = cs << 5;
        uint32_t stu = sb + (c & 1) * STG;
        #pragma unroll
        for (int s = tid; s < 1024; s += 512) {
            int pl = s >> 9, rem = s & 511, row = rem >> 2, q = rem & 3;
            const __nv_bfloat16* src =
                (pl ? sg->Al : sg->Ah) + (size_t)(m0 + row) * sg->lda + kt + q * 8;
            cpasync16(stu + pl * AP + swz64(row * 64 + q * 16), src);
        }
        #pragma unroll
        for (int s = tid; s < NT * 8; s += 512) {
            int pl = (s >= NT * 4) ? 1 : 0;
            int rem = pl ? s - NT * 4 : s;
            int row = rem >> 2, q = rem & 3;
            const __nv_bfloat16* src =
                (pl ? sg->Wl : sg->Wh) + (size_t)(n0 + row) * sg->ldw + kt + q * 8;
            cpasync16(stu + 2 * AP + pl * WP + swz64(row * 64 + q * 16), src);
        }
        CP_COMMIT();
    };

    float acc[2][NAw][4] = {};

    issue(0);
    for (int c = 0; c < nk; ++c) {
        if (c + 1 < nk) { issue(c + 1); CP_WAIT(1); }
        else            { CP_WAIT(0); }
        __syncthreads();
        uint32_t stu = sb + (c & 1) * STG;
        #pragma unroll
        for (int ks = 0; ks < 2; ++ks) {
            uint32_t ah[2][4], al[2][4];
            #pragma unroll
            for (int am = 0; am < 2; ++am) {
                uint32_t off = (uint32_t)(wm + am * 16 + (lane & 15)) * 64
                               + ks * 32 + (lane >> 4) * 16;
                ldsm4(ah[am], stu + swz64(off));
                ldsm4(al[am], stu + AP + swz64(off));
            }
            #pragma unroll
            for (int p = 0; p < NAw / 2; ++p) {
                int g = lane >> 3;
                uint32_t off = (uint32_t)(wn + p * 16 + ((g >> 1) << 3) + (lane & 7)) * 64
                               + ks * 32 + (g & 1) * 16;
                uint32_t th[4], tl[4];
                ldsm4(th, stu + 2 * AP + swz64(off));
                ldsm4(tl, stu + 2 * AP + WP + swz64(off));
                #pragma unroll
                for (int am = 0; am < 2; ++am) {
                    mma16816(acc[am][2 * p],     ah[am], th);
                    mma16816(acc[am][2 * p],     ah[am], tl);
                    mma16816(acc[am][2 * p],     al[am], th);
                    mma16816(acc[am][2 * p + 1], ah[am], th + 2);
                    mma16816(acc[am][2 * p + 1], ah[am], tl + 2);
                    mma16816(acc[am][2 * p + 1], al[am], th + 2);
                }
            }
        }
        __syncthreads();
    }

    #pragma unroll
    for (int am = 0; am < 2; ++am) {
        int r0 = m0 + wm + am * 16 + (lane >> 2);
        #pragma unroll
        for (int j = 0; j < NAw; ++j) {
            int cc = n0 + wn + j * 8 + (lane & 3) * 2;
            float* p0 = C + (size_t)r0 * ldc + cc;
            float* p1 = C + (size_t)(r0 + 8) * ldc + cc;
            float2 v0 = make_float2(acc[am][j][0], acc[am][j][1]);
            float2 v1 = make_float2(acc[am][j][2], acc[am][j][3]);
            if (addTo) {
                float2 o0 = *(const float2*)p0, o1 = *(const float2*)p1;
                v0.x += o0.x; v0.y += o0.y; v1.x += o1.x; v1.y += o1.y;
            }
            *(float2*)p0 = v0;
            *(float2*)p1 = v1;
        }
    }
}

// ================= fused scan (all 8 blocks) + solver, one launch ===========
// grid = 144 CTAs x 256 threads.
//   CTAs 0-15:  blocked Cholesky + fwd/bwd solves + S split (gbar among 16).
//   CTAs 16-143: per-strip scan; strip = 256 rows; all 8 column blocks looped
//                internally. Cross-GEMM reads only the CTA's OWN strip of w.
__global__ __launch_bounds__(256) void scan_solve()
{
    extern __shared__ __align__(128) char smem[];
    int tid = threadIdx.x;

    if (blockIdx.x < 16) {
        float (*shA)[68] = (float(*)[68])(smem);
        float (*shB)[68] = (float(*)[68])(smem + 16 * 68 * 4);
        float (*S64)[65] = (float(*)[65])(smem + 2 * 16 * 68 * 4);
        float (*T64)[65] = (float(*)[65])(smem + 2 * 16 * 68 * 4 + 64 * 65 * 4);
        float* Dinv      = (float*)(smem + 2 * 16 * 68 * 4 + 2 * 64 * 65 * 4);
        float* sdv       = Dinv + 64;
        int cta = blockIdx.x;
        unsigned gen = 0;

        for (int k = 0; k < 8; ++k) {
            if (cta == 0) dev_potf2_inv(k, S64, Dinv, sdv);
            gbar(gen);
            int nrem = 7 - k;
            if (nrem > 0) {
                if (cta < nrem) {
                    int i = k + 1 + cta;
                    float* panel = g_P + (size_t)i * 64 * 512 + k * 64;
                    dev_gemm_ABt64(panel, 512, g_Linv + k * 4096, 64,
                                   panel, 512, 1.0f, 0.0f, shA, shB);
                }
                gbar(gen);
                int t = 0;
                for (int i = k + 1; i < 8; ++i)
                    for (int j = k + 1; j <= i; ++j, ++t)
                        if ((t & 15) == cta)
                            dev_gemm_ABt64(g_P + (size_t)i * 64 * 512 + k * 64, 512,
                                           g_P + (size_t)j * 64 * 512 + k * 64, 512,
                                           g_P + (size_t)i * 64 * 512 + j * 64, 512,
                                           -1.0f, 1.0f, shA, shB);
                gbar(gen);
            }
        }
        dev_fwd(cta * 64, S64, T64);
        dev_bwd(cta * 64, S64, T64);
        gbar(gen);
        for (int i = cta * 256 + tid; i < NXc * 1024 / 4; i += 4096) {
            float4 v = ((const float4*)g_S)[i];
            __nv_bfloat162 h0, h1, l0, l1;
            h0.x = __float2bfloat16(v.x); h0.y = __float2bfloat16(v.y);
            h1.x = __float2bfloat16(v.z); h1.y = __float2bfloat16(v.w);
            l0.x = __float2bfloat16(v.x - __bfloat162float(h0.x));
            l0.y = __float2bfloat16(v.y - __bfloat162float(h0.y));
            l1.x = __float2bfloat16(v.z - __bfloat162float(h1.x));
            l1.y = __float2bfloat16(v.w - __bfloat162float(h1.y));
            ((__nv_bfloat162*)g_Sh)[i * 2] = h0; ((__nv_bfloat162*)g_Sh)[i * 2 + 1] = h1;
            ((__nv_bfloat162*)g_Sl)[i * 2] = l0; ((__nv_bfloat162*)g_Sl)[i * 2 + 1] = l1;
        }
        return;
    }

    constexpr int APc  = 256 * 64;
    constexpr int WPc  = 64 * 64;
    constexpr int STGc = 2 * APc + 2 * WPc;
    constexpr int CRo  = 2 * STGc;
    constexpr int DSo  = CRo + 256 * 68 * 4;
    uint32_t sb = smem_to_u32(smem);
    float* cross = (float*)(smem + CRo);
    float* ds    = (float*)(smem + DSo);
    int wid = tid >> 5, lane = tid & 31;
    int strip0 = (blockIdx.x - 16) * 256;

    for (int b = 0; b < 8; ++b) {
        int nk = (64 * b) >> 5;

        auto issue = [&](int c) {
            int kt = c << 5;
            uint32_t stu = sb + (c & 1) * STGc;
            #pragma unroll
            for (int s = tid; s < 2048; s += 256) {
                int pl = s >> 10, rem = s & 1023, row = rem >> 2, q = rem & 3;
                const __nv_bfloat16* src =
                    (pl ? g_wl : g_wh) + (size_t)(strip0 + row) * NQc + kt + q * 8;
                cpasync16(stu + pl * APc + swz64(row * 64 + q * 16), src);
            }
            #pragma unroll
            for (int s = tid; s < 512; s += 256) {
                int pl = s >> 8, rem = s & 255, row = rem >> 2, q = rem & 3;
                const __nv_bfloat16* src =
                    (pl ? g_D11l : g_D11h) + (size_t)(b * 64 + row) * NQc + kt + q * 8;
                cpasync16(stu + 2 * APc + pl * WPc + swz64(row * 64 + q * 16), src);
            }
            CP_COMMIT();
        };

        float acc[2][8][4] = {};
        if (nk > 0) {
            issue(0);
            for (int c = 0; c < nk; ++c) {
                if (c + 1 < nk) { issue(c + 1); CP_WAIT(1); }
                else            { CP_WAIT(0); }
                __syncthreads();
                uint32_t stu = sb + (c & 1) * STGc;
                int wm = wid * 32;
                #pragma unroll
                for (int ks = 0; ks < 2; ++ks) {
                    uint32_t ah[2][4], al[2][4];
                    #pragma unroll
                    for (int am = 0; am < 2; ++am) {
                        uint32_t off = (uint32_t)(wm + am * 16 + (lane & 15)) * 64
                                       + ks * 32 + (lane >> 4) * 16;
                        ldsm4(ah[am], stu + swz64(off));
                        ldsm4(al[am], stu + APc + swz64(off));
                    }
                    uint32_t bh[8][2], bl[8][2];
                    #pragma unroll
                    for (int p = 0; p < 4; ++p) {
                        int g = lane >> 3;
                        uint32_t off = (uint32_t)(p * 16 + ((g >> 1) << 3) + (lane & 7)) * 64
                                       + ks * 32 + (g & 1) * 16;
                        uint32_t t4[4];
                        ldsm4(t4, stu + 2 * APc + swz64(off));
                        bh[2 * p][0] = t4[0]; bh[2 * p][1] = t4[1];
                        bh[2 * p + 1][0] = t4[2]; bh[2 * p + 1][1] = t4[3];
                        ldsm4(t4, stu + 2 * APc + WPc + swz64(off));
                        bl[2 * p][0] = t4[0]; bl[2 * p][1] = t4[1];
                        bl[2 * p + 1][0] = t4[2]; bl[2 * p + 1][1] = t4[3];
                    }
                    #pragma unroll
                    for (int am = 0; am < 2; ++am)
                        #pragma unroll
                        for (int j = 0; j < 8; ++j) {
                            mma16816(acc[am][j], ah[am], bh[j]);
                            mma16816(acc[am][j], ah[am], bl[j]);
                            mma16816(acc[am][j], al[am], bh[j]);
                        }
                }
                __syncthreads();
            }
        }
        {
            int wm = wid * 32;
            #pragma unroll
            for (int am = 0; am < 2; ++am) {
                int r0 = wm + am * 16 + (lane >> 2);
                #pragma unroll
                for (int j = 0; j < 8; ++j) {
                    int cc = j * 8 + (lane & 3) * 2;
                    cross[r0 * 68 + cc]           = acc[am][j][0];
                    cross[r0 * 68 + cc + 1]       = acc[am][j][1];
                    cross[(r0 + 8) * 68 + cc]     = acc[am][j][2];
                    cross[(r0 + 8) * 68 + cc + 1] = acc[am][j][3];
                }
            }
        }
        for (int idx = tid; idx < 4096; idx += 256) {
            int i = idx >> 6, j = idx & 63;
            ds[i * 65 + j] = g_D11[(size_t)(b * 64 + i) * NQc + b * 64 + j];
        }
        __syncthreads();

        int r = strip0 + tid;
        float bb[64];
        const float4* bp = (const float4*)(g_base + (size_t)r * NQc + b * 64);
        #pragma unroll
        for (int q = 0; q < 16; ++q) {
            float4 v = bp[q];
            bb[q * 4 + 0] = v.x + cross[tid * 68 + q * 4 + 0];
            bb[q * 4 + 1] = v.y + cross[tid * 68 + q * 4 + 1];
            bb[q * 4 + 2] = v.z + cross[tid * 68 + q * 4 + 2];
            bb[q * 4 + 3] = v.w + cross[tid * 68 + q * 4 + 3];
        }
        float wv[64];
        #pragma unroll
        for (int i = 0; i < 64; ++i) {
            float s0 = 0.f, s1 = 0.f, s2 = 0.f, s3 = 0.f;
            #pragma unroll
            for (int j = 0; j < 64; ++j) {
                if (j < i) {
                    float p = wv[j] * ds[i * 65 + j];
                    if      ((j & 3) == 0) s0 += p;
                    else if ((j & 3) == 1) s1 += p;
                    else if ((j & 3) == 2) s2 += p;
                    else                   s3 += p;
                }
            }
            wv[i] = ftanh(bb[i] + ((s0 + s1) + (s2 + s3)));
        }
        __nv_bfloat162* whp = (__nv_bfloat162*)(g_wh + (size_t)r * NQc + b * 64);
        __nv_bfloat162* wlp = (__nv_bfloat162*)(g_wl + (size_t)r * NQc + b * 64);
        #pragma unroll
        for (int q = 0; q < 32; ++q) {
            float a = wv[q * 2], c = wv[q * 2 + 1];
            __nv_bfloat162 h, l;
            h.x = __float2bfloat16(a); h.y = __float2bfloat16(c);
            l.x = __float2bfloat16(a - __bfloat162float(h.x));
            l.y = __float2bfloat16(c - __bfloat162float(h.y));
            whp[q] = h; wlp[q] = l;
        }
        __syncthreads();
    }
}

// ================= host orchestration =======================================
extern "C" void kernel_launch(void* const* d_in, const int* in_sizes, int n_in,
                              void* d_out, int out_size)
{
    const float* xi    = (const float*)d_in[1];
    const float* u     = (const float*)d_in[2];
    const float* Pstar = (const float*)d_in[3];
    const float* Chi   = (const float*)d_in[4];
    const float* Y1    = (const float*)d_in[5];
    const float* B2    = (const float*)d_in[6];
    const float* D12   = (const float*)d_in[7];
    const float* X     = (const float*)d_in[8];
    float* out = (float*)d_out;

    float *H, *P, *base;
    __nv_bfloat16 *xih, *xil, *uh, *ul, *wh, *wl, *Xh, *Xl, *C1h, *C1l, *D11h, *D11l;
    __nv_bfloat16 *Sh, *Sl, *D12h, *D12l, *B2h, *B2l;
    cudaGetSymbolAddress((void**)&H, g_H);       cudaGetSymbolAddress((void**)&P, g_P);
    cudaGetSymbolAddress((void**)&base, g_base);
    cudaGetSymbolAddress((void**)&xih, g_xih);   cudaGetSymbolAddress((void**)&xil, g_xil);
    cudaGetSymbolAddress((void**)&uh, g_uh);     cudaGetSymbolAddress((void**)&ul, g_ul);
    cudaGetSymbolAddress((void**)&wh, g_wh);     cudaGetSymbolAddress((void**)&wl, g_wl);
    cudaGetSymbolAddress((void**)&Xh, g_Xh);     cudaGetSymbolAddress((void**)&Xl, g_Xl);
    cudaGetSymbolAddress((void**)&C1h, g_C1h);   cudaGetSymbolAddress((void**)&C1l, g_C1l);
    cudaGetSymbolAddress((void**)&D11h, g_D11h); cudaGetSymbolAddress((void**)&D11l, g_D11l);
    cudaGetSymbolAddress((void**)&Sh, g_Sh);     cudaGetSymbolAddress((void**)&Sl, g_Sl);
    cudaGetSymbolAddress((void**)&D12h, g_D12h); cudaGetSymbolAddress((void**)&D12l, g_D12l);
    cudaGetSymbolAddress((void**)&B2h, g_B2h);   cudaGetSymbolAddress((void**)&B2l, g_B2l);

    constexpr int SM128 = 2 * (2 * 128 * 64 + 2 * 128 * 64);     // 65536 (2-stage)
    constexpr int SM64  = 2 * (2 * 128 * 64 + 2 * 64 * 64);      // 49152 (2-stage)
    constexpr int SMSF  = 2 * (2 * 256 * 64 + 2 * 64 * 64) + 256 * 68 * 4 + 64 * 65 * 4; // 168192
    cudaFuncSetAttribute(mma_gemm<128>, cudaFuncAttributeMaxDynamicSharedMemorySize, SM128);
    cudaFuncSetAttribute(mma_gemm<64>,  cudaFuncAttributeMaxDynamicSharedMemorySize, SM64);
    cudaFuncSetAttribute(scan_solve,    cudaFuncAttributeMaxDynamicSharedMemorySize, SMSF);

    Seg zs = { nullptr, nullptr, nullptr, nullptr, 0, 0, 0 };

    // splits
    splitk<<<16384, 256>>>(xi, xih, xil, Bc * NXc / 4);
    splitk<<<4096, 256>>>(u, uh, ul, Bc * NUc / 4);
    splitk<<<1024, 256>>>(X, Xh, Xl, 1024 * 1024 / 4);

    // H = X X^T via tensor path
    Seg sXX = { Xh, Xl, Xh, Xl, 1024, 1024, 1024 };
    mma_gemm<64><<<dim3(16, 8), 512, SM64>>>(sXX, zs, zs, H, 1024, 0);

    // prep (RHS, D11(+planes), C1 planes, D12/B2 planes)
    prep_mats2<<<1024, 256>>>(Y1, Chi, D12, B2);

    // P = 0.5 Pstar Pstar^T + eps I (fp32, feeds Cholesky)
    sgemm64<0, 1><<<dim3(8, 8), 256>>>(Pstar, 512, Pstar, 512, P, 512, 512, 0.5f, 0.0f, EPSc);

    // base = xi C1^T + u D12^T
    Seg sXC1 = { xih, xil, C1h, C1l, NXc, NXc, NXc };
    Seg sUD  = { uh, ul, D12h, D12l, NUc, NUc, NUc };
    mma_gemm<128><<<dim3(4, 256), 512, SM128>>>(sXC1, sUD, zs, base, NQc, 0);

    // fused: solver (16 CTAs, gbar) || full 8-block scan (128 strip CTAs)
    reset_bar<<<1, 32>>>();
    scan_solve<<<144, 256, SMSF>>>();

    // out = xi A^T + w B1^T + u B2^T
    Seg sXA = { xih, xil, Sh, Sl, NXc, 1024, NXc };
    Seg sWB = { wh, wl, Sh + 512, Sl + 512, NQc, 1024, NQc };
    Seg sUB = { uh, ul, B2h, B2l, NUc, NUc, NUc };
    mma_gemm<128><<<dim3(4, 256), 512, SM128>>>(sXA, sWB, sUB, out, NXc, 0);
}

// round 10
// speedup vs baseline: 1.9181x; 1.0149x over previous
#include <cuda_runtime.h>
#include <cuda_bf16.h>
#include <cstdint>
#include <math.h>

#define NXc 512
#define NQc 512
#define NUc 128
#define Bc  32768
#define EPSc 1e-3f

// ================= baseline-ISA helpers (compute_103-safe) ==================
__device__ __forceinline__ uint32_t smem_to_u32(const void* p) {
    uint32_t a;
    asm("{ .reg .u64 t; cvta.to.shared.u64 t, %1; cvt.u32.u64 %0, t; }" : "=r"(a) : "l"(p));
    return a;
}
__device__ __forceinline__ void cpasync16(uint32_t d, const void* s) {
    asm volatile("cp.async.cg.shared.global [%0], [%1], 16;" :: "r"(d), "l"(s));
}
#define CP_COMMIT() asm volatile("cp.async.commit_group;" ::: "memory")
#define CP_WAIT(N)  asm volatile("cp.async.wait_group %0;" :: "n"(N) : "memory")

__device__ __forceinline__ void ldsm4(uint32_t* r, uint32_t addr) {
    asm volatile("ldmatrix.sync.aligned.m8n8.x4.shared.b16 {%0,%1,%2,%3}, [%4];"
        : "=r"(r[0]), "=r"(r[1]), "=r"(r[2]), "=r"(r[3]) : "r"(addr));
}
__device__ __forceinline__ void mma16816(float* d, const uint32_t* a, const uint32_t* b) {
    asm volatile("mma.sync.aligned.m16n8k16.row.col.f32.bf16.bf16.f32 "
        "{%0,%1,%2,%3}, {%4,%5,%6,%7}, {%8,%9}, {%0,%1,%2,%3};"
        : "+f"(d[0]), "+f"(d[1]), "+f"(d[2]), "+f"(d[3])
        : "r"(a[0]), "r"(a[1]), "r"(a[2]), "r"(a[3]), "r"(b[0]), "r"(b[1]));
}
__device__ __forceinline__ uint32_t swz64(uint32_t off) { return off ^ ((off >> 3) & 0x30); }

// ================= scratch (device globals) =================================
__device__ float g_H[1024 * 1024];
__device__ float g_P[NXc * NXc];
__device__ float g_Linv[8 * 64 * 64];
__device__ float g_D11[NQc * NQc];
__device__ float g_RHS[NXc * 1024];
__device__ float g_Z[NXc * 1024];
__device__ float g_S[NXc * 1024];
__device__ unsigned g_barCnt;
__device__ __nv_bfloat16 g_xih[(size_t)Bc * NXc], g_xil[(size_t)Bc * NXc];
__device__ __nv_bfloat16 g_uh[(size_t)Bc * NUc],  g_ul[(size_t)Bc * NUc];
__device__ __nv_bfloat16 g_wh[(size_t)Bc * NQc],  g_wl[(size_t)Bc * NQc];
__device__ __nv_bfloat16 g_Xh[1024 * 1024], g_Xl[1024 * 1024];
__device__ __nv_bfloat16 g_C1h[NQc * NXc],  g_C1l[NQc * NXc];
__device__ __nv_bfloat16 g_D11h[NQc * NQc], g_D11l[NQc * NQc];
__device__ __nv_bfloat16 g_Sh[NXc * 1024],  g_Sl[NXc * 1024];
__device__ __nv_bfloat16 g_D12h[NQc * NUc], g_D12l[NQc * NUc];
__device__ __nv_bfloat16 g_B2h[NXc * NUc],  g_B2l[NXc * NUc];

// ================= misc small kernels =======================================
__device__ __forceinline__ float ftanh(float x) {
    float a = fabsf(x);
    float t = __expf(-2.0f * a);
    float r = __fdividef(1.0f - t, 1.0f + t);
    return copysignf(r, x);
}

__global__ void splitk(const float* __restrict__ in, __nv_bfloat16* __restrict__ hi,
                       __nv_bfloat16* __restrict__ lo, int n4) {
    int i = blockIdx.x * 256 + threadIdx.x;
    if (i >= n4) return;
    float4 v = ((const float4*)in)[i];
    __nv_bfloat162 h0, h1, l0, l1;
    h0.x = __float2bfloat16(v.x); h0.y = __float2bfloat16(v.y);
    h1.x = __float2bfloat16(v.z); h1.y = __float2bfloat16(v.w);
    l0.x = __float2bfloat16(v.x - __bfloat162float(h0.x));
    l0.y = __float2bfloat16(v.y - __bfloat162float(h0.y));
    l1.x = __float2bfloat16(v.z - __bfloat162float(h1.x));
    l1.y = __float2bfloat16(v.w - __bfloat162float(h1.y));
    ((__nv_bfloat162*)hi)[i * 2] = h0; ((__nv_bfloat162*)hi)[i * 2 + 1] = h1;
    ((__nv_bfloat162*)lo)[i * 2] = l0; ((__nv_bfloat162*)lo)[i * 2 + 1] = l1;
}

__global__ void prep_mats2(const float* __restrict__ Y1, const float* __restrict__ Chi,
                           const float* __restrict__ D12, const float* __restrict__ B2) {
    int idx = blockIdx.x * 256 + threadIdx.x;
    int i = idx >> 9, j = idx & 511;
    float h1 = g_H[(size_t)i * 1024 + j];
    g_RHS[(size_t)i * 1024 + j] =
        -0.5f * (h1 + ((i == j) ? EPSc : 0.0f) + Y1[(size_t)i * 512 + j] - Y1[(size_t)j * 512 + i]);
    g_RHS[(size_t)i * 1024 + 512 + j] =
        -g_H[(size_t)i * 1024 + 512 + j] - Chi[(size_t)i * 512 + j];
    float rl = 2.0f / (g_H[(size_t)(NXc + i) * 1024 + NXc + i] + EPSc);
    float d = (j < i) ? -g_H[(size_t)(512 + i) * 1024 + 512 + j] * rl : 0.0f;
    g_D11[(size_t)i * 512 + j] = d;
    __nv_bfloat16 dh = __float2bfloat16(d);
    g_D11h[(size_t)i * 512 + j] = dh;
    g_D11l[(size_t)i * 512 + j] = __float2bfloat16(d - __bfloat162float(dh));
    float c1 = Chi[(size_t)j * 512 + i] * rl;
    __nv_bfloat16 ch = __float2bfloat16(c1);
    g_C1h[(size_t)i * 512 + j] = ch;
    g_C1l[(size_t)i * 512 + j] = __float2bfloat16(c1 - __bfloat162float(ch));
    if (j < NUc) {
        float v = D12[(size_t)i * NUc + j];
        __nv_bfloat16 vh = __float2bfloat16(v);
        g_D12h[(size_t)i * NUc + j] = vh;
        g_D12l[(size_t)i * NUc + j] = __float2bfloat16(v - __bfloat162float(vh));
        float w = B2[(size_t)i * NUc + j];
        __nv_bfloat16 wh = __float2bfloat16(w);
        g_B2h[(size_t)i * NUc + j] = wh;
        g_B2l[(size_t)i * NUc + j] = __float2bfloat16(w - __bfloat162float(wh));
    }
}

__global__ void reset_bar() { if (threadIdx.x == 0) g_barCnt = 0u; }

// ================= fp32 SIMT GEMM (P = 0.5 Pstar Pstar^T + eps I) ===========
template <int TA, int TB>
__global__ __launch_bounds__(256) void sgemm64(
    const float* __restrict__ A, int lda,
    const float* __restrict__ B, int ldb,
    float* __restrict__ C, int ldc,
    int K, float alpha, float beta, float diagAdd)
{
    __shared__ float As[16][68];
    __shared__ float Bs[16][68];
    int tid = threadIdx.x;
    int m0 = blockIdx.y * 64, n0 = blockIdx.x * 64;
    int tx = tid & 15, ty = tid >> 4;
    float acc[4][4] = {};
    for (int kt = 0; kt < K; kt += 16) {
        __syncthreads();
        if (TA == 0) {
            int r = tid >> 2, kq = (tid & 3) * 4;
            float4 v = *(const float4*)(A + (size_t)(m0 + r) * lda + kt + kq);
            As[kq + 0][r] = v.x; As[kq + 1][r] = v.y; As[kq + 2][r] = v.z; As[kq + 3][r] = v.w;
        } else {
            int m4 = (tid & 15) * 4, k = tid >> 4;
            float4 v = *(const float4*)(A + (size_t)(kt + k) * lda + m0 + m4);
            As[k][m4 + 0] = v.x; As[k][m4 + 1] = v.y; As[k][m4 + 2] = v.z; As[k][m4 + 3] = v.w;
        }
        if (TB == 0) {
            int n4 = (tid & 15) * 4, k = tid >> 4;
            float4 v = *(const float4*)(B + (size_t)(kt + k) * ldb + n0 + n4);
            Bs[k][n4 + 0] = v.x; Bs[k][n4 + 1] = v.y; Bs[k][n4 + 2] = v.z; Bs[k][n4 + 3] = v.w;
        } else {
            int r = tid >> 2, kq = (tid & 3) * 4;
            float4 v = *(const float4*)(B + (size_t)(n0 + r) * ldb + kt + kq);
            Bs[kq + 0][r] = v.x; Bs[kq + 1][r] = v.y; Bs[kq + 2][r] = v.z; Bs[kq + 3][r] = v.w;
        }
        __syncthreads();
        #pragma unroll
        for (int kk = 0; kk < 16; ++kk) {
            float4 a = *(const float4*)&As[kk][ty * 4];
            float4 b = *(const float4*)&Bs[kk][tx * 4];
            float am[4] = {a.x, a.y, a.z, a.w};
            float bm[4] = {b.x, b.y, b.z, b.w};
            #pragma unroll
            for (int i = 0; i < 4; ++i)
                #pragma unroll
                for (int j = 0; j < 4; ++j)
                    acc[i][j] += am[i] * bm[j];
        }
    }
    #pragma unroll
    for (int i = 0; i < 4; ++i) {
        int gr = m0 + ty * 4 + i;
        #pragma unroll
        for (int j = 0; j < 4; ++j) {
            int gc = n0 + tx * 4 + j;
            float v = alpha * acc[i][j];
            if (beta != 0.0f) v += beta * C[(size_t)gr * ldc + gc];
            if (gr == gc) v += diagAdd;
            C[(size_t)gr * ldc + gc] = v;
        }
    }
}

// ================= solver device pieces (fp32, 256 threads) =================
__device__ __forceinline__ void gbar(unsigned& gen) {
    __syncthreads();
    gen += 16;
    if (threadIdx.x == 0) {
        __threadfence();
        atomicAdd(&g_barCnt, 1u);
        while (*(volatile unsigned*)&g_barCnt < gen) { }
        __threadfence();
    }
    __syncthreads();
}

__device__ void dev_potf2_inv(int k, float (*S)[65], float* Dinv, float* sdp)
{
    int tid = threadIdx.x;
    for (int idx = tid; idx < 4096; idx += 256) {
        int i = idx >> 6, j = idx & 63;
        S[i][j] = g_P[(size_t)(k * 64 + i) * NXc + k * 64 + j];
    }
    __syncthreads();
    for (int j = 0; j < 64; ++j) {
        if (tid == 0) *sdp = rsqrtf(S[j][j]);
        __syncthreads();
        if (tid >= j && tid < 64) S[tid][j] *= *sdp;
        __syncthreads();
        for (int idx = tid; idx < 4096; idx += 256) {
            int i = idx >> 6, c = idx & 63;
            if (i > j && c > j) S[i][c] -= S[i][j] * S[c][j];
        }
        __syncthreads();
    }
    if (tid < 64) Dinv[tid] = 1.0f / S[tid][tid];
    __syncthreads();
    int wd = tid >> 5, lane = tid & 31;
    for (int cc = 0; cc < 8; ++cc) {
        int c = wd * 8 + cc;
        float x0 = (lane == c) ? 1.0f : 0.0f;
        float x1 = (lane + 32 == c) ? 1.0f : 0.0f;
        for (int i = c; i < 64; ++i) {
            float src = (i < 32) ? x0 : x1;
            float part = __shfl_sync(0xffffffffu, src, i & 31);
            float xv = part * Dinv[i];
            if (i < 32) { if (lane == i) x0 = xv; }
            else        { if (lane == i - 32) x1 = xv; }
            if (lane > i)      x0 -= S[lane][i] * xv;
            if (lane + 32 > i) x1 -= S[lane + 32][i] * xv;
        }
        g_Linv[k * 4096 + lane * 64 + c] = x0;
        g_Linv[k * 4096 + (lane + 32) * 64 + c] = x1;
    }
}

__device__ void dev_gemm_ABt64(const float* A, int lda, const float* B, int ldb,
                               float* C, int ldc, float alpha, float beta,
                               float (*As)[68], float (*Bs)[68])
{
    int tid = threadIdx.x;
    int tx = tid & 15, ty = tid >> 4;
    float acc[4][4] = {};
    for (int kt = 0; kt < 64; kt += 16) {
        __syncthreads();
        {
            int r = tid >> 2, kq = (tid & 3) * 4;
            float4 v = *(const float4*)(A + (size_t)r * lda + kt + kq);
            As[kq + 0][r] = v.x; As[kq + 1][r] = v.y; As[kq + 2][r] = v.z; As[kq + 3][r] = v.w;
            float4 w = *(const float4*)(B + (size_t)r * ldb + kt + kq);
            Bs[kq + 0][r] = w.x; Bs[kq + 1][r] = w.y; Bs[kq + 2][r] = w.z; Bs[kq + 3][r] = w.w;
        }
        __syncthreads();
        #pragma unroll
        for (int kk = 0; kk < 16; ++kk) {
            float4 a = *(const float4*)&As[kk][ty * 4];
            float4 b = *(const float4*)&Bs[kk][tx * 4];
            float am[4] = {a.x, a.y, a.z, a.w};
            float bm[4] = {b.x, b.y, b.z, b.w};
            #pragma unroll
            for (int i = 0; i < 4; ++i)
                #pragma unroll
                for (int j = 0; j < 4; ++j)
                    acc[i][j] += am[i] * bm[j];
        }
    }
    __syncthreads();
    #pragma unroll
    for (int i = 0; i < 4; ++i)
        #pragma unroll
        for (int j = 0; j < 4; ++j) {
            float v = alpha * acc[i][j];
            if (beta != 0.0f) v += beta * C[(size_t)(ty * 4 + i) * ldc + tx * 4 + j];
            C[(size_t)(ty * 4 + i) * ldc + tx * 4 + j] = v;
        }
}

__device__ void dev_fwd(int c0, float (*Lt)[65], float (*Zt)[65])
{
    int tid = threadIdx.x;
    int tx = tid & 15, ty = tid >> 4;
    for (int ib = 0; ib < 8; ++ib) {
        float acc[4][4] = {};
        for (int jb = 0; jb < ib; ++jb) {
            for (int idx = tid; idx < 4096; idx += 256) {
                int i = idx >> 6, j = idx & 63;
                Lt[i][j] = g_P[(size_t)(ib * 64 + i) * 512 + jb * 64 + j];
                Zt[i][j] = g_Z[(size_t)(jb * 64 + i) * 1024 + c0 + j];
            }
            __syncthreads();
            #pragma unroll 8
            for (int kk = 0; kk < 64; ++kk)
                #pragma unroll
                for (int ii = 0; ii < 4; ++ii)
                    #pragma unroll
                    for (int jj = 0; jj < 4; ++jj)
                        acc[ii][jj] += Lt[ty * 4 + ii][kk] * Zt[kk][tx * 4 + jj];
            __syncthreads();
        }
        #pragma unroll
        for (int ii = 0; ii < 4; ++ii)
            #pragma unroll
            for (int jj = 0; jj < 4; ++jj)
                Zt[ty * 4 + ii][tx * 4 + jj] =
                    g_RHS[(size_t)(ib * 64 + ty * 4 + ii) * 1024 + c0 + tx * 4 + jj] - acc[ii][jj];
        for (int idx = tid; idx < 4096; idx += 256) {
            int i = idx >> 6, j = idx & 63;
            Lt[i][j] = g_Linv[ib * 4096 + i * 64 + j];
        }
        __syncthreads();
        float z[4][4] = {};
        #pragma unroll 8
        for (int kk = 0; kk < 64; ++kk)
            #pragma unroll
            for (int ii = 0; ii < 4; ++ii)
                #pragma unroll
                for (int jj = 0; jj < 4; ++jj)
                    z[ii][jj] += Lt[ty * 4 + ii][kk] * Zt[kk][tx * 4 + jj];
        #pragma unroll
        for (int ii = 0; ii < 4; ++ii)
            #pragma unroll
            for (int jj = 0; jj < 4; ++jj)
                g_Z[(size_t)(ib * 64 + ty * 4 + ii) * 1024 + c0 + tx * 4 + jj] = z[ii][jj];
        __syncthreads();
    }
}

__device__ void dev_bwd(int c0, float (*Lt)[65], float (*Zt)[65])
{
    int tid = threadIdx.x;
    int tx = tid & 15, ty = tid >> 4;
    for (int ib = 7; ib >= 0; --ib) {
        float acc[4][4] = {};
        for (int jb = ib + 1; jb < 8; ++jb) {
            for (int idx = tid; idx < 4096; idx += 256) {
                int i = idx >> 6, j = idx & 63;
                Lt[i][j] = g_P[(size_t)(jb * 64 + i) * 512 + ib * 64 + j];
                Zt[i][j] = g_S[(size_t)(jb * 64 + i) * 1024 + c0 + j];
            }
            __syncthreads();
            #pragma unroll 8
            for (int kk = 0; kk < 64; ++kk)
                #pragma unroll
                for (int ii = 0; ii < 4; ++ii)
                    #pragma unroll
                    for (int jj = 0; jj < 4; ++jj)
                        acc[ii][jj] += Lt[kk][ty * 4 + ii] * Zt[kk][tx * 4 + jj];
            __syncthreads();
        }
        #pragma unroll
        for (int ii = 0; ii < 4; ++ii)
            #pragma unroll
            for (int jj = 0; jj < 4; ++jj)
                Zt[ty * 4 + ii][tx * 4 + jj] =
                    g_Z[(size_t)(ib * 64 + ty * 4 + ii) * 1024 + c0 + tx * 4 + jj] - acc[ii][jj];
        for (int idx = tid; idx < 4096; idx += 256) {
            int i = idx >> 6, j = idx & 63;
            Lt[i][j] = g_Linv[ib * 4096 + i * 64 + j];
        }
        __syncthreads();
        float z[4][4] = {};
        #pragma unroll 8
        for (int kk = 0; kk < 64; ++kk)
            #pragma unroll
            for (int ii = 0; ii < 4; ++ii)
                #pragma unroll
                for (int jj = 0; jj < 4; ++jj)
                    z[ii][jj] += Lt[kk][ty * 4 + ii] * Zt[kk][tx * 4 + jj];
        #pragma unroll
        for (int ii = 0; ii < 4; ++ii)
            #pragma unroll
            for (int jj = 0; jj < 4; ++jj)
                g_S[(size_t)(ib * 64 + ty * 4 + ii) * 1024 + c0 + tx * 4 + jj] = z[ii][jj];
        __syncthreads();
    }
}

// ================= mma.sync split-bf16 batch GEMM (2 CTAs/SM) ===============
struct Seg {
    const __nv_bfloat16 *Ah, *Al, *Wh, *Wl;
    int lda, ldw, K;
};

template <int NT>
__global__ __launch_bounds__(512, 2) void mma_gemm(
    Seg s0, Seg s1, Seg s2, float* __restrict__ C, int ldc, int addTo)
{
    extern __shared__ __align__(128) char smem[];
    constexpr int AP  = 128 * 64;
    constexpr int WP  = NT * 64;
    constexpr int STG = 2 * AP + 2 * WP;
    constexpr int NAw = NT / 32;

    uint32_t sb = smem_to_u32(smem);
    int tid = threadIdx.x;
    int wid = tid >> 5, lane = tid & 31;
    int m0 = blockIdx.y * 128, n0 = blockIdx.x * NT;
    int wm = (wid & 3) * 32;
    int wn = (wid >> 2) * (NT / 4);

    int nk0 = s0.K >> 5, nk1 = s1.K >> 5, nk2 = s2.K >> 5;
    int nk = nk0 + nk1 + nk2;

    auto issue = [&](int c) {
        int cs = c;
        const Seg* sg = &s0;
        if (cs >= nk0) { cs -= nk0; sg = &s1; if (cs >= nk1) { cs -= nk1; sg = &s2; } }
        int kt = cs << 5;
        uint32_t stu = sb + (c & 1) * STG;
        #pragma unroll
        for (int s = tid; s < 1024; s += 512) {
            int pl = s >> 9, rem = s & 511, row = rem >> 2, q = rem & 3;
            const __nv_bfloat16* src =
                (pl ? sg->Al : sg->Ah) + (size_t)(m0 + row) * sg->lda + kt + q * 8;
            cpasync16(stu + pl * AP + swz64(row * 64 + q * 16), src);
        }
        #pragma unroll
        for (int s = tid; s < NT * 8; s += 512) {
            int pl = (s >= NT * 4) ? 1 : 0;
            int rem = pl ? s - NT * 4 : s;
            int row = rem >> 2, q = rem & 3;
            const __nv_bfloat16* src =
                (pl ? sg->Wl : sg->Wh) + (size_t)(n0 + row) * sg->ldw + kt + q * 8;
            cpasync16(stu + 2 * AP + pl * WP + swz64(row * 64 + q * 16), src);
        }
        CP_COMMIT();
    };

    float acc[2][NAw][4] = {};

    issue(0);
    for (int c = 0; c < nk; ++c) {
        if (c + 1 < nk) { issue(c + 1); CP_WAIT(1); }
        else            { CP_WAIT(0); }
        __syncthreads();
        uint32_t stu = sb + (c & 1) * STG;
        #pragma unroll
        for (int ks = 0; ks < 2; ++ks) {
            uint32_t ah[2][4], al[2][4];
            #pragma unroll
            for (int am = 0; am < 2; ++am) {
                uint32_t off = (uint32_t)(wm + am * 16 + (lane & 15)) * 64
                               + ks * 32 + (lane >> 4) * 16;
                ldsm4(ah[am], stu + swz64(off));
                ldsm4(al[am], stu + AP + swz64(off));
            }
            #pragma unroll
            for (int p = 0; p < NAw / 2; ++p) {
                int g = lane >> 3;
                uint32_t off = (uint32_t)(wn + p * 16 + ((g >> 1) << 3) + (lane & 7)) * 64
                               + ks * 32 + (g & 1) * 16;
                uint32_t th[4], tl[4];
                ldsm4(th, stu + 2 * AP + swz64(off));
                ldsm4(tl, stu + 2 * AP + WP + swz64(off));
                #pragma unroll
                for (int am = 0; am < 2; ++am) {
                    mma16816(acc[am][2 * p],     ah[am], th);
                    mma16816(acc[am][2 * p],     ah[am], tl);
                    mma16816(acc[am][2 * p],     al[am], th);
                    mma16816(acc[am][2 * p + 1], ah[am], th + 2);
                    mma16816(acc[am][2 * p + 1], ah[am], tl + 2);
                    mma16816(acc[am][2 * p + 1], al[am], th + 2);
                }
            }
        }
        __syncthreads();
    }

    #pragma unroll
    for (int am = 0; am < 2; ++am) {
        int r0 = m0 + wm + am * 16 + (lane >> 2);
        #pragma unroll
        for (int j = 0; j < NAw; ++j) {
            int cc = n0 + wn + j * 8 + (lane & 3) * 2;
            float* p0 = C + (size_t)r0 * ldc + cc;
            float* p1 = C + (size_t)(r0 + 8) * ldc + cc;
            float2 v0 = make_float2(acc[am][j][0], acc[am][j][1]);
            float2 v1 = make_float2(acc[am][j][2], acc[am][j][3]);
            if (addTo) {
                float2 o0 = *(const float2*)p0, o1 = *(const float2*)p1;
                v0.x += o0.x; v0.y += o0.y; v1.x += o1.x; v1.y += o1.y;
            }
            *(float2*)p0 = v0;
            *(float2*)p1 = v1;
        }
    }
}

// ============= fused base+cross GEMM + scan (all blocks) + solver ===========
// grid = 272 CTAs x 256 threads, ~100KB smem -> 2 CTAs/SM, all co-resident.
//   CTAs 0-15:   Cholesky + fwd/bwd solves + S split (gbar among 16).
//   CTAs 16-271: strip = 128 rows. Per block b, cross[128x64] =
//                xi_strip @ C1[b]^T (K=512) + u_strip @ D12[b]^T (K=128)
//                + w_strip @ D11[b]^T (K=64b)   -- base folded in, no g_base.
//                Then in-block sequential tanh recurrence (threads 0-127).
__global__ __launch_bounds__(256) void scan_solve()
{
    extern __shared__ __align__(128) char smem[];
    int tid = threadIdx.x;

    if (blockIdx.x < 16) {
        float (*shA)[68] = (float(*)[68])(smem);
        float (*shB)[68] = (float(*)[68])(smem + 16 * 68 * 4);
        float (*S64)[65] = (float(*)[65])(smem + 2 * 16 * 68 * 4);
        float (*T64)[65] = (float(*)[65])(smem + 2 * 16 * 68 * 4 + 64 * 65 * 4);
        float* Dinv      = (float*)(smem + 2 * 16 * 68 * 4 + 2 * 64 * 65 * 4);
        float* sdv       = Dinv + 64;
        int cta = blockIdx.x;
        unsigned gen = 0;

        for (int k = 0; k < 8; ++k) {
            if (cta == 0) dev_potf2_inv(k, S64, Dinv, sdv);
            gbar(gen);
            int nrem = 7 - k;
            if (nrem > 0) {
                if (cta < nrem) {
                    int i = k + 1 + cta;
                    float* panel = g_P + (size_t)i * 64 * 512 + k * 64;
                    dev_gemm_ABt64(panel, 512, g_Linv + k * 4096, 64,
                                   panel, 512, 1.0f, 0.0f, shA, shB);
                }
                gbar(gen);
                int t = 0;
                for (int i = k + 1; i < 8; ++i)
                    for (int j = k + 1; j <= i; ++j, ++t)
                        if ((t & 15) == cta)
                            dev_gemm_ABt64(g_P + (size_t)i * 64 * 512 + k * 64, 512,
                                           g_P + (size_t)j * 64 * 512 + k * 64, 512,
                                           g_P + (size_t)i * 64 * 512 + j * 64, 512,
                                           -1.0f, 1.0f, shA, shB);
                gbar(gen);
            }
        }
        dev_fwd(cta * 64, S64, T64);
        dev_bwd(cta * 64, S64, T64);
        gbar(gen);
        for (int i = cta * 256 + tid; i < NXc * 1024 / 4; i += 4096) {
            float4 v = ((const float4*)g_S)[i];
            __nv_bfloat162 h0, h1, l0, l1;
            h0.x = __float2bfloat16(v.x); h0.y = __float2bfloat16(v.y);
            h1.x = __float2bfloat16(v.z); h1.y = __float2bfloat16(v.w);
            l0.x = __float2bfloat16(v.x - __bfloat162float(h0.x));
            l0.y = __float2bfloat16(v.y - __bfloat162float(h0.y));
            l1.x = __float2bfloat16(v.z - __bfloat162float(h1.x));
            l1.y = __float2bfloat16(v.w - __bfloat162float(h1.y));
            ((__nv_bfloat162*)g_Sh)[i * 2] = h0; ((__nv_bfloat162*)g_Sh)[i * 2 + 1] = h1;
            ((__nv_bfloat162*)g_Sl)[i * 2] = l0; ((__nv_bfloat162*)g_Sl)[i * 2 + 1] = l1;
        }
        return;
    }

    constexpr int APc  = 128 * 64;            // 8192 B per A plane stage
    constexpr int WPc  = 64 * 64;             // 4096 B per W plane stage
    constexpr int STGc = 2 * APc + 2 * WPc;   // 24576
    constexpr int CRo  = 2 * STGc;            // 49152: cross (128 x 68 f32)
    constexpr int DSo  = CRo + 128 * 68 * 4;  // 83968: ds (64 x 65 f32)
    uint32_t sb = smem_to_u32(smem);
    float* cross = (float*)(smem + CRo);
    float* ds    = (float*)(smem + DSo);
    int wid = tid >> 5, lane = tid & 31;
    int strip0 = (blockIdx.x - 16) * 128;

    const __nv_bfloat16* xiH = g_xih + (size_t)strip0 * NXc;
    const __nv_bfloat16* xiL = g_xil + (size_t)strip0 * NXc;
    const __nv_bfloat16* uH  = g_uh  + (size_t)strip0 * NUc;
    const __nv_bfloat16* uL  = g_ul  + (size_t)strip0 * NUc;
    const __nv_bfloat16* wH  = g_wh  + (size_t)strip0 * NQc;
    const __nv_bfloat16* wL  = g_wl  + (size_t)strip0 * NQc;

    for (int b = 0; b < 8; ++b) {
        int nk = 20 + 2 * b;   // 16 (xi·C1) + 4 (u·D12) + 2b (w·D11)

        auto issue = [&](int c) {
            int cs = c;
            const __nv_bfloat16 *Ah, *Al, *Wh, *Wl;
            int lda, ldw;
            if (cs < 16) {
                Ah = xiH; Al = xiL; lda = NXc;
                Wh = g_C1h + (size_t)b * 64 * NXc; Wl = g_C1l + (size_t)b * 64 * NXc; ldw = NXc;
            } else if (cs < 20) {
                cs -= 16;
                Ah = uH; Al = uL; lda = NUc;
                Wh = g_D12h + (size_t)b * 64 * NUc; Wl = g_D12l + (size_t)b * 64 * NUc; ldw = NUc;
            } else {
                cs -= 20;
                Ah = wH; Al = wL; lda = NQc;
                Wh = g_D11h + (size_t)b * 64 * NQc; Wl = g_D11l + (size_t)b * 64 * NQc; ldw = NQc;
            }
            int kt = cs << 5;
            uint32_t stu = sb + (c & 1) * STGc;
            #pragma unroll
            for (int s = tid; s < 1024; s += 256) {
                int pl = s >> 9, rem = s & 511, row = rem >> 2, q = rem & 3;
                const __nv_bfloat16* src = (pl ? Al : Ah) + (size_t)row * lda + kt + q * 8;
                cpasync16(stu + pl * APc + swz64(row * 64 + q * 16), src);
            }
            #pragma unroll
            for (int s = tid; s < 512; s += 256) {
                int pl = s >> 8, rem = s & 255, row = rem >> 2, q = rem & 3;
                const __nv_bfloat16* src = (pl ? Wl : Wh) + (size_t)row * ldw + kt + q * 8;
                cpasync16(stu + 2 * APc + pl * WPc + swz64(row * 64 + q * 16), src);
            }
            CP_COMMIT();
        };

        float acc[2][4][4] = {};
        int wm = (wid & 3) * 32;
        int wn = (wid >> 2) * 32;

        issue(0);
        for (int c = 0; c < nk; ++c) {
            if (c + 1 < nk) { issue(c + 1); CP_WAIT(1); }
            else            { CP_WAIT(0); }
            __syncthreads();
            uint32_t stu = sb + (c & 1) * STGc;
            #pragma unroll
            for (int ks = 0; ks < 2; ++ks) {
                uint32_t ah[2][4], al[2][4];
                #pragma unroll
                for (int am = 0; am < 2; ++am) {
                    uint32_t off = (uint32_t)(wm + am * 16 + (lane & 15)) * 64
                                   + ks * 32 + (lane >> 4) * 16;
                    ldsm4(ah[am], stu + swz64(off));
                    ldsm4(al[am], stu + APc + swz64(off));
                }
                #pragma unroll
                for (int p = 0; p < 2; ++p) {
                    int g = lane >> 3;
                    uint32_t off = (uint32_t)(wn + p * 16 + ((g >> 1) << 3) + (lane & 7)) * 64
                                   + ks * 32 + (g & 1) * 16;
                    uint32_t th[4], tl[4];
                    ldsm4(th, stu + 2 * APc + swz64(off));
                    ldsm4(tl, stu + 2 * APc + WPc + swz64(off));
                    #pragma unroll
                    for (int am = 0; am < 2; ++am) {
                        mma16816(acc[am][2 * p],     ah[am], th);
                        mma16816(acc[am][2 * p],     ah[am], tl);
                        mma16816(acc[am][2 * p],     al[am], th);
                        mma16816(acc[am][2 * p + 1], ah[am], th + 2);
                        mma16816(acc[am][2 * p + 1], ah[am], tl + 2);
                        mma16816(acc[am][2 * p + 1], al[am], th + 2);
                    }
                }
            }
            __syncthreads();
        }

        // epilogue: acc -> cross (smem); cross IS base+cross now
        #pragma unroll
        for (int am = 0; am < 2; ++am) {
            int r0 = wm + am * 16 + (lane >> 2);
            #pragma unroll
            for (int j = 0; j < 4; ++j) {
                int cc = wn + j * 8 + (lane & 3) * 2;
                cross[r0 * 68 + cc]           = acc[am][j][0];
                cross[r0 * 68 + cc + 1]       = acc[am][j][1];
                cross[(r0 + 8) * 68 + cc]     = acc[am][j][2];
                cross[(r0 + 8) * 68 + cc + 1] = acc[am][j][3];
            }
        }
        for (int idx = tid; idx < 4096; idx += 256) {
            int i = idx >> 6, j = idx & 63;
            ds[i * 65 + j] = g_D11[(size_t)(b * 64 + i) * NQc + b * 64 + j];
        }
        __syncthreads();

        // sequential tanh recurrence; threads 0-127 own one row each
        if (tid < 128) {
            int r = strip0 + tid;
            float bb[64];
            #pragma unroll
            for (int q = 0; q < 64; ++q) bb[q] = cross[tid * 68 + q];
            float wv[64];
            #pragma unroll
            for (int i = 0; i < 64; ++i) {
                float s0 = 0.f, s1 = 0.f, s2 = 0.f, s3 = 0.f;
                #pragma unroll
                for (int j = 0; j < 64; ++j) {
                    if (j < i) {
                        float p = wv[j] * ds[i * 65 + j];
                        if      ((j & 3) == 0) s0 += p;
                        else if ((j & 3) == 1) s1 += p;
                        else if ((j & 3) == 2) s2 += p;
                        else                   s3 += p;
                    }
                }
                wv[i] = ftanh(bb[i] + ((s0 + s1) + (s2 + s3)));
            }
            __nv_bfloat162* whp = (__nv_bfloat162*)(g_wh + (size_t)r * NQc + b * 64);
            __nv_bfloat162* wlp = (__nv_bfloat162*)(g_wl + (size_t)r * NQc + b * 64);
            #pragma unroll
            for (int q = 0; q < 32; ++q) {
                float a = wv[q * 2], c = wv[q * 2 + 1];
                __nv_bfloat162 h, l;
                h.x = __float2bfloat16(a); h.y = __float2bfloat16(c);
                l.x = __float2bfloat16(a - __bfloat162float(h.x));
                l.y = __float2bfloat16(c - __bfloat162float(h.y));
                whp[q] = h; wlp[q] = l;
            }
        }
        __syncthreads();
    }
}

// ================= host orchestration =======================================
extern "C" void kernel_launch(void* const* d_in, const int* in_sizes, int n_in,
                              void* d_out, int out_size)
{
    const float* xi    = (const float*)d_in[1];
    const float* u     = (const float*)d_in[2];
    const float* Pstar = (const float*)d_in[3];
    const float* Chi   = (const float*)d_in[4];
    const float* Y1    = (const float*)d_in[5];
    const float* B2    = (const float*)d_in[6];
    const float* D12   = (const float*)d_in[7];
    const float* X     = (const float*)d_in[8];
    float* out = (float*)d_out;

    float *H, *P;
    __nv_bfloat16 *xih, *xil, *uh, *ul, *wh, *wl, *Xh, *Xl;
    __nv_bfloat16 *Sh, *Sl, *B2h, *B2l;
    cudaGetSymbolAddress((void**)&H, g_H);       cudaGetSymbolAddress((void**)&P, g_P);
    cudaGetSymbolAddress((void**)&xih, g_xih);   cudaGetSymbolAddress((void**)&xil, g_xil);
    cudaGetSymbolAddress((void**)&uh, g_uh);     cudaGetSymbolAddress((void**)&ul, g_ul);
    cudaGetSymbolAddress((void**)&wh, g_wh);     cudaGetSymbolAddress((void**)&wl, g_wl);
    cudaGetSymbolAddress((void**)&Xh, g_Xh);     cudaGetSymbolAddress((void**)&Xl, g_Xl);
    cudaGetSymbolAddress((void**)&Sh, g_Sh);     cudaGetSymbolAddress((void**)&Sl, g_Sl);
    cudaGetSymbolAddress((void**)&B2h, g_B2h);   cudaGetSymbolAddress((void**)&B2l, g_B2l);

    constexpr int SM128 = 2 * (2 * 128 * 64 + 2 * 128 * 64);  // 65536
    constexpr int SM64  = 2 * (2 * 128 * 64 + 2 * 64 * 64);   // 49152
    constexpr int SMSF  = 2 * (2 * 128 * 64 + 2 * 64 * 64) + 128 * 68 * 4 + 64 * 65 * 4; // 100608
    cudaFuncSetAttribute(mma_gemm<128>, cudaFuncAttributeMaxDynamicSharedMemorySize, SM128);
    cudaFuncSetAttribute(mma_gemm<64>,  cudaFuncAttributeMaxDynamicSharedMemorySize, SM64);
    cudaFuncSetAttribute(scan_solve,    cudaFuncAttributeMaxDynamicSharedMemorySize, SMSF);

    Seg zs = { nullptr, nullptr, nullptr, nullptr, 0, 0, 0 };

    // splits
    splitk<<<16384, 256>>>(xi, xih, xil, Bc * NXc / 4);
    splitk<<<4096, 256>>>(u, uh, ul, Bc * NUc / 4);
    splitk<<<1024, 256>>>(X, Xh, Xl, 1024 * 1024 / 4);

    // H = X X^T via tensor path
    Seg sXX = { Xh, Xl, Xh, Xl, 1024, 1024, 1024 };
    mma_gemm<64><<<dim3(16, 8), 512, SM64>>>(sXX, zs, zs, H, 1024, 0);

    // prep (RHS, D11(+planes), C1 planes, D12/B2 planes)
    prep_mats2<<<1024, 256>>>(Y1, Chi, D12, B2);

    // P = 0.5 Pstar Pstar^T + eps I (fp32, feeds Cholesky)
    sgemm64<0, 1><<<dim3(8, 8), 256>>>(Pstar, 512, Pstar, 512, P, 512, 512, 0.5f, 0.0f, EPSc);

    // fused: solver (16 CTAs, gbar) || base+cross GEMM + scan (256 strip CTAs)
    reset_bar<<<1, 32>>>();
    scan_solve<<<272, 256, SMSF>>>();

    // out = xi A^T + w B1^T + u B2^T
    Seg sXA = { xih, xil, Sh, Sl, NXc, 1024, NXc };
    Seg sWB = { wh, wl, Sh + 512, Sl + 512, NQc, 1024, NQc };
    Seg sUB = { uh, ul, B2h, B2l, NUc, NUc, NUc };
    mma_gemm<128><<<dim3(4, 256), 512, SM128>>>(sXA, sWB, sUB, out, NXc, 0);
}